// round 1
// baseline (speedup 1.0000x reference)
#include <cuda_runtime.h>
#include <cstdint>

#define NV 50000
#define NE 800000
#define FVD 128
#define FED 64
#define FUD 64
#define FZD 128

#define NTHR 256
#define TE 128
#define SA_STRIDE 132
// dynamic smem: sA[128][132] + sB[64][128] floats
#define SMEM_FLOATS (128 * SA_STRIDE + 64 * 128)
#define SMEM_BYTES (SMEM_FLOATS * 4)

__device__ float g_agg[(size_t)NV * FVD];
__device__ float g_deg[NV];
__device__ float g_vsum[FVD];
__device__ float g_vmax[FVD];

__device__ __forceinline__ void atomicMaxF(float* addr, float val) {
    int old = __float_as_int(*addr);
    while (__int_as_float(old) < val) {
        int assumed = old;
        old = atomicCAS((int*)addr, assumed, __float_as_int(val));
        if (old == assumed) break;
    }
}

__global__ void init_kernel() {
    int i = blockIdx.x * blockDim.x + threadIdx.x;
    int stride = gridDim.x * blockDim.x;
    for (int k = i; k < NV * FVD; k += stride) g_agg[k] = 0.0f;
    for (int k = i; k < NV; k += stride) g_deg[k] = 0.0f;
    if (i < FVD) { g_vsum[i] = 0.0f; g_vmax[i] = -3.402823466e38f; }
}

// ============================================================================
// Edge kernel: per 128-edge tile:
//   X[128,320] = [E | V[src] | V[dst]] ; H = relu(X@W1+b1) ; C = H@W2+b2
//   atomicAdd C rows into g_agg[dst], count g_deg.
// ============================================================================
extern __shared__ float smem[];

__global__ __launch_bounds__(NTHR, 2) void edge_kernel(
    const float* __restrict__ V, const float* __restrict__ E,
    const int* __restrict__ ei,
    const float* __restrict__ W1, const float* __restrict__ b1,
    const float* __restrict__ W2, const float* __restrict__ b2)
{
    float* sA = smem;                      // [128][SA_STRIDE]
    float* sB = smem + 128 * SA_STRIDE;    // [64][128]
    __shared__ int sSrc[TE], sDst[TE];

    const int tid = threadIdx.x;
    const int ebase = blockIdx.x * TE;

    if (tid < TE) {
        int e = ebase + tid;
        int s = 0, d = 0;
        if (e < NE) { s = ei[e]; d = ei[NE + e]; }
        sSrc[tid] = s; sDst[tid] = d;
        if (e < NE) atomicAdd(&g_deg[d], 1.0f);
    }
    __syncthreads();

    const int r0 = (tid >> 4) * 8;
    const int c0 = (tid & 15) * 8;

    float acc[8][8];
#pragma unroll
    for (int i = 0; i < 8; i++)
#pragma unroll
        for (int j = 0; j < 8; j++) acc[i][j] = 0.0f;

    // ---- GEMM1: K = 320, 5 chunks of 64. sA holds X^T chunk: sA[kk][e] ----
    for (int kc = 0; kc < 5; ++kc) {
#pragma unroll
        for (int it = 0; it < 8; ++it) {
            int id = tid + it * NTHR;          // 0..2047
            int e  = id & (TE - 1);
            int kq = id >> 7;                  // 0..15
            int eg = ebase + e;
            float4 v = make_float4(0.f, 0.f, 0.f, 0.f);
            if (eg < NE) {
                if (kc == 0)
                    v = *(const float4*)&E[(size_t)eg * FED + kq * 4];
                else if (kc < 3)
                    v = *(const float4*)&V[(size_t)sSrc[e] * FVD + (kc - 1) * 64 + kq * 4];
                else
                    v = *(const float4*)&V[(size_t)sDst[e] * FVD + (kc - 3) * 64 + kq * 4];
            }
            int kk = kq * 4;
            sA[(kk + 0) * SA_STRIDE + e] = v.x;
            sA[(kk + 1) * SA_STRIDE + e] = v.y;
            sA[(kk + 2) * SA_STRIDE + e] = v.z;
            sA[(kk + 3) * SA_STRIDE + e] = v.w;
        }
#pragma unroll
        for (int it = 0; it < 8; ++it) {
            int id = tid + it * NTHR;
            int kk = id >> 5;                  // 0..63
            int j  = (id & 31) * 4;
            *(float4*)&sB[kk * 128 + j] =
                *(const float4*)&W1[(size_t)(kc * 64 + kk) * 128 + j];
        }
        __syncthreads();
#pragma unroll 8
        for (int kk = 0; kk < 64; ++kk) {
            float4 a0 = *(float4*)&sA[kk * SA_STRIDE + r0];
            float4 a1 = *(float4*)&sA[kk * SA_STRIDE + r0 + 4];
            float4 b0 = *(float4*)&sB[kk * 128 + c0];
            float4 b1 = *(float4*)&sB[kk * 128 + c0 + 4];
            float a[8] = {a0.x, a0.y, a0.z, a0.w, a1.x, a1.y, a1.z, a1.w};
            float b[8] = {b0.x, b0.y, b0.z, b0.w, b1.x, b1.y, b1.z, b1.w};
#pragma unroll
            for (int i = 0; i < 8; i++)
#pragma unroll
                for (int j = 0; j < 8; j++)
                    acc[i][j] = fmaf(a[i], b[j], acc[i][j]);
        }
        __syncthreads();
    }

    // ---- bias + relu, stage C1 row-major: sA[r][c] ----
    float bia[8];
    {
        float4 t0 = *(const float4*)&b1[c0];
        float4 t1 = *(const float4*)&b1[c0 + 4];
        bia[0]=t0.x; bia[1]=t0.y; bia[2]=t0.z; bia[3]=t0.w;
        bia[4]=t1.x; bia[5]=t1.y; bia[6]=t1.z; bia[7]=t1.w;
    }
#pragma unroll
    for (int i = 0; i < 8; i++) {
#pragma unroll
        for (int j = 0; j < 8; j++) {
            float v = acc[i][j] + bia[j];
            acc[i][j] = v > 0.0f ? v : 0.0f;
        }
        float4 v0 = make_float4(acc[i][0], acc[i][1], acc[i][2], acc[i][3]);
        float4 v1 = make_float4(acc[i][4], acc[i][5], acc[i][6], acc[i][7]);
        *(float4*)&sA[(r0 + i) * SA_STRIDE + c0]     = v0;
        *(float4*)&sA[(r0 + i) * SA_STRIDE + c0 + 4] = v1;
    }

#pragma unroll
    for (int i = 0; i < 8; i++)
#pragma unroll
        for (int j = 0; j < 8; j++) acc[i][j] = 0.0f;

    // ---- GEMM2: K = 128, 2 chunks of 64, A = C1 in sA (row-major) ----
    for (int kc = 0; kc < 2; ++kc) {
#pragma unroll
        for (int it = 0; it < 8; ++it) {
            int id = tid + it * NTHR;
            int kk = id >> 5;
            int j  = (id & 31) * 4;
            *(float4*)&sB[kk * 128 + j] =
                *(const float4*)&W2[(size_t)(kc * 64 + kk) * 128 + j];
        }
        __syncthreads();
#pragma unroll 8
        for (int kk = 0; kk < 64; ++kk) {
            int k = kc * 64 + kk;
            float a[8];
#pragma unroll
            for (int i = 0; i < 8; i++) a[i] = sA[(r0 + i) * SA_STRIDE + k];
            float4 b0 = *(float4*)&sB[kk * 128 + c0];
            float4 b1 = *(float4*)&sB[kk * 128 + c0 + 4];
            float b[8] = {b0.x, b0.y, b0.z, b0.w, b1.x, b1.y, b1.z, b1.w};
#pragma unroll
            for (int i = 0; i < 8; i++)
#pragma unroll
                for (int j = 0; j < 8; j++)
                    acc[i][j] = fmaf(a[i], b[j], acc[i][j]);
        }
        __syncthreads();
    }

    // ---- bias + scatter into g_agg[dst] ----
    {
        float4 t0 = *(const float4*)&b2[c0];
        float4 t1 = *(const float4*)&b2[c0 + 4];
        bia[0]=t0.x; bia[1]=t0.y; bia[2]=t0.z; bia[3]=t0.w;
        bia[4]=t1.x; bia[5]=t1.y; bia[6]=t1.z; bia[7]=t1.w;
    }
#pragma unroll
    for (int i = 0; i < 8; i++) {
        int e = ebase + r0 + i;
        if (e < NE) {
            float* base = &g_agg[(size_t)sDst[r0 + i] * FVD + c0];
#pragma unroll
            for (int j = 0; j < 8; j++)
                atomicAdd(base + j, acc[i][j] + bia[j]);
        }
    }
}

// ============================================================================
// Node kernel: per 128-node tile:
//   X[128,448] = [agg/deg | V | z | u] ; H = relu(X@W1+b1) ; V' = H@W2+b2
//   write V' to out, block-reduce column sum/max into g_vsum/g_vmax.
// ============================================================================
__global__ __launch_bounds__(NTHR, 2) void node_kernel(
    const float* __restrict__ V, const float* __restrict__ z,
    const float* __restrict__ u,
    const float* __restrict__ W1, const float* __restrict__ b1,
    const float* __restrict__ W2, const float* __restrict__ b2,
    float* __restrict__ out)
{
    float* sA = smem;
    float* sB = smem + 128 * SA_STRIDE;
    __shared__ float sInv[TE];

    const int tid = threadIdx.x;
    const int nbase = blockIdx.x * TE;

    if (tid < TE) {
        int n = nbase + tid;
        sInv[tid] = (n < NV) ? 1.0f / fmaxf(g_deg[n], 1.0f) : 0.0f;
    }
    __syncthreads();

    const int r0 = (tid >> 4) * 8;
    const int c0 = (tid & 15) * 8;

    float acc[8][8];
#pragma unroll
    for (int i = 0; i < 8; i++)
#pragma unroll
        for (int j = 0; j < 8; j++) acc[i][j] = 0.0f;

    // ---- GEMM1: K = 448, 7 chunks of 64 ----
    for (int kc = 0; kc < 7; ++kc) {
#pragma unroll
        for (int it = 0; it < 8; ++it) {
            int id = tid + it * NTHR;
            int e  = id & (TE - 1);
            int kq = id >> 7;
            int n  = nbase + e;
            float4 v = make_float4(0.f, 0.f, 0.f, 0.f);
            if (n < NV) {
                if (kc < 2) {
                    v = *(const float4*)&g_agg[(size_t)n * FVD + kc * 64 + kq * 4];
                    float inv = sInv[e];
                    v.x *= inv; v.y *= inv; v.z *= inv; v.w *= inv;
                } else if (kc < 4) {
                    v = *(const float4*)&V[(size_t)n * FVD + (kc - 2) * 64 + kq * 4];
                } else if (kc < 6) {
                    v = *(const float4*)&z[(kc - 4) * 64 + kq * 4];
                } else {
                    v = *(const float4*)&u[kq * 4];
                }
            }
            int kk = kq * 4;
            sA[(kk + 0) * SA_STRIDE + e] = v.x;
            sA[(kk + 1) * SA_STRIDE + e] = v.y;
            sA[(kk + 2) * SA_STRIDE + e] = v.z;
            sA[(kk + 3) * SA_STRIDE + e] = v.w;
        }
#pragma unroll
        for (int it = 0; it < 8; ++it) {
            int id = tid + it * NTHR;
            int kk = id >> 5;
            int j  = (id & 31) * 4;
            *(float4*)&sB[kk * 128 + j] =
                *(const float4*)&W1[(size_t)(kc * 64 + kk) * 128 + j];
        }
        __syncthreads();
#pragma unroll 8
        for (int kk = 0; kk < 64; ++kk) {
            float4 a0 = *(float4*)&sA[kk * SA_STRIDE + r0];
            float4 a1 = *(float4*)&sA[kk * SA_STRIDE + r0 + 4];
            float4 b0 = *(float4*)&sB[kk * 128 + c0];
            float4 b1 = *(float4*)&sB[kk * 128 + c0 + 4];
            float a[8] = {a0.x, a0.y, a0.z, a0.w, a1.x, a1.y, a1.z, a1.w};
            float b[8] = {b0.x, b0.y, b0.z, b0.w, b1.x, b1.y, b1.z, b1.w};
#pragma unroll
            for (int i = 0; i < 8; i++)
#pragma unroll
                for (int j = 0; j < 8; j++)
                    acc[i][j] = fmaf(a[i], b[j], acc[i][j]);
        }
        __syncthreads();
    }

    float bia[8];
    {
        float4 t0 = *(const float4*)&b1[c0];
        float4 t1 = *(const float4*)&b1[c0 + 4];
        bia[0]=t0.x; bia[1]=t0.y; bia[2]=t0.z; bia[3]=t0.w;
        bia[4]=t1.x; bia[5]=t1.y; bia[6]=t1.z; bia[7]=t1.w;
    }
#pragma unroll
    for (int i = 0; i < 8; i++) {
#pragma unroll
        for (int j = 0; j < 8; j++) {
            float v = acc[i][j] + bia[j];
            acc[i][j] = v > 0.0f ? v : 0.0f;
        }
        float4 v0 = make_float4(acc[i][0], acc[i][1], acc[i][2], acc[i][3]);
        float4 v1 = make_float4(acc[i][4], acc[i][5], acc[i][6], acc[i][7]);
        *(float4*)&sA[(r0 + i) * SA_STRIDE + c0]     = v0;
        *(float4*)&sA[(r0 + i) * SA_STRIDE + c0 + 4] = v1;
    }

#pragma unroll
    for (int i = 0; i < 8; i++)
#pragma unroll
        for (int j = 0; j < 8; j++) acc[i][j] = 0.0f;

    // ---- GEMM2 ----
    for (int kc = 0; kc < 2; ++kc) {
#pragma unroll
        for (int it = 0; it < 8; ++it) {
            int id = tid + it * NTHR;
            int kk = id >> 5;
            int j  = (id & 31) * 4;
            *(float4*)&sB[kk * 128 + j] =
                *(const float4*)&W2[(size_t)(kc * 64 + kk) * 128 + j];
        }
        __syncthreads();
#pragma unroll 8
        for (int kk = 0; kk < 64; ++kk) {
            int k = kc * 64 + kk;
            float a[8];
#pragma unroll
            for (int i = 0; i < 8; i++) a[i] = sA[(r0 + i) * SA_STRIDE + k];
            float4 b0 = *(float4*)&sB[kk * 128 + c0];
            float4 b1 = *(float4*)&sB[kk * 128 + c0 + 4];
            float b[8] = {b0.x, b0.y, b0.z, b0.w, b1.x, b1.y, b1.z, b1.w};
#pragma unroll
            for (int i = 0; i < 8; i++)
#pragma unroll
                for (int j = 0; j < 8; j++)
                    acc[i][j] = fmaf(a[i], b[j], acc[i][j]);
        }
        __syncthreads();
    }

    {
        float4 t0 = *(const float4*)&b2[c0];
        float4 t1 = *(const float4*)&b2[c0 + 4];
        bia[0]=t0.x; bia[1]=t0.y; bia[2]=t0.z; bia[3]=t0.w;
        bia[4]=t1.x; bia[5]=t1.y; bia[6]=t1.z; bia[7]=t1.w;
    }

    float colsum[8], colmax[8];
#pragma unroll
    for (int j = 0; j < 8; j++) { colsum[j] = 0.0f; colmax[j] = -3.402823466e38f; }

#pragma unroll
    for (int i = 0; i < 8; i++) {
        int n = nbase + r0 + i;
        if (n < NV) {
            float vals[8];
#pragma unroll
            for (int j = 0; j < 8; j++) {
                vals[j] = acc[i][j] + bia[j];
                colsum[j] += vals[j];
                colmax[j] = fmaxf(colmax[j], vals[j]);
            }
            float4 v0 = make_float4(vals[0], vals[1], vals[2], vals[3]);
            float4 v1 = make_float4(vals[4], vals[5], vals[6], vals[7]);
            *(float4*)&out[(size_t)n * FVD + c0]     = v0;
            *(float4*)&out[(size_t)n * FVD + c0 + 4] = v1;
        }
    }

    // block reduction over the 16 row-groups via sB scratch
    int rg = tid >> 4;
#pragma unroll
    for (int j = 0; j < 8; j++) {
        sB[rg * 128 + c0 + j]        = colsum[j];
        sB[(16 + rg) * 128 + c0 + j] = colmax[j];
    }
    __syncthreads();
    if (tid < 128) {
        float s = 0.0f, m = -3.402823466e38f;
#pragma unroll
        for (int g = 0; g < 16; g++) {
            s += sB[g * 128 + tid];
            m = fmaxf(m, sB[(16 + g) * 128 + tid]);
        }
        atomicAdd(&g_vsum[tid], s);
        atomicMaxF(&g_vmax[tid], m);
    }
}

// ============================================================================
// Global kernel: z' = MLP([v_mean, z]); u' = MLP([v_mean, v_max, z', u])
// ============================================================================
__global__ void global_kernel(
    const float* __restrict__ z, const float* __restrict__ u,
    const float* __restrict__ Wg1, const float* __restrict__ bg1,
    const float* __restrict__ Wg2, const float* __restrict__ bg2,
    const float* __restrict__ Wu1, const float* __restrict__ bu1,
    const float* __restrict__ Wu2, const float* __restrict__ bu2,
    float* __restrict__ out)
{
    __shared__ float x[448];
    __shared__ float h[128];
    const int t = threadIdx.x;   // 128 threads
    const float inv_nv = 1.0f / (float)NV;

    float vmean = g_vsum[t] * inv_nv;
    x[t] = vmean;
    x[128 + t] = z[t];
    __syncthreads();

    float s = bg1[t];
    for (int k = 0; k < 256; k++) s = fmaf(x[k], Wg1[k * 128 + t], s);
    h[t] = fmaxf(s, 0.0f);
    __syncthreads();

    float s2 = bg2[t];
    for (int k = 0; k < 128; k++) s2 = fmaf(h[k], Wg2[k * 128 + t], s2);
    out[(size_t)NV * FVD + FUD + t] = s2;   // z' at offset 6,400,064
    __syncthreads();

    x[128 + t] = g_vmax[t];
    x[256 + t] = s2;
    if (t < 64) x[384 + t] = u[t];
    __syncthreads();

    float s3 = bu1[t];
    for (int k = 0; k < 448; k++) s3 = fmaf(x[k], Wu1[k * 128 + t], s3);
    h[t] = fmaxf(s3, 0.0f);
    __syncthreads();

    if (t < 64) {
        float s4 = bu2[t];
        for (int k = 0; k < 128; k++) s4 = fmaf(h[k], Wu2[k * 64 + t], s4);
        out[(size_t)NV * FVD + t] = s4;     // u' at offset 6,400,000
    }
}

extern "C" void kernel_launch(void* const* d_in, const int* in_sizes, int n_in,
                              void* d_out, int out_size) {
    const float* V   = (const float*)d_in[0];
    const float* E   = (const float*)d_in[1];
    const int*   ei  = (const int*)d_in[2];
    const float* u   = (const float*)d_in[3];
    const float* z   = (const float*)d_in[4];
    const float* We1 = (const float*)d_in[5];
    const float* be1 = (const float*)d_in[6];
    const float* We2 = (const float*)d_in[7];
    const float* be2 = (const float*)d_in[8];
    const float* Wn1 = (const float*)d_in[9];
    const float* bn1 = (const float*)d_in[10];
    const float* Wn2 = (const float*)d_in[11];
    const float* bn2 = (const float*)d_in[12];
    const float* Wg1 = (const float*)d_in[13];
    const float* bg1 = (const float*)d_in[14];
    const float* Wg2 = (const float*)d_in[15];
    const float* bg2 = (const float*)d_in[16];
    const float* Wu1 = (const float*)d_in[17];
    const float* bu1 = (const float*)d_in[18];
    const float* Wu2 = (const float*)d_in[19];
    const float* bu2 = (const float*)d_in[20];
    float* out = (float*)d_out;

    cudaFuncSetAttribute(edge_kernel, cudaFuncAttributeMaxDynamicSharedMemorySize, SMEM_BYTES);
    cudaFuncSetAttribute(node_kernel, cudaFuncAttributeMaxDynamicSharedMemorySize, SMEM_BYTES);

    init_kernel<<<1024, 256>>>();
    edge_kernel<<<(NE + TE - 1) / TE, NTHR, SMEM_BYTES>>>(V, E, ei, We1, be1, We2, be2);
    node_kernel<<<(NV + TE - 1) / TE, NTHR, SMEM_BYTES>>>(V, z, u, Wn1, bn1, Wn2, bn2, out);
    global_kernel<<<1, 128>>>(z, u, Wg1, bg1, Wg2, bg2, Wu1, bu1, Wu2, bu2, out);
}

// round 3
// speedup vs baseline: 1.1958x; 1.1958x over previous
#include <cuda_runtime.h>
#include <cuda_bf16.h>
#include <cstdint>

#define NV 50000
#define NE 800000

// ============================ device globals ================================
__device__ float g_agg[(size_t)NV * 128];
__device__ float g_deg[NV];
__device__ float g_vsum[128];
__device__ float g_vmax[128];
// pre-split transposed weights: [N=128 rows][K cols] bf16 hi/lo
__device__ __nv_bfloat16 WB1h[128 * 320], WB1l[128 * 320];
__device__ __nv_bfloat16 WB2h[128 * 128], WB2l[128 * 128];
__device__ __nv_bfloat16 WN1h[128 * 448], WN1l[128 * 448];
__device__ __nv_bfloat16 WN2h[128 * 128], WN2l[128 * 128];

// ============================ helpers =======================================
__device__ __forceinline__ uint32_t smem_u32(const void* p) {
    uint32_t a;
    asm("{ .reg .u64 t; cvta.to.shared.u64 t, %1; cvt.u32.u64 %0, t; }" : "=r"(a) : "l"(p));
    return a;
}

__device__ __forceinline__ void ldsm4(uint32_t* r, uint32_t addr) {
    asm volatile("ldmatrix.sync.aligned.m8n8.x4.shared.b16 {%0,%1,%2,%3}, [%4];"
                 : "=r"(r[0]), "=r"(r[1]), "=r"(r[2]), "=r"(r[3]) : "r"(addr));
}

__device__ __forceinline__ void mma16816(float* d, const uint32_t* a, const uint32_t* b) {
    asm volatile("mma.sync.aligned.m16n8k16.row.col.f32.bf16.bf16.f32 "
                 "{%0,%1,%2,%3}, {%4,%5,%6,%7}, {%8,%9}, {%0,%1,%2,%3};"
                 : "+f"(d[0]), "+f"(d[1]), "+f"(d[2]), "+f"(d[3])
                 : "r"(a[0]), "r"(a[1]), "r"(a[2]), "r"(a[3]), "r"(b[0]), "r"(b[1]));
}

__device__ __forceinline__ void red4(float* p, float a, float b, float c, float d) {
    asm volatile("red.global.add.v4.f32 [%0], {%1, %2, %3, %4};"
                 :: "l"(p), "f"(a), "f"(b), "f"(c), "f"(d) : "memory");
}

__device__ __forceinline__ void atomicMaxF(float* addr, float val) {
    int old = __float_as_int(*addr);
    while (__int_as_float(old) < val) {
        int assumed = old;
        old = atomicCAS((int*)addr, assumed, __float_as_int(val));
        if (old == assumed) break;
    }
}

// split 32 fp32 (scaled) -> bf16 hi/lo, store 64B to each of hptr/lptr
__device__ __forceinline__ void split32(const float* __restrict__ p, float scale,
                                        __nv_bfloat16* hptr, __nv_bfloat16* lptr) {
    uint32_t H[16], L[16];
#pragma unroll
    for (int g = 0; g < 8; g++) {
        float4 f = reinterpret_cast<const float4*>(p)[g];
        f.x *= scale; f.y *= scale; f.z *= scale; f.w *= scale;
        __nv_bfloat162 h0 = __floats2bfloat162_rn(f.x, f.y);
        __nv_bfloat162 l0 = __floats2bfloat162_rn(f.x - __low2float(h0), f.y - __high2float(h0));
        __nv_bfloat162 h1 = __floats2bfloat162_rn(f.z, f.w);
        __nv_bfloat162 l1 = __floats2bfloat162_rn(f.z - __low2float(h1), f.w - __high2float(h1));
        H[g * 2 + 0] = *reinterpret_cast<uint32_t*>(&h0);
        H[g * 2 + 1] = *reinterpret_cast<uint32_t*>(&h1);
        L[g * 2 + 0] = *reinterpret_cast<uint32_t*>(&l0);
        L[g * 2 + 1] = *reinterpret_cast<uint32_t*>(&l1);
    }
    uint4* dh = reinterpret_cast<uint4*>(hptr);
    uint4* dl = reinterpret_cast<uint4*>(lptr);
#pragma unroll
    for (int q = 0; q < 4; q++) {
        dh[q] = make_uint4(H[q * 4], H[q * 4 + 1], H[q * 4 + 2], H[q * 4 + 3]);
        dl[q] = make_uint4(L[q * 4], L[q * 4 + 1], L[q * 4 + 2], L[q * 4 + 3]);
    }
}
__device__ __forceinline__ void zero32(__nv_bfloat16* hptr, __nv_bfloat16* lptr) {
    uint4 z4 = make_uint4(0, 0, 0, 0);
    uint4* dh = reinterpret_cast<uint4*>(hptr);
    uint4* dl = reinterpret_cast<uint4*>(lptr);
#pragma unroll
    for (int q = 0; q < 4; q++) { dh[q] = z4; dl[q] = z4; }
}

// copy one 64-k chunk (hi+lo) of a weight row into sB[n][0..63 | 64..127]
__device__ __forceinline__ void copy_b(const __nv_bfloat16* wh, const __nv_bfloat16* wl,
                                       __nv_bfloat16* sB, int n, int half) {
    const uint4* sh = reinterpret_cast<const uint4*>(wh + half * 32);
    const uint4* sl = reinterpret_cast<const uint4*>(wl + half * 32);
    uint4* dh = reinterpret_cast<uint4*>(sB + n * 136 + half * 32);
    uint4* dl = reinterpret_cast<uint4*>(sB + n * 136 + 64 + half * 32);
#pragma unroll
    for (int q = 0; q < 4; q++) { dh[q] = sh[q]; dl[q] = sl[q]; }
}

// one 64-k chunk, 3 bf16x3 passes: acc += [Ah|Al](abase) x [Bh|Bl]
// A: smem [128][280] bf16, hi at abase+0..63, lo at abase+64..127
// B: smem [128][136] bf16, hi 0..63, lo 64..127
__device__ __forceinline__ void mma_chunk(float* acc, uint32_t aS, uint32_t bS,
                                          int wm, int wn, int lane, int abase) {
#pragma unroll
    for (int pass = 0; pass < 3; pass++) {
        const int aoff = abase + (pass == 2 ? 64 : 0);
        const int boff = (pass == 1 ? 64 : 0);
#pragma unroll
        for (int ks = 0; ks < 4; ks++) {
            const int kb = ks * 16;
            uint32_t a[2][4];
#pragma unroll
            for (int mi = 0; mi < 2; mi++) {
                int r = wm * 32 + mi * 16 + (lane & 15);
                uint32_t ad = aS + ((uint32_t)(r * 280 + aoff + kb + ((lane >> 4) << 3)) << 1);
                ldsm4(a[mi], ad);
            }
            uint32_t b[4][4];
#pragma unroll
            for (int np = 0; np < 4; np++) {
                int row = wn * 64 + np * 16 + (lane & 7) + ((lane >> 4) << 3);
                int k = boff + kb + (((lane >> 3) & 1) << 3);
                uint32_t bd = bS + ((uint32_t)(row * 136 + k) << 1);
                ldsm4(b[np], bd);
            }
#pragma unroll
            for (int mi = 0; mi < 2; mi++)
#pragma unroll
                for (int ni = 0; ni < 8; ni++)
                    mma16816(&acc[(mi * 8 + ni) * 4], a[mi], &b[ni >> 1][(ni & 1) * 2]);
        }
    }
}

// ============================ small kernels =================================
__global__ void init_kernel() {
    int i = blockIdx.x * blockDim.x + threadIdx.x;
    int stride = gridDim.x * blockDim.x;
    float4 z4 = make_float4(0.f, 0.f, 0.f, 0.f);
    for (int k = i; k < NV * 32; k += stride) reinterpret_cast<float4*>(g_agg)[k] = z4;
    for (int k = i; k < NV; k += stride) g_deg[k] = 0.0f;
    if (i < 128) { g_vsum[i] = 0.0f; g_vmax[i] = -3.402823466e38f; }
}

__global__ void wprep_kernel(const float* __restrict__ We1, const float* __restrict__ We2,
                             const float* __restrict__ Wn1, const float* __restrict__ Wn2) {
    int i = blockIdx.x * blockDim.x + threadIdx.x;
    int stride = gridDim.x * blockDim.x;
    for (int idx = i; idx < 320 * 128; idx += stride) {
        int k = idx >> 7, n = idx & 127;
        float v = We1[idx];
        __nv_bfloat16 h = __float2bfloat16(v);
        WB1h[n * 320 + k] = h;
        WB1l[n * 320 + k] = __float2bfloat16(v - __bfloat162float(h));
    }
    for (int idx = i; idx < 128 * 128; idx += stride) {
        int k = idx >> 7, n = idx & 127;
        float v = We2[idx];
        __nv_bfloat16 h = __float2bfloat16(v);
        WB2h[n * 128 + k] = h;
        WB2l[n * 128 + k] = __float2bfloat16(v - __bfloat162float(h));
    }
    for (int idx = i; idx < 448 * 128; idx += stride) {
        int k = idx >> 7, n = idx & 127;
        float v = Wn1[idx];
        __nv_bfloat16 h = __float2bfloat16(v);
        WN1h[n * 448 + k] = h;
        WN1l[n * 448 + k] = __float2bfloat16(v - __bfloat162float(h));
    }
    for (int idx = i; idx < 128 * 128; idx += stride) {
        int k = idx >> 7, n = idx & 127;
        float v = Wn2[idx];
        __nv_bfloat16 h = __float2bfloat16(v);
        WN2h[n * 128 + k] = h;
        WN2l[n * 128 + k] = __float2bfloat16(v - __bfloat162float(h));
    }
}

// smem: A bf16[128][280] (two 144-offset chunk slots) | B bf16[128][136]
#define A_ELEMS (128 * 280)
#define DSMEM_BYTES (A_ELEMS * 2 + 128 * 136 * 2)

extern __shared__ __nv_bfloat16 dynsm[];

// ============================ edge kernel ===================================
__global__ __launch_bounds__(256, 2) void edge_kernel(
    const float* __restrict__ V, const float* __restrict__ E,
    const int* __restrict__ ei,
    const float* __restrict__ b1, const float* __restrict__ b2)
{
    __nv_bfloat16* sA = dynsm;
    __nv_bfloat16* sB = dynsm + A_ELEMS;
    __shared__ float sb1[128], sb2[128];
    __shared__ int sSrc[128], sDst[128];

    const int tid = threadIdx.x;
    const int lane = tid & 31;
    const int w = tid >> 5;
    const int wm = w >> 1, wn = w & 1;
    const int ebase = blockIdx.x * 128;

    if (tid < 128) {
        sb1[tid] = b1[tid];
        int s = ei[ebase + tid], d = ei[NE + ebase + tid];
        sSrc[tid] = s; sDst[tid] = d;
        atomicAdd(&g_deg[d], 1.0f);
    } else {
        sb2[tid - 128] = b2[tid - 128];
    }

    const uint32_t aS = smem_u32(sA), bS = smem_u32(sB);
    const int arow = tid >> 1, half = tid & 1;

    float acc[64];
#pragma unroll
    for (int i = 0; i < 64; i++) acc[i] = 0.0f;

    // ---- GEMM1: K=320, 5 chunks of 64 ----
    for (int kc = 0; kc < 5; kc++) {
        __syncthreads();
        {
            const float* p;
            if (kc == 0)      p = E + (size_t)(ebase + arow) * 64 + half * 32;
            else if (kc == 1) p = V + (size_t)sSrc[arow] * 128 + half * 32;
            else if (kc == 2) p = V + (size_t)sSrc[arow] * 128 + 64 + half * 32;
            else if (kc == 3) p = V + (size_t)sDst[arow] * 128 + half * 32;
            else              p = V + (size_t)sDst[arow] * 128 + 64 + half * 32;
            split32(p, 1.0f, sA + arow * 280 + half * 32, sA + arow * 280 + 64 + half * 32);
            copy_b(WB1h + (size_t)arow * 320 + kc * 64,
                   WB1l + (size_t)arow * 320 + kc * 64, sB, arow, half);
        }
        __syncthreads();
        mma_chunk(acc, aS, bS, wm, wn, lane, 0);
    }

    // ---- H = relu(D1 + b1), split into A slots directly from fragments ----
    __syncthreads();
#pragma unroll
    for (int mi = 0; mi < 2; mi++)
#pragma unroll
        for (int ni = 0; ni < 8; ni++) {
            float* a4 = &acc[(mi * 8 + ni) * 4];
            int c = wn * 64 + ni * 8 + 2 * (lane & 3);
            int soff = (c >> 6) * 144, kk = c & 63;
            float bb0 = sb1[c], bb1 = sb1[c + 1];
            int r0 = wm * 32 + mi * 16 + (lane >> 2);
#pragma unroll
            for (int hh = 0; hh < 2; hh++) {
                int r = r0 + hh * 8;
                float v0 = fmaxf(a4[hh * 2 + 0] + bb0, 0.0f);
                float v1 = fmaxf(a4[hh * 2 + 1] + bb1, 0.0f);
                __nv_bfloat162 hv = __floats2bfloat162_rn(v0, v1);
                __nv_bfloat162 lv = __floats2bfloat162_rn(v0 - __low2float(hv), v1 - __high2float(hv));
                *reinterpret_cast<uint32_t*>(sA + r * 280 + soff + kk) = *reinterpret_cast<uint32_t*>(&hv);
                *reinterpret_cast<uint32_t*>(sA + r * 280 + soff + 64 + kk) = *reinterpret_cast<uint32_t*>(&lv);
            }
        }
#pragma unroll
    for (int i = 0; i < 64; i++) acc[i] = 0.0f;

    // ---- GEMM2: K=128, 2 chunks (A already staged in slots) ----
    for (int kc = 0; kc < 2; kc++) {
        if (kc > 0) __syncthreads();
        copy_b(WB2h + (size_t)arow * 128 + kc * 64,
               WB2l + (size_t)arow * 128 + kc * 64, sB, arow, half);
        __syncthreads();
        mma_chunk(acc, aS, bS, wm, wn, lane, kc * 144);
    }

    // ---- stage D2 + b2 to f32 smem, then coalesced red.v4 scatter ----
    __syncthreads();
    float* st = reinterpret_cast<float*>(sA);   // [128][140] f32
#pragma unroll
    for (int mi = 0; mi < 2; mi++)
#pragma unroll
        for (int ni = 0; ni < 8; ni++) {
            float* a4 = &acc[(mi * 8 + ni) * 4];
            int c = wn * 64 + ni * 8 + 2 * (lane & 3);
            float bb0 = sb2[c], bb1 = sb2[c + 1];
            int r0 = wm * 32 + mi * 16 + (lane >> 2);
            st[r0 * 140 + c] = a4[0] + bb0;
            st[r0 * 140 + c + 1] = a4[1] + bb1;
            st[(r0 + 8) * 140 + c] = a4[2] + bb0;
            st[(r0 + 8) * 140 + c + 1] = a4[3] + bb1;
        }
    __syncthreads();
#pragma unroll
    for (int i = 0; i < 16; i++) {
        int idx = tid + i * 256;
        int row = idx >> 5, c4 = (idx & 31) * 4;
        float4 v = *reinterpret_cast<float4*>(st + row * 140 + c4);
        red4(&g_agg[(size_t)sDst[row] * 128 + c4], v.x, v.y, v.z, v.w);
    }
}

// ============================ node kernel ===================================
__global__ __launch_bounds__(256, 2) void node_kernel(
    const float* __restrict__ V, const float* __restrict__ z,
    const float* __restrict__ u,
    const float* __restrict__ b1, const float* __restrict__ b2,
    float* __restrict__ out)
{
    __nv_bfloat16* sA = dynsm;
    __nv_bfloat16* sB = dynsm + A_ELEMS;
    __shared__ float sb1[128], sb2[128];

    const int tid = threadIdx.x;
    const int lane = tid & 31;
    const int w = tid >> 5;
    const int wm = w >> 1, wn = w & 1;
    const int nbase = blockIdx.x * 128;

    if (tid < 128) sb1[tid] = b1[tid];
    else           sb2[tid - 128] = b2[tid - 128];

    const uint32_t aS = smem_u32(sA), bS = smem_u32(sB);
    const int arow = tid >> 1, half = tid & 1;
    const int n = nbase + arow;
    const bool valid = n < NV;
    const float inv = valid ? 1.0f / fmaxf(g_deg[n], 1.0f) : 0.0f;

    float acc[64];
#pragma unroll
    for (int i = 0; i < 64; i++) acc[i] = 0.0f;

    // ---- GEMM1: K=448, 7 chunks ----
    for (int kc = 0; kc < 7; kc++) {
        __syncthreads();
        {
            __nv_bfloat16* hd = sA + arow * 280 + half * 32;
            __nv_bfloat16* ld = sA + arow * 280 + 64 + half * 32;
            if (kc < 2) {
                if (valid) split32(&g_agg[(size_t)n * 128 + kc * 64 + half * 32], inv, hd, ld);
                else       zero32(hd, ld);
            } else if (kc < 4) {
                if (valid) split32(V + (size_t)n * 128 + (kc - 2) * 64 + half * 32, 1.0f, hd, ld);
                else       zero32(hd, ld);
            } else if (kc < 6) {
                split32(z + (kc - 4) * 64 + half * 32, 1.0f, hd, ld);
            } else {
                split32(u + half * 32, 1.0f, hd, ld);
            }
            copy_b(WN1h + (size_t)arow * 448 + kc * 64,
                   WN1l + (size_t)arow * 448 + kc * 64, sB, arow, half);
        }
        __syncthreads();
        mma_chunk(acc, aS, bS, wm, wn, lane, 0);
    }

    // ---- H split into slots ----
    __syncthreads();
#pragma unroll
    for (int mi = 0; mi < 2; mi++)
#pragma unroll
        for (int ni = 0; ni < 8; ni++) {
            float* a4 = &acc[(mi * 8 + ni) * 4];
            int c = wn * 64 + ni * 8 + 2 * (lane & 3);
            int soff = (c >> 6) * 144, kk = c & 63;
            float bb0 = sb1[c], bb1 = sb1[c + 1];
            int r0 = wm * 32 + mi * 16 + (lane >> 2);
#pragma unroll
            for (int hh = 0; hh < 2; hh++) {
                int r = r0 + hh * 8;
                float v0 = fmaxf(a4[hh * 2 + 0] + bb0, 0.0f);
                float v1 = fmaxf(a4[hh * 2 + 1] + bb1, 0.0f);
                __nv_bfloat162 hv = __floats2bfloat162_rn(v0, v1);
                __nv_bfloat162 lv = __floats2bfloat162_rn(v0 - __low2float(hv), v1 - __high2float(hv));
                *reinterpret_cast<uint32_t*>(sA + r * 280 + soff + kk) = *reinterpret_cast<uint32_t*>(&hv);
                *reinterpret_cast<uint32_t*>(sA + r * 280 + soff + 64 + kk) = *reinterpret_cast<uint32_t*>(&lv);
            }
        }
#pragma unroll
    for (int i = 0; i < 64; i++) acc[i] = 0.0f;

    // ---- GEMM2 ----
    for (int kc = 0; kc < 2; kc++) {
        if (kc > 0) __syncthreads();
        copy_b(WN2h + (size_t)arow * 128 + kc * 64,
               WN2l + (size_t)arow * 128 + kc * 64, sB, arow, half);
        __syncthreads();
        mma_chunk(acc, aS, bS, wm, wn, lane, kc * 144);
    }

    // ---- stage V' to f32 smem, write out ----
    __syncthreads();
    float* st = reinterpret_cast<float*>(sA);
#pragma unroll
    for (int mi = 0; mi < 2; mi++)
#pragma unroll
        for (int ni = 0; ni < 8; ni++) {
            float* a4 = &acc[(mi * 8 + ni) * 4];
            int c = wn * 64 + ni * 8 + 2 * (lane & 3);
            float bb0 = sb2[c], bb1 = sb2[c + 1];
            int r0 = wm * 32 + mi * 16 + (lane >> 2);
            st[r0 * 140 + c] = a4[0] + bb0;
            st[r0 * 140 + c + 1] = a4[1] + bb1;
            st[(r0 + 8) * 140 + c] = a4[2] + bb0;
            st[(r0 + 8) * 140 + c + 1] = a4[3] + bb1;
        }
    __syncthreads();
#pragma unroll
    for (int i = 0; i < 16; i++) {
        int idx = tid + i * 256;
        int row = idx >> 5, c4 = (idx & 31) * 4;
        int nn = nbase + row;
        if (nn < NV) {
            float4 v = *reinterpret_cast<float4*>(st + row * 140 + c4);
            *reinterpret_cast<float4*>(out + (size_t)nn * 128 + c4) = v;
        }
    }
}

// ======================= V' column sum/max reduce ===========================
__global__ void reduce_kernel(const float* __restrict__ out) {
    const int t = threadIdx.x;           // 128
    const int b = blockIdx.x;            // 200 blocks x 250 rows
    float s = 0.0f, mx = -3.402823466e38f;
    for (int r = b * 250; r < (b + 1) * 250; r++) {
        float v = out[(size_t)r * 128 + t];
        s += v;
        mx = fmaxf(mx, v);
    }
    atomicAdd(&g_vsum[t], s);
    atomicMaxF(&g_vmax[t], mx);
}

// ============================ global kernel =================================
__global__ void global_kernel(
    const float* __restrict__ z, const float* __restrict__ u,
    const float* __restrict__ Wg1, const float* __restrict__ bg1,
    const float* __restrict__ Wg2, const float* __restrict__ bg2,
    const float* __restrict__ Wu1, const float* __restrict__ bu1,
    const float* __restrict__ Wu2, const float* __restrict__ bu2,
    float* __restrict__ out)
{
    __shared__ float x[448], h[128], part[4][128], zp[128];
    const int tid = threadIdx.x;         // 512
    const int t = tid & 127, s = tid >> 7;

    if (tid < 128)      x[tid] = g_vsum[tid] * (1.0f / (float)NV);
    else if (tid < 256) x[tid] = z[tid - 128];
    __syncthreads();

    { // z' layer1: K=256
        float acc = 0.0f;
        for (int k = s * 64; k < s * 64 + 64; k++) acc = fmaf(x[k], Wg1[k * 128 + t], acc);
        part[s][t] = acc;
    }
    __syncthreads();
    if (s == 0) h[t] = fmaxf(part[0][t] + part[1][t] + part[2][t] + part[3][t] + bg1[t], 0.0f);
    __syncthreads();
    { // z' layer2: K=128
        float acc = 0.0f;
        for (int k = s * 32; k < s * 32 + 32; k++) acc = fmaf(h[k], Wg2[k * 128 + t], acc);
        part[s][t] = acc;
    }
    __syncthreads();
    if (s == 0) {
        float v = part[0][t] + part[1][t] + part[2][t] + part[3][t] + bg2[t];
        zp[t] = v;
        out[(size_t)NV * 128 + 64 + t] = v;           // z'
        x[128 + t] = g_vmax[t];
    }
    __syncthreads();
    if (tid < 128)      x[256 + tid] = zp[tid];
    else if (tid < 192) x[384 + (tid - 128)] = u[tid - 128];
    __syncthreads();
    { // u' layer1: K=448
        float acc = 0.0f;
        for (int k = s * 112; k < s * 112 + 112; k++) acc = fmaf(x[k], Wu1[k * 128 + t], acc);
        part[s][t] = acc;
    }
    __syncthreads();
    if (s == 0) h[t] = fmaxf(part[0][t] + part[1][t] + part[2][t] + part[3][t] + bu1[t], 0.0f);
    __syncthreads();
    if (t < 64) { // u' layer2: K=128
        float acc = 0.0f;
        for (int k = s * 32; k < s * 32 + 32; k++) acc = fmaf(h[k], Wu2[k * 64 + t], acc);
        part[s][t] = acc;
    }
    __syncthreads();
    if (s == 0 && t < 64)
        out[(size_t)NV * 128 + t] = part[0][t] + part[1][t] + part[2][t] + part[3][t] + bu2[t];
}

// ============================ launch ========================================
extern "C" void kernel_launch(void* const* d_in, const int* in_sizes, int n_in,
                              void* d_out, int out_size) {
    const float* V   = (const float*)d_in[0];
    const float* E   = (const float*)d_in[1];
    const int*   ei  = (const int*)d_in[2];
    const float* u   = (const float*)d_in[3];
    const float* z   = (const float*)d_in[4];
    const float* We1 = (const float*)d_in[5];
    const float* be1 = (const float*)d_in[6];
    const float* We2 = (const float*)d_in[7];
    const float* be2 = (const float*)d_in[8];
    const float* Wn1 = (const float*)d_in[9];
    const float* bn1 = (const float*)d_in[10];
    const float* Wn2 = (const float*)d_in[11];
    const float* bn2 = (const float*)d_in[12];
    const float* Wg1 = (const float*)d_in[13];
    const float* bg1 = (const float*)d_in[14];
    const float* Wg2 = (const float*)d_in[15];
    const float* bg2 = (const float*)d_in[16];
    const float* Wu1 = (const float*)d_in[17];
    const float* bu1 = (const float*)d_in[18];
    const float* Wu2 = (const float*)d_in[19];
    const float* bu2 = (const float*)d_in[20];
    float* out = (float*)d_out;

    cudaFuncSetAttribute(edge_kernel, cudaFuncAttributeMaxDynamicSharedMemorySize, DSMEM_BYTES);
    cudaFuncSetAttribute(node_kernel, cudaFuncAttributeMaxDynamicSharedMemorySize, DSMEM_BYTES);

    init_kernel<<<512, 256>>>();
    wprep_kernel<<<256, 256>>>(We1, We2, Wn1, Wn2);
    edge_kernel<<<NE / 128, 256, DSMEM_BYTES>>>(V, E, ei, be1, be2);
    node_kernel<<<(NV + 127) / 128, 256, DSMEM_BYTES>>>(V, z, u, bn1, bn2, out);
    reduce_kernel<<<200, 128>>>(out);
    global_kernel<<<1, 512>>>(z, u, Wg1, bg1, Wg2, bg2, Wu1, bu1, Wu2, bu2, out);
}

// round 4
// speedup vs baseline: 1.5223x; 1.2731x over previous
#include <cuda_runtime.h>
#include <cuda_bf16.h>
#include <cstdint>

#define NV 50000
#define NE 800000

// ============================ device globals ================================
__device__ float g_agg[(size_t)NV * 128];
__device__ float g_deg[NV];
__device__ float g_vsum[128];
__device__ float g_vmax[128];
// pre-split transposed weights: [N=128 rows][K cols] bf16 hi/lo
__device__ __nv_bfloat16 WB1h[128 * 320], WB1l[128 * 320];
__device__ __nv_bfloat16 WB2h[128 * 128], WB2l[128 * 128];
__device__ __nv_bfloat16 WN1h[128 * 448], WN1l[128 * 448];
__device__ __nv_bfloat16 WN2h[128 * 128], WN2l[128 * 128];

// smem layout (bytes):
//   sA   [0, 71680)              bf16[128][280]  split A / f32 staging for epilogue
//   sR   [71680, 71680+2*36864)  f32 raw chunk, 2 bufs, stride 72 fl (halves at 0/36)
//   sB   [145408, +2*34816)      bf16[128][136] weights, 2 bufs
#define R_OFF 71680
#define R_BUF 36864
#define B_OFF (R_OFF + 2 * R_BUF)
#define B_BUF 34816
#define SMEM_TOTAL (B_OFF + 2 * B_BUF)   // 215040

extern __shared__ char dynbase[];

// ============================ helpers =======================================
__device__ __forceinline__ uint32_t smem_u32(const void* p) {
    uint32_t a;
    asm("{ .reg .u64 t; cvta.to.shared.u64 t, %1; cvt.u32.u64 %0, t; }" : "=r"(a) : "l"(p));
    return a;
}
__device__ __forceinline__ void ldsm4(uint32_t* r, uint32_t addr) {
    asm volatile("ldmatrix.sync.aligned.m8n8.x4.shared.b16 {%0,%1,%2,%3}, [%4];"
                 : "=r"(r[0]), "=r"(r[1]), "=r"(r[2]), "=r"(r[3]) : "r"(addr));
}
__device__ __forceinline__ void mma16816(float* d, const uint32_t* a, const uint32_t* b) {
    asm volatile("mma.sync.aligned.m16n8k16.row.col.f32.bf16.bf16.f32 "
                 "{%0,%1,%2,%3}, {%4,%5,%6,%7}, {%8,%9}, {%0,%1,%2,%3};"
                 : "+f"(d[0]), "+f"(d[1]), "+f"(d[2]), "+f"(d[3])
                 : "r"(a[0]), "r"(a[1]), "r"(a[2]), "r"(a[3]), "r"(b[0]), "r"(b[1]));
}
__device__ __forceinline__ void red4(float* p, float a, float b, float c, float d) {
    asm volatile("red.global.add.v4.f32 [%0], {%1, %2, %3, %4};"
                 :: "l"(p), "f"(a), "f"(b), "f"(c), "f"(d) : "memory");
}
__device__ __forceinline__ void atomicMaxF(float* addr, float val) {
    int old = __float_as_int(*addr);
    while (__int_as_float(old) < val) {
        int assumed = old;
        old = atomicCAS((int*)addr, assumed, __float_as_int(val));
        if (old == assumed) break;
    }
}
__device__ __forceinline__ void cp16(uint32_t dst, const void* src, int sz) {
    asm volatile("cp.async.cg.shared.global [%0], [%1], 16, %2;"
                 :: "r"(dst), "l"(src), "r"(sz) : "memory");
}
#define CP_COMMIT() asm volatile("cp.async.commit_group;" ::: "memory")
#define CP_WAIT1()  asm volatile("cp.async.wait_group 1;" ::: "memory")
#define CP_WAIT0()  asm volatile("cp.async.wait_group 0;" ::: "memory")

// split 32 fp32 (scaled) -> bf16 hi/lo, store 64B to each of hptr/lptr
__device__ __forceinline__ void split32(const float* __restrict__ p, float scale,
                                        __nv_bfloat16* hptr, __nv_bfloat16* lptr) {
    uint32_t H[16], L[16];
#pragma unroll
    for (int g = 0; g < 8; g++) {
        float4 f = reinterpret_cast<const float4*>(p)[g];
        f.x *= scale; f.y *= scale; f.z *= scale; f.w *= scale;
        __nv_bfloat162 h0 = __floats2bfloat162_rn(f.x, f.y);
        __nv_bfloat162 l0 = __floats2bfloat162_rn(f.x - __low2float(h0), f.y - __high2float(h0));
        __nv_bfloat162 h1 = __floats2bfloat162_rn(f.z, f.w);
        __nv_bfloat162 l1 = __floats2bfloat162_rn(f.z - __low2float(h1), f.w - __high2float(h1));
        H[g * 2 + 0] = *reinterpret_cast<uint32_t*>(&h0);
        H[g * 2 + 1] = *reinterpret_cast<uint32_t*>(&h1);
        L[g * 2 + 0] = *reinterpret_cast<uint32_t*>(&l0);
        L[g * 2 + 1] = *reinterpret_cast<uint32_t*>(&l1);
    }
    uint4* dh = reinterpret_cast<uint4*>(hptr);
    uint4* dl = reinterpret_cast<uint4*>(lptr);
#pragma unroll
    for (int q = 0; q < 4; q++) {
        dh[q] = make_uint4(H[q * 4], H[q * 4 + 1], H[q * 4 + 2], H[q * 4 + 3]);
        dl[q] = make_uint4(L[q * 4], L[q * 4 + 1], L[q * 4 + 2], L[q * 4 + 3]);
    }
}

// issue one raw A half-row (32 floats) into staging buf
__device__ __forceinline__ void issue_raw(const float* src, uint32_t dR, int sz) {
#pragma unroll
    for (int g = 0; g < 8; g++) cp16(dR + g * 16, src + g * 4, sz);
}
// issue one weight half-row chunk (hi+lo, 32+32 bf16)
__device__ __forceinline__ void issue_w(const __nv_bfloat16* Wh, const __nv_bfloat16* Wl,
                                        int stride, int chunk, uint32_t bBuf,
                                        int row, int half) {
    const __nv_bfloat16* sh = Wh + (size_t)row * stride + chunk * 64 + half * 32;
    const __nv_bfloat16* sl = Wl + (size_t)row * stride + chunk * 64 + half * 32;
    uint32_t dh = bBuf + (uint32_t)(row * 272 + half * 64);
    uint32_t dl = dh + 128;
#pragma unroll
    for (int g = 0; g < 4; g++) { cp16(dh + g * 16, sh + g * 8, 16); cp16(dl + g * 16, sl + g * 8, 16); }
}

// one 64-k chunk, bf16x3: acc += Ah*Bh + Ah*Bl + Al*Bh (12 ldsm4 / k-step)
__device__ __forceinline__ void mma_chunk2(float* acc, uint32_t aS, uint32_t bS,
                                           int wm, int wn, int lane, int abase) {
#pragma unroll
    for (int ks = 0; ks < 4; ks++) {
        const int kb = ks * 16;
        uint32_t ah[2][4], al[2][4], bh[4][4], bl[4][4];
#pragma unroll
        for (int mi = 0; mi < 2; mi++) {
            int r = wm * 32 + mi * 16 + (lane & 15);
            ldsm4(ah[mi], aS + ((uint32_t)(r * 280 + abase + kb + ((lane >> 4) << 3)) << 1));
        }
#pragma unroll
        for (int np = 0; np < 4; np++) {
            int rowb = wn * 64 + np * 16 + (lane & 7) + ((lane >> 4) << 3);
            int k = kb + (((lane >> 3) & 1) << 3);
            ldsm4(bh[np], bS + ((uint32_t)(rowb * 136 + k) << 1));
        }
#pragma unroll
        for (int mi = 0; mi < 2; mi++)
#pragma unroll
            for (int ni = 0; ni < 8; ni++)
                mma16816(&acc[(mi * 8 + ni) * 4], ah[mi], &bh[ni >> 1][(ni & 1) * 2]);
#pragma unroll
        for (int np = 0; np < 4; np++) {
            int rowb = wn * 64 + np * 16 + (lane & 7) + ((lane >> 4) << 3);
            int k = kb + (((lane >> 3) & 1) << 3);
            ldsm4(bl[np], bS + ((uint32_t)(rowb * 136 + 64 + k) << 1));
        }
#pragma unroll
        for (int mi = 0; mi < 2; mi++)
#pragma unroll
            for (int ni = 0; ni < 8; ni++)
                mma16816(&acc[(mi * 8 + ni) * 4], ah[mi], &bl[ni >> 1][(ni & 1) * 2]);
#pragma unroll
        for (int mi = 0; mi < 2; mi++) {
            int r = wm * 32 + mi * 16 + (lane & 15);
            ldsm4(al[mi], aS + ((uint32_t)(r * 280 + abase + 64 + kb + ((lane >> 4) << 3)) << 1));
        }
#pragma unroll
        for (int mi = 0; mi < 2; mi++)
#pragma unroll
            for (int ni = 0; ni < 8; ni++)
                mma16816(&acc[(mi * 8 + ni) * 4], al[mi], &bh[ni >> 1][(ni & 1) * 2]);
    }
}

// bias+relu+split H fragments into GEMM2 A slots (abase 0 and 144)
__device__ __forceinline__ void hsplit(const float* acc, __nv_bfloat16* sA,
                                       const float* sb1, int wm, int wn, int lane) {
#pragma unroll
    for (int mi = 0; mi < 2; mi++)
#pragma unroll
        for (int ni = 0; ni < 8; ni++) {
            const float* a4 = &acc[(mi * 8 + ni) * 4];
            int c = wn * 64 + ni * 8 + 2 * (lane & 3);
            int soff = (c >> 6) * 144, kk = c & 63;
            float bb0 = sb1[c], bb1 = sb1[c + 1];
            int r0 = wm * 32 + mi * 16 + (lane >> 2);
#pragma unroll
            for (int hh = 0; hh < 2; hh++) {
                int r = r0 + hh * 8;
                float v0 = fmaxf(a4[hh * 2 + 0] + bb0, 0.0f);
                float v1 = fmaxf(a4[hh * 2 + 1] + bb1, 0.0f);
                __nv_bfloat162 hv = __floats2bfloat162_rn(v0, v1);
                __nv_bfloat162 lv = __floats2bfloat162_rn(v0 - __low2float(hv), v1 - __high2float(hv));
                *reinterpret_cast<uint32_t*>(sA + r * 280 + soff + kk) = *reinterpret_cast<uint32_t*>(&hv);
                *reinterpret_cast<uint32_t*>(sA + r * 280 + soff + 64 + kk) = *reinterpret_cast<uint32_t*>(&lv);
            }
        }
}

// stage D2+bias fragments to f32 smem [128][140]
__device__ __forceinline__ void stage_out(const float* acc, float* st, const float* sb2,
                                          int wm, int wn, int lane) {
#pragma unroll
    for (int mi = 0; mi < 2; mi++)
#pragma unroll
        for (int ni = 0; ni < 8; ni++) {
            const float* a4 = &acc[(mi * 8 + ni) * 4];
            int c = wn * 64 + ni * 8 + 2 * (lane & 3);
            float bb0 = sb2[c], bb1 = sb2[c + 1];
            int r0 = wm * 32 + mi * 16 + (lane >> 2);
            st[r0 * 140 + c] = a4[0] + bb0;
            st[r0 * 140 + c + 1] = a4[1] + bb1;
            st[(r0 + 8) * 140 + c] = a4[2] + bb0;
            st[(r0 + 8) * 140 + c + 1] = a4[3] + bb1;
        }
}

// ============================ small kernels =================================
__global__ void init_kernel() {
    int i = blockIdx.x * blockDim.x + threadIdx.x;
    int stride = gridDim.x * blockDim.x;
    float4 z4 = make_float4(0.f, 0.f, 0.f, 0.f);
    for (int k = i; k < NV * 32; k += stride) reinterpret_cast<float4*>(g_agg)[k] = z4;
    for (int k = i; k < NV; k += stride) g_deg[k] = 0.0f;
    if (i < 128) { g_vsum[i] = 0.0f; g_vmax[i] = -3.402823466e38f; }
}

__global__ void wprep_kernel(const float* __restrict__ We1, const float* __restrict__ We2,
                             const float* __restrict__ Wn1, const float* __restrict__ Wn2) {
    int i = blockIdx.x * blockDim.x + threadIdx.x;
    int stride = gridDim.x * blockDim.x;
    for (int idx = i; idx < 320 * 128; idx += stride) {
        int k = idx >> 7, n = idx & 127;
        float v = We1[idx];
        __nv_bfloat16 h = __float2bfloat16(v);
        WB1h[n * 320 + k] = h;
        WB1l[n * 320 + k] = __float2bfloat16(v - __bfloat162float(h));
    }
    for (int idx = i; idx < 128 * 128; idx += stride) {
        int k = idx >> 7, n = idx & 127;
        float v = We2[idx];
        __nv_bfloat16 h = __float2bfloat16(v);
        WB2h[n * 128 + k] = h;
        WB2l[n * 128 + k] = __float2bfloat16(v - __bfloat162float(h));
    }
    for (int idx = i; idx < 448 * 128; idx += stride) {
        int k = idx >> 7, n = idx & 127;
        float v = Wn1[idx];
        __nv_bfloat16 h = __float2bfloat16(v);
        WN1h[n * 448 + k] = h;
        WN1l[n * 448 + k] = __float2bfloat16(v - __bfloat162float(h));
    }
    for (int idx = i; idx < 128 * 128; idx += stride) {
        int k = idx >> 7, n = idx & 127;
        float v = Wn2[idx];
        __nv_bfloat16 h = __float2bfloat16(v);
        WN2h[n * 128 + k] = h;
        WN2l[n * 128 + k] = __float2bfloat16(v - __bfloat162float(h));
    }
}

// ============================ edge kernel ===================================
__global__ __launch_bounds__(256) void edge_kernel(
    const float* __restrict__ V, const float* __restrict__ E,
    const int* __restrict__ ei,
    const float* __restrict__ b1, const float* __restrict__ b2)
{
    __nv_bfloat16* sA = reinterpret_cast<__nv_bfloat16*>(dynbase);
    __shared__ float sb1[128], sb2[128];
    __shared__ int sSrc[128], sDst[128];

    const int tid = threadIdx.x, lane = tid & 31, w = tid >> 5;
    const int wm = w >> 1, wn = w & 1;
    const int ebase = blockIdx.x * 128;
    const int row = tid >> 1, half = tid & 1;

    const uint32_t aS = smem_u32(dynbase);
    const uint32_t rB[2] = {aS + R_OFF, aS + R_OFF + R_BUF};
    const uint32_t bB[2] = {aS + B_OFF, aS + B_OFF + B_BUF};
    float* sRp[2] = {(float*)(dynbase + R_OFF), (float*)(dynbase + R_OFF + R_BUF)};
    const uint32_t dRoff = (uint32_t)(row * 288 + half * 144);

    // stage 0: E rows + W1 chunk0 -> buf0 (no index dependence)
    issue_raw(E + (size_t)(ebase + row) * 64 + half * 32, rB[0] + dRoff, 16);
    issue_w(WB1h, WB1l, 320, 0, bB[0], row, half);
    CP_COMMIT();

    if (tid < 128) {
        sb1[tid] = b1[tid];
        int s = ei[ebase + tid], d = ei[NE + ebase + tid];
        sSrc[tid] = s; sDst[tid] = d;
        atomicAdd(&g_deg[d], 1.0f);
    } else {
        sb2[tid - 128] = b2[tid - 128];
    }
    __syncthreads();

    // stage 1: V[src] low half + W1 chunk1 -> buf1
    issue_raw(V + (size_t)sSrc[row] * 128 + half * 32, rB[1] + dRoff, 16);
    issue_w(WB1h, WB1l, 320, 1, bB[1], row, half);
    CP_COMMIT();

    float acc[64];
#pragma unroll
    for (int i = 0; i < 64; i++) acc[i] = 0.0f;

    // ---- GEMM1: 5 chunks, 2-stage pipeline ----
    for (int s = 0; s < 5; s++) {
        const int buf = s & 1;
        CP_WAIT1();
        __syncthreads();
        split32(sRp[buf] + row * 72 + half * 36, 1.0f,
                sA + row * 280 + half * 32, sA + row * 280 + 64 + half * 32);
        __syncthreads();
        mma_chunk2(acc, aS, bB[buf], wm, wn, lane, 0);
        __syncthreads();
        const int t = s + 2;
        if (t < 5) {
            const float* src;
            if (t == 2)      src = V + (size_t)sSrc[row] * 128 + 64 + half * 32;
            else if (t == 3) src = V + (size_t)sDst[row] * 128 + half * 32;
            else             src = V + (size_t)sDst[row] * 128 + 64 + half * 32;
            issue_raw(src, rB[buf] + dRoff, 16);
            issue_w(WB1h, WB1l, 320, t, bB[buf], row, half);
        } else {
            issue_w(WB2h, WB2l, 128, t - 5, bB[buf], row, half);
        }
        CP_COMMIT();
    }

    // ---- H = relu(D1+b1) split into GEMM2 slots ----
    hsplit(acc, sA, sb1, wm, wn, lane);
#pragma unroll
    for (int i = 0; i < 64; i++) acc[i] = 0.0f;

    // ---- GEMM2: 2 chunks (stages 5,6) ----
    for (int j = 0; j < 2; j++) {
        const int buf = (5 + j) & 1;
        if (j == 0) CP_WAIT1(); else CP_WAIT0();
        __syncthreads();
        mma_chunk2(acc, aS, bB[buf], wm, wn, lane, j * 144);
    }

    // ---- stage D2+b2, coalesced red.v4 scatter ----
    __syncthreads();
    float* st = reinterpret_cast<float*>(dynbase);
    stage_out(acc, st, sb2, wm, wn, lane);
    __syncthreads();
#pragma unroll
    for (int i = 0; i < 16; i++) {
        int idx = tid + i * 256;
        int r = idx >> 5, c4 = (idx & 31) * 4;
        float4 v = *reinterpret_cast<float4*>(st + r * 140 + c4);
        red4(&g_agg[(size_t)sDst[r] * 128 + c4], v.x, v.y, v.z, v.w);
    }
}

// ============================ node kernel ===================================
__global__ __launch_bounds__(256) void node_kernel(
    const float* __restrict__ V, const float* __restrict__ z,
    const float* __restrict__ u,
    const float* __restrict__ b1, const float* __restrict__ b2,
    float* __restrict__ out)
{
    __nv_bfloat16* sA = reinterpret_cast<__nv_bfloat16*>(dynbase);
    __shared__ float sb1[128], sb2[128];

    const int tid = threadIdx.x, lane = tid & 31, w = tid >> 5;
    const int wm = w >> 1, wn = w & 1;
    const int nbase = blockIdx.x * 128;
    const int row = tid >> 1, half = tid & 1;

    const uint32_t aS = smem_u32(dynbase);
    const uint32_t rB[2] = {aS + R_OFF, aS + R_OFF + R_BUF};
    const uint32_t bB[2] = {aS + B_OFF, aS + B_OFF + B_BUF};
    float* sRp[2] = {(float*)(dynbase + R_OFF), (float*)(dynbase + R_OFF + R_BUF)};
    const uint32_t dRoff = (uint32_t)(row * 288 + half * 144);

    const int n = nbase + row;
    const bool valid = n < NV;
    const size_t nc = valid ? (size_t)n : (size_t)(NV - 1);
    const int vsz = valid ? 16 : 0;

    if (tid < 128) sb1[tid] = b1[tid];
    else           sb2[tid - 128] = b2[tid - 128];
    const float inv = valid ? 1.0f / fmaxf(g_deg[n], 1.0f) : 0.0f;

    // stage 0,1: agg halves + W1 chunks 0,1
    issue_raw(g_agg + nc * 128 + half * 32, rB[0] + dRoff, vsz);
    issue_w(WN1h, WN1l, 448, 0, bB[0], row, half);
    CP_COMMIT();
    issue_raw(g_agg + nc * 128 + 64 + half * 32, rB[1] + dRoff, vsz);
    issue_w(WN1h, WN1l, 448, 1, bB[1], row, half);
    CP_COMMIT();
    __syncthreads();

    float acc[64];
#pragma unroll
    for (int i = 0; i < 64; i++) acc[i] = 0.0f;

    // ---- GEMM1: 7 chunks ----
    for (int s = 0; s < 7; s++) {
        const int buf = s & 1;
        CP_WAIT1();
        __syncthreads();
        split32(sRp[buf] + row * 72 + half * 36, (s < 2) ? inv : 1.0f,
                sA + row * 280 + half * 32, sA + row * 280 + 64 + half * 32);
        __syncthreads();
        mma_chunk2(acc, aS, bB[buf], wm, wn, lane, 0);
        __syncthreads();
        const int t = s + 2;
        if (t < 7) {
            const float* src;
            int sz = 16;
            if (t == 2)      { src = V + nc * 128 + half * 32; sz = vsz; }
            else if (t == 3) { src = V + nc * 128 + 64 + half * 32; sz = vsz; }
            else if (t == 4) { src = z + half * 32; }
            else if (t == 5) { src = z + 64 + half * 32; }
            else             { src = u + half * 32; }
            issue_raw(src, rB[buf] + dRoff, sz);
            issue_w(WN1h, WN1l, 448, t, bB[buf], row, half);
        } else {
            issue_w(WN2h, WN2l, 128, t - 7, bB[buf], row, half);
        }
        CP_COMMIT();
    }

    hsplit(acc, sA, sb1, wm, wn, lane);
#pragma unroll
    for (int i = 0; i < 64; i++) acc[i] = 0.0f;

    for (int j = 0; j < 2; j++) {
        const int buf = (7 + j) & 1;
        if (j == 0) CP_WAIT1(); else CP_WAIT0();
        __syncthreads();
        mma_chunk2(acc, aS, bB[buf], wm, wn, lane, j * 144);
    }

    __syncthreads();
    float* st = reinterpret_cast<float*>(dynbase);
    stage_out(acc, st, sb2, wm, wn, lane);
    __syncthreads();
#pragma unroll
    for (int i = 0; i < 16; i++) {
        int idx = tid + i * 256;
        int r = idx >> 5, c4 = (idx & 31) * 4;
        int nn = nbase + r;
        if (nn < NV) {
            float4 v = *reinterpret_cast<float4*>(st + r * 140 + c4);
            *reinterpret_cast<float4*>(out + (size_t)nn * 128 + c4) = v;
        }
    }
}

// ======================= V' column sum/max reduce ===========================
__global__ void reduce_kernel(const float* __restrict__ out) {
    const int t = threadIdx.x;           // 128
    const int b = blockIdx.x;            // 200 blocks x 250 rows
    float s = 0.0f, mx = -3.402823466e38f;
    for (int r = b * 250; r < (b + 1) * 250; r++) {
        float v = out[(size_t)r * 128 + t];
        s += v;
        mx = fmaxf(mx, v);
    }
    atomicAdd(&g_vsum[t], s);
    atomicMaxF(&g_vmax[t], mx);
}

// ============================ global kernel =================================
__global__ void global_kernel(
    const float* __restrict__ z, const float* __restrict__ u,
    const float* __restrict__ Wg1, const float* __restrict__ bg1,
    const float* __restrict__ Wg2, const float* __restrict__ bg2,
    const float* __restrict__ Wu1, const float* __restrict__ bu1,
    const float* __restrict__ Wu2, const float* __restrict__ bu2,
    float* __restrict__ out)
{
    __shared__ float x[448], h[128], part[4][128], zp[128];
    const int tid = threadIdx.x;         // 512
    const int t = tid & 127, s = tid >> 7;

    if (tid < 128)      x[tid] = g_vsum[tid] * (1.0f / (float)NV);
    else if (tid < 256) x[tid] = z[tid - 128];
    __syncthreads();

    { // z' layer1: K=256
        float acc = 0.0f;
        for (int k = s * 64; k < s * 64 + 64; k++) acc = fmaf(x[k], Wg1[k * 128 + t], acc);
        part[s][t] = acc;
    }
    __syncthreads();
    if (s == 0) h[t] = fmaxf(part[0][t] + part[1][t] + part[2][t] + part[3][t] + bg1[t], 0.0f);
    __syncthreads();
    { // z' layer2: K=128
        float acc = 0.0f;
        for (int k = s * 32; k < s * 32 + 32; k++) acc = fmaf(h[k], Wg2[k * 128 + t], acc);
        part[s][t] = acc;
    }
    __syncthreads();
    if (s == 0) {
        float v = part[0][t] + part[1][t] + part[2][t] + part[3][t] + bg2[t];
        zp[t] = v;
        out[(size_t)NV * 128 + 64 + t] = v;           // z'
        x[128 + t] = g_vmax[t];
    }
    __syncthreads();
    if (tid < 128)      x[256 + tid] = zp[tid];
    else if (tid < 192) x[384 + (tid - 128)] = u[tid - 128];
    __syncthreads();
    { // u' layer1: K=448
        float acc = 0.0f;
        for (int k = s * 112; k < s * 112 + 112; k++) acc = fmaf(x[k], Wu1[k * 128 + t], acc);
        part[s][t] = acc;
    }
    __syncthreads();
    if (s == 0) h[t] = fmaxf(part[0][t] + part[1][t] + part[2][t] + part[3][t] + bu1[t], 0.0f);
    __syncthreads();
    if (t < 64) { // u' layer2: K=128
        float acc = 0.0f;
        for (int k = s * 32; k < s * 32 + 32; k++) acc = fmaf(h[k], Wu2[k * 64 + t], acc);
        part[s][t] = acc;
    }
    __syncthreads();
    if (s == 0 && t < 64)
        out[(size_t)NV * 128 + t] = part[0][t] + part[1][t] + part[2][t] + part[3][t] + bu2[t];
}

// ============================ launch ========================================
extern "C" void kernel_launch(void* const* d_in, const int* in_sizes, int n_in,
                              void* d_out, int out_size) {
    const float* V   = (const float*)d_in[0];
    const float* E   = (const float*)d_in[1];
    const int*   ei  = (const int*)d_in[2];
    const float* u   = (const float*)d_in[3];
    const float* z   = (const float*)d_in[4];
    const float* We1 = (const float*)d_in[5];
    const float* be1 = (const float*)d_in[6];
    const float* We2 = (const float*)d_in[7];
    const float* be2 = (const float*)d_in[8];
    const float* Wn1 = (const float*)d_in[9];
    const float* bn1 = (const float*)d_in[10];
    const float* Wn2 = (const float*)d_in[11];
    const float* bn2 = (const float*)d_in[12];
    const float* Wg1 = (const float*)d_in[13];
    const float* bg1 = (const float*)d_in[14];
    const float* Wg2 = (const float*)d_in[15];
    const float* bg2 = (const float*)d_in[16];
    const float* Wu1 = (const float*)d_in[17];
    const float* bu1 = (const float*)d_in[18];
    const float* Wu2 = (const float*)d_in[19];
    const float* bu2 = (const float*)d_in[20];
    float* out = (float*)d_out;

    cudaFuncSetAttribute(edge_kernel, cudaFuncAttributeMaxDynamicSharedMemorySize, SMEM_TOTAL);
    cudaFuncSetAttribute(node_kernel, cudaFuncAttributeMaxDynamicSharedMemorySize, SMEM_TOTAL);

    init_kernel<<<512, 256>>>();
    wprep_kernel<<<256, 256>>>(We1, We2, Wn1, Wn2);
    edge_kernel<<<NE / 128, 256, SMEM_TOTAL>>>(V, E, ei, be1, be2);
    node_kernel<<<(NV + 127) / 128, 256, SMEM_TOTAL>>>(V, z, u, bn1, bn2, out);
    reduce_kernel<<<200, 128>>>(out);
    global_kernel<<<1, 512>>>(z, u, Wg1, bg1, Wg2, bg2, Wu1, bu1, Wu2, bu2, out);
}

// round 10
// speedup vs baseline: 3.0387x; 1.9961x over previous
#include <cuda_runtime.h>
#include <cuda_bf16.h>
#include <cstdint>

#define NV 50000
#define NE 800000

// ============================ device globals ================================
__device__ float g_agg[(size_t)NV * 128];
__device__ float g_deg[NV];
__device__ float g_vsum[128];
__device__ float g_vmax[128];
__device__ float g_Ps[(size_t)NV * 128];   // V @ W1s^T
__device__ float g_Pd[(size_t)NV * 128];   // V @ W1d^T
__device__ float g_cnode[128];             // z@W1z + u@W1u + b1 (node)
// pre-split transposed weights [n][k] bf16 hi/lo
__device__ __nv_bfloat16 WE1h[128 * 64],  WE1l[128 * 64];    // We1 rows 0..63
__device__ __nv_bfloat16 WS1h[128 * 128], WS1l[128 * 128];   // We1 rows 64..191
__device__ __nv_bfloat16 WD1h[128 * 128], WD1l[128 * 128];   // We1 rows 192..319
__device__ __nv_bfloat16 WB2h[128 * 128], WB2l[128 * 128];
__device__ __nv_bfloat16 WN1h[128 * 256], WN1l[128 * 256];   // Wn1 rows 0..255
__device__ __nv_bfloat16 WN2h[128 * 128], WN2l[128 * 128];

// smem layout (bytes):
//   A  [0, 71680)          bf16[128][280]: GEMM A slots (slot0 @0, slot1 @144)
//   B  [71680, +2*34816)   bf16[128][136] weight bufs
//   P  [141312, +69632)    f32[128][136]: raw staging / P rows / epilogue staging
#define B_OFF 71680
#define B_BUF 34816
#define P_OFF 141312
#define SMEM_TOTAL (P_OFF + 69632)   // 210944

extern __shared__ char dynbase[];

// ============================ helpers =======================================
__device__ __forceinline__ uint32_t smem_u32(const void* p) {
    uint32_t a;
    asm("{ .reg .u64 t; cvta.to.shared.u64 t, %1; cvt.u32.u64 %0, t; }" : "=r"(a) : "l"(p));
    return a;
}
__device__ __forceinline__ void ldsm4(uint32_t* r, uint32_t addr) {
    asm volatile("ldmatrix.sync.aligned.m8n8.x4.shared.b16 {%0,%1,%2,%3}, [%4];"
                 : "=r"(r[0]), "=r"(r[1]), "=r"(r[2]), "=r"(r[3]) : "r"(addr));
}
__device__ __forceinline__ void mma16816(float* d, const uint32_t* a, const uint32_t* b) {
    asm volatile("mma.sync.aligned.m16n8k16.row.col.f32.bf16.bf16.f32 "
                 "{%0,%1,%2,%3}, {%4,%5,%6,%7}, {%8,%9}, {%0,%1,%2,%3};"
                 : "+f"(d[0]), "+f"(d[1]), "+f"(d[2]), "+f"(d[3])
                 : "r"(a[0]), "r"(a[1]), "r"(a[2]), "r"(a[3]), "r"(b[0]), "r"(b[1]));
}
__device__ __forceinline__ void red4(float* p, float a, float b, float c, float d) {
    asm volatile("red.global.add.v4.f32 [%0], {%1, %2, %3, %4};"
                 :: "l"(p), "f"(a), "f"(b), "f"(c), "f"(d) : "memory");
}
__device__ __forceinline__ void atomicMaxF(float* addr, float val) {
    int old = __float_as_int(*addr);
    while (__int_as_float(old) < val) {
        int assumed = old;
        old = atomicCAS((int*)addr, assumed, __float_as_int(val));
        if (old == assumed) break;
    }
}
__device__ __forceinline__ void cp16(uint32_t dst, const void* src, int sz) {
    asm volatile("cp.async.cg.shared.global [%0], [%1], 16, %2;"
                 :: "r"(dst), "l"(src), "r"(sz) : "memory");
}
#define CP_COMMIT() asm volatile("cp.async.commit_group;" ::: "memory")
#define CP_WAIT0()  asm volatile("cp.async.wait_group 0;" ::: "memory")

// split 32 fp32 (scaled) -> bf16 hi/lo (64B each)
__device__ __forceinline__ void split32(const float* __restrict__ p, float scale,
                                        __nv_bfloat16* hptr, __nv_bfloat16* lptr) {
    uint32_t H[16], L[16];
#pragma unroll
    for (int g = 0; g < 8; g++) {
        float4 f = reinterpret_cast<const float4*>(p)[g];
        f.x *= scale; f.y *= scale; f.z *= scale; f.w *= scale;
        __nv_bfloat162 h0 = __floats2bfloat162_rn(f.x, f.y);
        __nv_bfloat162 l0 = __floats2bfloat162_rn(f.x - __low2float(h0), f.y - __high2float(h0));
        __nv_bfloat162 h1 = __floats2bfloat162_rn(f.z, f.w);
        __nv_bfloat162 l1 = __floats2bfloat162_rn(f.z - __low2float(h1), f.w - __high2float(h1));
        H[g * 2 + 0] = *reinterpret_cast<uint32_t*>(&h0);
        H[g * 2 + 1] = *reinterpret_cast<uint32_t*>(&h1);
        L[g * 2 + 0] = *reinterpret_cast<uint32_t*>(&l0);
        L[g * 2 + 1] = *reinterpret_cast<uint32_t*>(&l1);
    }
    uint4* dh = reinterpret_cast<uint4*>(hptr);
    uint4* dl = reinterpret_cast<uint4*>(lptr);
#pragma unroll
    for (int q = 0; q < 4; q++) {
        dh[q] = make_uint4(H[q * 4], H[q * 4 + 1], H[q * 4 + 2], H[q * 4 + 3]);
        dl[q] = make_uint4(L[q * 4], L[q * 4 + 1], L[q * 4 + 2], L[q * 4 + 3]);
    }
}

// raw 32 floats -> P staging buf (stride 136 f32, halves at 0/68)
__device__ __forceinline__ void issue_raw(const float* src, uint32_t P0, int row, int half, int sz) {
    uint32_t d = P0 + (uint32_t)(row * 544 + half * 272);
#pragma unroll
    for (int g = 0; g < 8; g++) cp16(d + g * 16, src + g * 4, sz);
}
// one weight half-row chunk (hi+lo) -> B buf
__device__ __forceinline__ void issue_w(const __nv_bfloat16* Wh, const __nv_bfloat16* Wl,
                                        int stride, int chunk, uint32_t bBuf,
                                        int row, int half) {
    const __nv_bfloat16* sh = Wh + (size_t)row * stride + chunk * 64 + half * 32;
    const __nv_bfloat16* sl = Wl + (size_t)row * stride + chunk * 64 + half * 32;
    uint32_t dh = bBuf + (uint32_t)(row * 272 + half * 64);
    uint32_t dl = dh + 128;
#pragma unroll
    for (int g = 0; g < 4; g++) { cp16(dh + g * 16, sh + g * 8, 16); cp16(dl + g * 16, sl + g * 8, 16); }
}
// gather half a P row (64 floats) into P staging
__device__ __forceinline__ void issue_p(const float* Prow, uint32_t P0, int row, int half) {
    const float* s = Prow + half * 64;
    uint32_t d = P0 + (uint32_t)(row * 544 + half * 256);
#pragma unroll
    for (int g = 0; g < 16; g++) cp16(d + g * 16, s + g * 4, 16);
}

// one 64-k chunk, bf16x3: acc += Ah*Bh + Ah*Bl + Al*Bh
__device__ __forceinline__ void mma_chunk2(float* acc, uint32_t aS, uint32_t bS,
                                           int wm, int wn, int lane, int abase) {
#pragma unroll
    for (int ks = 0; ks < 4; ks++) {
        const int kb = ks * 16;
        uint32_t ah[2][4], al[2][4], bh[4][4], bl[4][4];
#pragma unroll
        for (int mi = 0; mi < 2; mi++) {
            int r = wm * 32 + mi * 16 + (lane & 15);
            ldsm4(ah[mi], aS + ((uint32_t)(r * 280 + abase + kb + ((lane >> 4) << 3)) << 1));
        }
#pragma unroll
        for (int np = 0; np < 4; np++) {
            int rowb = wn * 64 + np * 16 + (lane & 7) + ((lane >> 4) << 3);
            int k = kb + (((lane >> 3) & 1) << 3);
            ldsm4(bh[np], bS + ((uint32_t)(rowb * 136 + k) << 1));
        }
#pragma unroll
        for (int mi = 0; mi < 2; mi++)
#pragma unroll
            for (int ni = 0; ni < 8; ni++)
                mma16816(&acc[(mi * 8 + ni) * 4], ah[mi], &bh[ni >> 1][(ni & 1) * 2]);
#pragma unroll
        for (int np = 0; np < 4; np++) {
            int rowb = wn * 64 + np * 16 + (lane & 7) + ((lane >> 4) << 3);
            int k = kb + (((lane >> 3) & 1) << 3);
            ldsm4(bl[np], bS + ((uint32_t)(rowb * 136 + 64 + k) << 1));
        }
#pragma unroll
        for (int mi = 0; mi < 2; mi++)
#pragma unroll
            for (int ni = 0; ni < 8; ni++)
                mma16816(&acc[(mi * 8 + ni) * 4], ah[mi], &bl[ni >> 1][(ni & 1) * 2]);
#pragma unroll
        for (int mi = 0; mi < 2; mi++) {
            int r = wm * 32 + mi * 16 + (lane & 15);
            ldsm4(al[mi], aS + ((uint32_t)(r * 280 + abase + 64 + kb + ((lane >> 4) << 3)) << 1));
        }
#pragma unroll
        for (int mi = 0; mi < 2; mi++)
#pragma unroll
            for (int ni = 0; ni < 8; ni++)
                mma16816(&acc[(mi * 8 + ni) * 4], al[mi], &bh[ni >> 1][(ni & 1) * 2]);
    }
}

// bias+relu+split fragments into A slots 0/1
__device__ __forceinline__ void hsplit(const float* acc, __nv_bfloat16* sA,
                                       const float* sb1, int wm, int wn, int lane) {
#pragma unroll
    for (int mi = 0; mi < 2; mi++)
#pragma unroll
        for (int ni = 0; ni < 8; ni++) {
            const float* a4 = &acc[(mi * 8 + ni) * 4];
            int c = wn * 64 + ni * 8 + 2 * (lane & 3);
            int soff = (c >> 6) * 144, kk = c & 63;
            float bb0 = sb1[c], bb1 = sb1[c + 1];
            int r0 = wm * 32 + mi * 16 + (lane >> 2);
#pragma unroll
            for (int hh = 0; hh < 2; hh++) {
                int r = r0 + hh * 8;
                float v0 = fmaxf(a4[hh * 2 + 0] + bb0, 0.0f);
                float v1 = fmaxf(a4[hh * 2 + 1] + bb1, 0.0f);
                __nv_bfloat162 hv = __floats2bfloat162_rn(v0, v1);
                __nv_bfloat162 lv = __floats2bfloat162_rn(v0 - __low2float(hv), v1 - __high2float(hv));
                *reinterpret_cast<uint32_t*>(sA + r * 280 + soff + kk) = *reinterpret_cast<uint32_t*>(&hv);
                *reinterpret_cast<uint32_t*>(sA + r * 280 + soff + 64 + kk) = *reinterpret_cast<uint32_t*>(&lv);
            }
        }
}

// acc += staged P rows (f32 [128][136])
__device__ __forceinline__ void add_p(float* acc, const float* pb, int wm, int wn, int lane) {
#pragma unroll
    for (int mi = 0; mi < 2; mi++)
#pragma unroll
        for (int ni = 0; ni < 8; ni++) {
            int c = wn * 64 + ni * 8 + 2 * (lane & 3);
            int r0 = wm * 32 + mi * 16 + (lane >> 2);
            float2 p0 = *reinterpret_cast<const float2*>(pb + r0 * 136 + c);
            float2 p1 = *reinterpret_cast<const float2*>(pb + (r0 + 8) * 136 + c);
            float* a4 = &acc[(mi * 8 + ni) * 4];
            a4[0] += p0.x; a4[1] += p0.y; a4[2] += p1.x; a4[3] += p1.y;
        }
}

// stage fragments (+bias) to f32 smem stride 136
__device__ __forceinline__ void stage_out(const float* acc, float* st, const float* sb2,
                                          int wm, int wn, int lane) {
#pragma unroll
    for (int mi = 0; mi < 2; mi++)
#pragma unroll
        for (int ni = 0; ni < 8; ni++) {
            const float* a4 = &acc[(mi * 8 + ni) * 4];
            int c = wn * 64 + ni * 8 + 2 * (lane & 3);
            float bb0 = sb2 ? sb2[c] : 0.0f, bb1 = sb2 ? sb2[c + 1] : 0.0f;
            int r0 = wm * 32 + mi * 16 + (lane >> 2);
            st[r0 * 136 + c] = a4[0] + bb0;
            st[r0 * 136 + c + 1] = a4[1] + bb1;
            st[(r0 + 8) * 136 + c] = a4[2] + bb0;
            st[(r0 + 8) * 136 + c + 1] = a4[3] + bb1;
        }
}

// ============================ small kernels =================================
__global__ void init_kernel() {
    int i = blockIdx.x * blockDim.x + threadIdx.x;
    int stride = gridDim.x * blockDim.x;
    float4 z4 = make_float4(0.f, 0.f, 0.f, 0.f);
    for (int k = i; k < NV * 32; k += stride) reinterpret_cast<float4*>(g_agg)[k] = z4;
    for (int k = i; k < NV; k += stride) g_deg[k] = 0.0f;
    if (i < 128) { g_vsum[i] = 0.0f; g_vmax[i] = -3.402823466e38f; }
}

__global__ void wprep_kernel(const float* __restrict__ We1, const float* __restrict__ We2,
                             const float* __restrict__ Wn1, const float* __restrict__ Wn2) {
    int i = blockIdx.x * blockDim.x + threadIdx.x;
    int stride = gridDim.x * blockDim.x;
    for (int idx = i; idx < 320 * 128; idx += stride) {
        int k = idx >> 7, n = idx & 127;
        float v = We1[idx];
        __nv_bfloat16 h = __float2bfloat16(v);
        __nv_bfloat16 l = __float2bfloat16(v - __bfloat162float(h));
        if (k < 64)       { WE1h[n * 64 + k] = h;          WE1l[n * 64 + k] = l; }
        else if (k < 192) { WS1h[n * 128 + (k - 64)] = h;  WS1l[n * 128 + (k - 64)] = l; }
        else              { WD1h[n * 128 + (k - 192)] = h; WD1l[n * 128 + (k - 192)] = l; }
    }
    for (int idx = i; idx < 128 * 128; idx += stride) {
        int k = idx >> 7, n = idx & 127;
        float v = We2[idx];
        __nv_bfloat16 h = __float2bfloat16(v);
        WB2h[n * 128 + k] = h;
        WB2l[n * 128 + k] = __float2bfloat16(v - __bfloat162float(h));
    }
    for (int idx = i; idx < 256 * 128; idx += stride) {
        int k = idx >> 7, n = idx & 127;
        float v = Wn1[idx];
        __nv_bfloat16 h = __float2bfloat16(v);
        WN1h[n * 256 + k] = h;
        WN1l[n * 256 + k] = __float2bfloat16(v - __bfloat162float(h));
    }
    for (int idx = i; idx < 128 * 128; idx += stride) {
        int k = idx >> 7, n = idx & 127;
        float v = Wn2[idx];
        __nv_bfloat16 h = __float2bfloat16(v);
        WN2h[n * 128 + k] = h;
        WN2l[n * 128 + k] = __float2bfloat16(v - __bfloat162float(h));
    }
}

// c[n] = bn1[n] + sum z[k] Wn1[256+k][n] + sum u[k] Wn1[384+k][n]
__global__ void cnode_kernel(const float* __restrict__ Wn1, const float* __restrict__ bn1,
                             const float* __restrict__ z, const float* __restrict__ u) {
    int t = threadIdx.x;
    float c = bn1[t];
    for (int k = 0; k < 128; k++) c = fmaf(z[k], Wn1[(256 + k) * 128 + t], c);
    for (int k = 0; k < 64; k++)  c = fmaf(u[k], Wn1[(384 + k) * 128 + t], c);
    g_cnode[t] = c;
}

// ============================ pgemm: P_s, P_d ===============================
__global__ __launch_bounds__(256) void pgemm_kernel(const float* __restrict__ V) {
    __nv_bfloat16* sA = reinterpret_cast<__nv_bfloat16*>(dynbase);
    const int tid = threadIdx.x, lane = tid & 31, w = tid >> 5;
    const int wm = w >> 1, wn = w & 1;
    const int nbase = blockIdx.x * 128;
    const int row = tid >> 1, half = tid & 1;
    const int n = nbase + row;
    const bool valid = n < NV;
    const size_t nc = valid ? (size_t)n : (size_t)(NV - 1);
    const int vsz = valid ? 16 : 0;

    const uint32_t aS = smem_u32(dynbase);
    const uint32_t bB[2] = {aS + B_OFF, aS + B_OFF + B_BUF};
    const uint32_t P0 = aS + P_OFF;
    float* pb = reinterpret_cast<float*>(dynbase + P_OFF);

    issue_raw(V + nc * 128 + half * 32, P0, row, half, vsz);
    CP_COMMIT();
    CP_WAIT0(); __syncthreads();
    split32(pb + row * 136 + half * 68, 1.0f,
            sA + row * 280 + half * 32, sA + row * 280 + 64 + half * 32);
    __syncthreads();
    issue_raw(V + nc * 128 + 64 + half * 32, P0, row, half, vsz);
    issue_w(WS1h, WS1l, 128, 0, bB[0], row, half);
    issue_w(WS1h, WS1l, 128, 1, bB[1], row, half);
    CP_COMMIT();
    CP_WAIT0(); __syncthreads();
    split32(pb + row * 136 + half * 68, 1.0f,
            sA + row * 280 + 144 + half * 32, sA + row * 280 + 144 + 64 + half * 32);
    __syncthreads();

    float acc[64];
#pragma unroll
    for (int i = 0; i < 64; i++) acc[i] = 0.0f;
    mma_chunk2(acc, aS, bB[0], wm, wn, lane, 0);
    mma_chunk2(acc, aS, bB[1], wm, wn, lane, 144);
    __syncthreads();
    issue_w(WD1h, WD1l, 128, 0, bB[0], row, half);
    issue_w(WD1h, WD1l, 128, 1, bB[1], row, half);
    CP_COMMIT();
    stage_out(acc, pb, nullptr, wm, wn, lane);
    __syncthreads();
#pragma unroll
    for (int i = 0; i < 16; i++) {
        int idx = tid + i * 256;
        int r = idx >> 5, c4 = (idx & 31) * 4;
        int nn = nbase + r;
        if (nn < NV)
            *reinterpret_cast<float4*>(&g_Ps[(size_t)nn * 128 + c4]) =
                *reinterpret_cast<float4*>(pb + r * 136 + c4);
    }
    CP_WAIT0(); __syncthreads();
#pragma unroll
    for (int i = 0; i < 64; i++) acc[i] = 0.0f;
    mma_chunk2(acc, aS, bB[0], wm, wn, lane, 0);
    mma_chunk2(acc, aS, bB[1], wm, wn, lane, 144);
    __syncthreads();
    stage_out(acc, pb, nullptr, wm, wn, lane);
    __syncthreads();
#pragma unroll
    for (int i = 0; i < 16; i++) {
        int idx = tid + i * 256;
        int r = idx >> 5, c4 = (idx & 31) * 4;
        int nn = nbase + r;
        if (nn < NV)
            *reinterpret_cast<float4*>(&g_Pd[(size_t)nn * 128 + c4]) =
                *reinterpret_cast<float4*>(pb + r * 136 + c4);
    }
}

// ============================ edge kernel ===================================
// H = relu(E@W1e + Ps[src] + Pd[dst] + b1); C = H@W2 + b2 -> scatter agg[dst]
__global__ __launch_bounds__(256) void edge_kernel(
    const float* __restrict__ E, const int* __restrict__ ei,
    const float* __restrict__ b1, const float* __restrict__ b2)
{
    __nv_bfloat16* sA = reinterpret_cast<__nv_bfloat16*>(dynbase);
    __shared__ float sb1[128], sb2[128];
    __shared__ int sDst[128];

    const int tid = threadIdx.x, lane = tid & 31, w = tid >> 5;
    const int wm = w >> 1, wn = w & 1;
    const int ebase = blockIdx.x * 128;
    const int row = tid >> 1, half = tid & 1;

    const uint32_t aS = smem_u32(dynbase);
    const uint32_t bB[2] = {aS + B_OFF, aS + B_OFF + B_BUF};
    const uint32_t P0 = aS + P_OFF;
    float* pb = reinterpret_cast<float*>(dynbase + P_OFF);

    // g0: E chunk + W1e
    issue_raw(E + (size_t)(ebase + row) * 64 + half * 32, P0, row, half, 16);
    issue_w(WE1h, WE1l, 64, 0, bB[0], row, half);
    CP_COMMIT();

    const int src = ei[ebase + row];
    const int dst = ei[NE + ebase + row];
    if (tid < 128) {
        sb1[tid] = b1[tid];
        sDst[tid] = ei[NE + ebase + tid];
        atomicAdd(&g_deg[sDst[tid]], 1.0f);
    } else {
        sb2[tid - 128] = b2[tid - 128];
    }

    CP_WAIT0(); __syncthreads();
    split32(pb + row * 136 + half * 68, 1.0f,
            sA + row * 280 + half * 32, sA + row * 280 + 64 + half * 32);
    __syncthreads();

    // g1: Ps gather + W2 chunk0 (overlaps GEMM1)
    issue_p(g_Ps + (size_t)src * 128, P0, row, half);
    issue_w(WB2h, WB2l, 128, 0, bB[1], row, half);
    CP_COMMIT();

    float acc[64];
#pragma unroll
    for (int i = 0; i < 64; i++) acc[i] = 0.0f;
    mma_chunk2(acc, aS, bB[0], wm, wn, lane, 0);   // GEMM1: E x W1e

    CP_WAIT0(); __syncthreads();
    add_p(acc, pb, wm, wn, lane);                  // += Ps[src]
    __syncthreads();

    // g2: Pd gather + W2 chunk1
    issue_p(g_Pd + (size_t)dst * 128, P0, row, half);
    issue_w(WB2h, WB2l, 128, 1, bB[0], row, half);
    CP_COMMIT();
    CP_WAIT0(); __syncthreads();
    add_p(acc, pb, wm, wn, lane);                  // += Pd[dst]

    hsplit(acc, sA, sb1, wm, wn, lane);            // relu(+b1) -> A slots
#pragma unroll
    for (int i = 0; i < 64; i++) acc[i] = 0.0f;
    __syncthreads();

    mma_chunk2(acc, aS, bB[1], wm, wn, lane, 0);   // GEMM2 c0
    mma_chunk2(acc, aS, bB[0], wm, wn, lane, 144); // GEMM2 c1
    __syncthreads();

    stage_out(acc, pb, sb2, wm, wn, lane);
    __syncthreads();
#pragma unroll
    for (int i = 0; i < 16; i++) {
        int idx = tid + i * 256;
        int r = idx >> 5, c4 = (idx & 31) * 4;
        float4 v = *reinterpret_cast<float4*>(pb + r * 136 + c4);
        red4(&g_agg[(size_t)sDst[r] * 128 + c4], v.x, v.y, v.z, v.w);
    }
}

// ============================ node kernel ===================================
// V' = relu([agg/deg | V] @ W1' + c) @ W2 + b2
__global__ __launch_bounds__(256) void node_kernel(
    const float* __restrict__ V,
    const float* __restrict__ b2, float* __restrict__ out)
{
    __nv_bfloat16* sA = reinterpret_cast<__nv_bfloat16*>(dynbase);
    __shared__ float sb1[128], sb2[128];

    const int tid = threadIdx.x, lane = tid & 31, w = tid >> 5;
    const int wm = w >> 1, wn = w & 1;
    const int nbase = blockIdx.x * 128;
    const int row = tid >> 1, half = tid & 1;

    const uint32_t aS = smem_u32(dynbase);
    const uint32_t bB[2] = {aS + B_OFF, aS + B_OFF + B_BUF};
    const uint32_t P0 = aS + P_OFF;
    float* pb = reinterpret_cast<float*>(dynbase + P_OFF);

    const int n = nbase + row;
    const bool valid = n < NV;
    const size_t nc = valid ? (size_t)n : (size_t)(NV - 1);
    const int vsz = valid ? 16 : 0;

    if (tid < 128) sb1[tid] = g_cnode[tid];
    else           sb2[tid - 128] = b2[tid - 128];
    const float inv = valid ? 1.0f / fmaxf(g_deg[n], 1.0f) : 0.0f;

    issue_raw(g_agg + nc * 128 + half * 32, P0, row, half, vsz);
    issue_w(WN1h, WN1l, 256, 0, bB[0], row, half);
    CP_COMMIT();

    float acc[64];
#pragma unroll
    for (int i = 0; i < 64; i++) acc[i] = 0.0f;

    // GEMM1: 4 chunks (agg0, agg1, V0, V1)
    for (int s = 0; s < 4; s++) {
        CP_WAIT0(); __syncthreads();
        split32(pb + row * 136 + half * 68, (s < 2) ? inv : 1.0f,
                sA + row * 280 + (s & 1) * 144 + half * 32,
                sA + row * 280 + (s & 1) * 144 + 64 + half * 32);
        __syncthreads();
        if (s < 3) {
            const float* src = (s == 0) ? g_agg + nc * 128 + 64 + half * 32
                             : (s == 1) ? V + nc * 128 + half * 32
                                        : V + nc * 128 + 64 + half * 32;
            issue_raw(src, P0, row, half, vsz);
            issue_w(WN1h, WN1l, 256, s + 1, bB[(s + 1) & 1], row, half);
        } else {
            issue_w(WN2h, WN2l, 128, 0, bB[0], row, half);
        }
        CP_COMMIT();
        mma_chunk2(acc, aS, bB[s & 1], wm, wn, lane, (s & 1) * 144);
    }

    CP_WAIT0(); __syncthreads();   // WN2c0 landed, all GEMM1 mma done
    hsplit(acc, sA, sb1, wm, wn, lane);
#pragma unroll
    for (int i = 0; i < 64; i++) acc[i] = 0.0f;
    issue_w(WN2h, WN2l, 128, 1, bB[1], row, half);
    CP_COMMIT();
    __syncthreads();               // hsplit visible to all

    mma_chunk2(acc, aS, bB[0], wm, wn, lane, 0);
    CP_WAIT0(); __syncthreads();   // FIX: barrier so other threads' WN2c1 cp.async
                                   // writes into bB[1] are visible before reading
    mma_chunk2(acc, aS, bB[1], wm, wn, lane, 144);
    __syncthreads();

    stage_out(acc, pb, sb2, wm, wn, lane);
    __syncthreads();
#pragma unroll
    for (int i = 0; i < 16; i++) {
        int idx = tid + i * 256;
        int r = idx >> 5, c4 = (idx & 31) * 4;
        int nn = nbase + r;
        if (nn < NV) {
            float4 v = *reinterpret_cast<float4*>(pb + r * 136 + c4);
            *reinterpret_cast<float4*>(out + (size_t)nn * 128 + c4) = v;
        }
    }
}

// ======================= V' column sum/max reduce ===========================
__global__ void reduce_kernel(const float* __restrict__ out) {
    const int t = threadIdx.x;
    const int b = blockIdx.x;
    float s = 0.0f, mx = -3.402823466e38f;
    for (int r = b * 250; r < (b + 1) * 250; r++) {
        float v = out[(size_t)r * 128 + t];
        s += v;
        mx = fmaxf(mx, v);
    }
    atomicAdd(&g_vsum[t], s);
    atomicMaxF(&g_vmax[t], mx);
}

// ============================ global kernel =================================
__global__ void global_kernel(
    const float* __restrict__ z, const float* __restrict__ u,
    const float* __restrict__ Wg1, const float* __restrict__ bg1,
    const float* __restrict__ Wg2, const float* __restrict__ bg2,
    const float* __restrict__ Wu1, const float* __restrict__ bu1,
    const float* __restrict__ Wu2, const float* __restrict__ bu2,
    float* __restrict__ out)
{
    __shared__ float x[448], h[128], part[4][128], zp[128];
    const int tid = threadIdx.x;         // 512
    const int t = tid & 127, s = tid >> 7;

    if (tid < 128)      x[tid] = g_vsum[tid] * (1.0f / (float)NV);
    else if (tid < 256) x[tid] = z[tid - 128];
    __syncthreads();

    {
        float acc = 0.0f;
        for (int k = s * 64; k < s * 64 + 64; k++) acc = fmaf(x[k], Wg1[k * 128 + t], acc);
        part[s][t] = acc;
    }
    __syncthreads();
    if (s == 0) h[t] = fmaxf(part[0][t] + part[1][t] + part[2][t] + part[3][t] + bg1[t], 0.0f);
    __syncthreads();
    {
        float acc = 0.0f;
        for (int k = s * 32; k < s * 32 + 32; k++) acc = fmaf(h[k], Wg2[k * 128 + t], acc);
        part[s][t] = acc;
    }
    __syncthreads();
    if (s == 0) {
        float v = part[0][t] + part[1][t] + part[2][t] + part[3][t] + bg2[t];
        zp[t] = v;
        out[(size_t)NV * 128 + 64 + t] = v;
        x[128 + t] = g_vmax[t];
    }
    __syncthreads();
    if (tid < 128)      x[256 + tid] = zp[tid];
    else if (tid < 192) x[384 + (tid - 128)] = u[tid - 128];
    __syncthreads();
    {
        float acc = 0.0f;
        for (int k = s * 112; k < s * 112 + 112; k++) acc = fmaf(x[k], Wu1[k * 128 + t], acc);
        part[s][t] = acc;
    }
    __syncthreads();
    if (s == 0) h[t] = fmaxf(part[0][t] + part[1][t] + part[2][t] + part[3][t] + bu1[t], 0.0f);
    __syncthreads();
    if (t < 64) {
        float acc = 0.0f;
        for (int k = s * 32; k < s * 32 + 32; k++) acc = fmaf(h[k], Wu2[k * 64 + t], acc);
        part[s][t] = acc;
    }
    __syncthreads();
    if (s == 0 && t < 64)
        out[(size_t)NV * 128 + t] = part[0][t] + part[1][t] + part[2][t] + part[3][t] + bu2[t];
}

// ============================ launch ========================================
extern "C" void kernel_launch(void* const* d_in, const int* in_sizes, int n_in,
                              void* d_out, int out_size) {
    const float* V   = (const float*)d_in[0];
    const float* E   = (const float*)d_in[1];
    const int*   ei  = (const int*)d_in[2];
    const float* u   = (const float*)d_in[3];
    const float* z   = (const float*)d_in[4];
    const float* We1 = (const float*)d_in[5];
    const float* be1 = (const float*)d_in[6];
    const float* We2 = (const float*)d_in[7];
    const float* be2 = (const float*)d_in[8];
    const float* Wn1 = (const float*)d_in[9];
    const float* bn1 = (const float*)d_in[10];
    const float* Wn2 = (const float*)d_in[11];
    const float* bn2 = (const float*)d_in[12];
    const float* Wg1 = (const float*)d_in[13];
    const float* bg1 = (const float*)d_in[14];
    const float* Wg2 = (const float*)d_in[15];
    const float* bg2 = (const float*)d_in[16];
    const float* Wu1 = (const float*)d_in[17];
    const float* bu1 = (const float*)d_in[18];
    const float* Wu2 = (const float*)d_in[19];
    const float* bu2 = (const float*)d_in[20];
    float* out = (float*)d_out;

    cudaFuncSetAttribute(pgemm_kernel, cudaFuncAttributeMaxDynamicSharedMemorySize, SMEM_TOTAL);
    cudaFuncSetAttribute(edge_kernel, cudaFuncAttributeMaxDynamicSharedMemorySize, SMEM_TOTAL);
    cudaFuncSetAttribute(node_kernel, cudaFuncAttributeMaxDynamicSharedMemorySize, SMEM_TOTAL);

    init_kernel<<<512, 256>>>();
    wprep_kernel<<<256, 256>>>(We1, We2, Wn1, Wn2);
    cnode_kernel<<<1, 128>>>(Wn1, bn1, z, u);
    pgemm_kernel<<<(NV + 127) / 128, 256, SMEM_TOTAL>>>(V);
    edge_kernel<<<NE / 128, 256, SMEM_TOTAL>>>(E, ei, be1, be2);
    node_kernel<<<(NV + 127) / 128, 256, SMEM_TOTAL>>>(V, bn2, out);
    reduce_kernel<<<200, 128>>>(out);
    global_kernel<<<1, 512>>>(z, u, Wg1, bg1, Wg2, bg2, Wu1, bu1, Wu2, bu2, out);
}

// round 14
// speedup vs baseline: 3.8090x; 1.2535x over previous
#include <cuda_runtime.h>
#include <cuda_bf16.h>
#include <cstdint>

#define NV 50000
#define NE 800000

// ============================ device globals ================================
__device__ float g_agg[(size_t)NV * 128];
__device__ float g_deg[NV];
__device__ float g_vsum[128];
__device__ float g_vmax[128];
__device__ float g_Ps[(size_t)NV * 128];   // V @ W1s^T
__device__ float g_Pd[(size_t)NV * 128];   // V @ W1d^T
__device__ float g_cnode[128];             // z@W1z + u@W1u + b1 (node)
// pre-split transposed weights [n][k] bf16 hi/lo
__device__ __nv_bfloat16 WE1h[128 * 64],  WE1l[128 * 64];    // We1 rows 0..63
__device__ __nv_bfloat16 WS1h[128 * 128], WS1l[128 * 128];   // We1 rows 64..191
__device__ __nv_bfloat16 WD1h[128 * 128], WD1l[128 * 128];   // We1 rows 192..319
__device__ __nv_bfloat16 WB2h[128 * 128], WB2l[128 * 128];
__device__ __nv_bfloat16 WN1h[128 * 256], WN1l[128 * 256];   // Wn1 rows 0..255
__device__ __nv_bfloat16 WN2h[128 * 128], WN2l[128 * 128];

// smem layout (bytes), per CTA (2 CTAs/SM):
//   A [0, 71680)        bf16[128][280]: GEMM A slots (slot0 @0, slot1 @144)
//                       doubles as f32[128][140] staging in epilogues
//   B [71680, +34816)   bf16[128][136] single weight buffer
#define B_OFF 71680
#define SMEM_TOTAL (B_OFF + 34816)   // 106496

extern __shared__ char dynbase[];

// ============================ helpers =======================================
__device__ __forceinline__ uint32_t smem_u32(const void* p) {
    uint32_t a;
    asm("{ .reg .u64 t; cvta.to.shared.u64 t, %1; cvt.u32.u64 %0, t; }" : "=r"(a) : "l"(p));
    return a;
}
__device__ __forceinline__ void ldsm4(uint32_t* r, uint32_t addr) {
    asm volatile("ldmatrix.sync.aligned.m8n8.x4.shared.b16 {%0,%1,%2,%3}, [%4];"
                 : "=r"(r[0]), "=r"(r[1]), "=r"(r[2]), "=r"(r[3]) : "r"(addr));
}
__device__ __forceinline__ void mma16816(float* d, const uint32_t* a, const uint32_t* b) {
    asm volatile("mma.sync.aligned.m16n8k16.row.col.f32.bf16.bf16.f32 "
                 "{%0,%1,%2,%3}, {%4,%5,%6,%7}, {%8,%9}, {%0,%1,%2,%3};"
                 : "+f"(d[0]), "+f"(d[1]), "+f"(d[2]), "+f"(d[3])
                 : "r"(a[0]), "r"(a[1]), "r"(a[2]), "r"(a[3]), "r"(b[0]), "r"(b[1]));
}
__device__ __forceinline__ void red4(float* p, float a, float b, float c, float d) {
    asm volatile("red.global.add.v4.f32 [%0], {%1, %2, %3, %4};"
                 :: "l"(p), "f"(a), "f"(b), "f"(c), "f"(d) : "memory");
}
__device__ __forceinline__ void atomicMaxF(float* addr, float val) {
    int old = __float_as_int(*addr);
    while (__int_as_float(old) < val) {
        int assumed = old;
        old = atomicCAS((int*)addr, assumed, __float_as_int(val));
        if (old == assumed) break;
    }
}
__device__ __forceinline__ void cp16(uint32_t dst, const void* src, int sz) {
    asm volatile("cp.async.cg.shared.global [%0], [%1], 16, %2;"
                 :: "r"(dst), "l"(src), "r"(sz) : "memory");
}
#define CP_COMMIT() asm volatile("cp.async.commit_group;" ::: "memory")
#define CP_WAIT0()  asm volatile("cp.async.wait_group 0;" ::: "memory")

// split 32 fp32 regs (scaled) -> bf16 hi/lo (64B each) to smem
__device__ __forceinline__ void split_regs(const float4* f, float scale,
                                           __nv_bfloat16* hptr, __nv_bfloat16* lptr) {
    uint32_t H[16], L[16];
#pragma unroll
    for (int g = 0; g < 8; g++) {
        float4 v = f[g];
        v.x *= scale; v.y *= scale; v.z *= scale; v.w *= scale;
        __nv_bfloat162 h0 = __floats2bfloat162_rn(v.x, v.y);
        __nv_bfloat162 l0 = __floats2bfloat162_rn(v.x - __low2float(h0), v.y - __high2float(h0));
        __nv_bfloat162 h1 = __floats2bfloat162_rn(v.z, v.w);
        __nv_bfloat162 l1 = __floats2bfloat162_rn(v.z - __low2float(h1), v.w - __high2float(h1));
        H[g * 2 + 0] = *reinterpret_cast<uint32_t*>(&h0);
        H[g * 2 + 1] = *reinterpret_cast<uint32_t*>(&h1);
        L[g * 2 + 0] = *reinterpret_cast<uint32_t*>(&l0);
        L[g * 2 + 1] = *reinterpret_cast<uint32_t*>(&l1);
    }
    uint4* dh = reinterpret_cast<uint4*>(hptr);
    uint4* dl = reinterpret_cast<uint4*>(lptr);
#pragma unroll
    for (int q = 0; q < 4; q++) {
        dh[q] = make_uint4(H[q * 4], H[q * 4 + 1], H[q * 4 + 2], H[q * 4 + 3]);
        dl[q] = make_uint4(L[q * 4], L[q * 4 + 1], L[q * 4 + 2], L[q * 4 + 3]);
    }
}

// one weight half-row chunk (hi+lo, 32+32 bf16) -> B buf via cp.async
__device__ __forceinline__ void issue_w(const __nv_bfloat16* Wh, const __nv_bfloat16* Wl,
                                        int stride, int chunk, uint32_t bBuf,
                                        int row, int half) {
    const __nv_bfloat16* sh = Wh + (size_t)row * stride + chunk * 64 + half * 32;
    const __nv_bfloat16* sl = Wl + (size_t)row * stride + chunk * 64 + half * 32;
    uint32_t dh = bBuf + (uint32_t)(row * 272 + half * 64);
    uint32_t dl = dh + 128;
#pragma unroll
    for (int g = 0; g < 4; g++) { cp16(dh + g * 16, sh + g * 8, 16); cp16(dl + g * 16, sl + g * 8, 16); }
}

// one 64-k chunk, bf16x3: acc += Ah*Bh + Al*Bh + Ah*Bl (reordered for reg peak)
__device__ __forceinline__ void mma_chunk2(float* acc, uint32_t aS, uint32_t bS,
                                           int wm, int wn, int lane, int abase) {
#pragma unroll
    for (int ks = 0; ks < 4; ks++) {
        const int kb = ks * 16;
        uint32_t ah[2][4], al[2][4], bh[4][4], bl[4][4];
#pragma unroll
        for (int mi = 0; mi < 2; mi++) {
            int r = wm * 32 + mi * 16 + (lane & 15);
            ldsm4(ah[mi], aS + ((uint32_t)(r * 280 + abase + kb + ((lane >> 4) << 3)) << 1));
        }
#pragma unroll
        for (int np = 0; np < 4; np++) {
            int rowb = wn * 64 + np * 16 + (lane & 7) + ((lane >> 4) << 3);
            int k = kb + (((lane >> 3) & 1) << 3);
            ldsm4(bh[np], bS + ((uint32_t)(rowb * 136 + k) << 1));
        }
#pragma unroll
        for (int mi = 0; mi < 2; mi++)
#pragma unroll
            for (int ni = 0; ni < 8; ni++)
                mma16816(&acc[(mi * 8 + ni) * 4], ah[mi], &bh[ni >> 1][(ni & 1) * 2]);
#pragma unroll
        for (int mi = 0; mi < 2; mi++) {
            int r = wm * 32 + mi * 16 + (lane & 15);
            ldsm4(al[mi], aS + ((uint32_t)(r * 280 + abase + 64 + kb + ((lane >> 4) << 3)) << 1));
        }
#pragma unroll
        for (int mi = 0; mi < 2; mi++)
#pragma unroll
            for (int ni = 0; ni < 8; ni++)
                mma16816(&acc[(mi * 8 + ni) * 4], al[mi], &bh[ni >> 1][(ni & 1) * 2]);
#pragma unroll
        for (int np = 0; np < 4; np++) {
            int rowb = wn * 64 + np * 16 + (lane & 7) + ((lane >> 4) << 3);
            int k = kb + (((lane >> 3) & 1) << 3);
            ldsm4(bl[np], bS + ((uint32_t)(rowb * 136 + 64 + k) << 1));
        }
#pragma unroll
        for (int mi = 0; mi < 2; mi++)
#pragma unroll
            for (int ni = 0; ni < 8; ni++)
                mma16816(&acc[(mi * 8 + ni) * 4], ah[mi], &bl[ni >> 1][(ni & 1) * 2]);
    }
}

// bias+relu+split fragments into A slots 0/1 (own 32-row band only)
__device__ __forceinline__ void hsplit(const float* acc, __nv_bfloat16* sA,
                                       const float* sb1, int wm, int wn, int lane) {
#pragma unroll
    for (int mi = 0; mi < 2; mi++)
#pragma unroll
        for (int ni = 0; ni < 8; ni++) {
            const float* a4 = &acc[(mi * 8 + ni) * 4];
            int c = wn * 64 + ni * 8 + 2 * (lane & 3);
            int soff = (c >> 6) * 144, kk = c & 63;
            float bb0 = sb1[c], bb1 = sb1[c + 1];
            int r0 = wm * 32 + mi * 16 + (lane >> 2);
#pragma unroll
            for (int hh = 0; hh < 2; hh++) {
                int r = r0 + hh * 8;
                float v0 = fmaxf(a4[hh * 2 + 0] + bb0, 0.0f);
                float v1 = fmaxf(a4[hh * 2 + 1] + bb1, 0.0f);
                __nv_bfloat162 hv = __floats2bfloat162_rn(v0, v1);
                __nv_bfloat162 lv = __floats2bfloat162_rn(v0 - __low2float(hv), v1 - __high2float(hv));
                *reinterpret_cast<uint32_t*>(sA + r * 280 + soff + kk) = *reinterpret_cast<uint32_t*>(&hv);
                *reinterpret_cast<uint32_t*>(sA + r * 280 + soff + 64 + kk) = *reinterpret_cast<uint32_t*>(&lv);
            }
        }
}

// acc += P[idx[r]][c] via direct gmem loads (L2-resident P)
__device__ __forceinline__ void add_p_gmem(float* acc, const float* __restrict__ P,
                                           const int* sIdx, int wm, int wn, int lane) {
#pragma unroll
    for (int mi = 0; mi < 2; mi++)
#pragma unroll
        for (int hh = 0; hh < 2; hh++) {
            int r = wm * 32 + mi * 16 + hh * 8 + (lane >> 2);
            const float* prow = P + (size_t)sIdx[r] * 128;
#pragma unroll
            for (int ni = 0; ni < 8; ni++) {
                int c = wn * 64 + ni * 8 + 2 * (lane & 3);
                float2 p = *reinterpret_cast<const float2*>(prow + c);
                acc[(mi * 8 + ni) * 4 + hh * 2 + 0] += p.x;
                acc[(mi * 8 + ni) * 4 + hh * 2 + 1] += p.y;
            }
        }
}

// stage fragments (+bias) to f32 smem stride 140 (A region reuse)
__device__ __forceinline__ void stage_out140(const float* acc, float* st, const float* sb2,
                                             int wm, int wn, int lane) {
#pragma unroll
    for (int mi = 0; mi < 2; mi++)
#pragma unroll
        for (int ni = 0; ni < 8; ni++) {
            const float* a4 = &acc[(mi * 8 + ni) * 4];
            int c = wn * 64 + ni * 8 + 2 * (lane & 3);
            float bb0 = sb2[c], bb1 = sb2[c + 1];
            int r0 = wm * 32 + mi * 16 + (lane >> 2);
            st[r0 * 140 + c] = a4[0] + bb0;
            st[r0 * 140 + c + 1] = a4[1] + bb1;
            st[(r0 + 8) * 140 + c] = a4[2] + bb0;
            st[(r0 + 8) * 140 + c + 1] = a4[3] + bb1;
        }
}

// store fragments directly to a [*,128] f32 gmem array (row nbase+r, no bias)
__device__ __forceinline__ void store_p(const float* acc, float* P, int nbase,
                                        int wm, int wn, int lane) {
#pragma unroll
    for (int mi = 0; mi < 2; mi++)
#pragma unroll
        for (int hh = 0; hh < 2; hh++) {
            int r = wm * 32 + mi * 16 + hh * 8 + (lane >> 2);
            int n = nbase + r;
            if (n < NV) {
                float* prow = P + (size_t)n * 128;
#pragma unroll
                for (int ni = 0; ni < 8; ni++) {
                    int c = wn * 64 + ni * 8 + 2 * (lane & 3);
                    *reinterpret_cast<float2*>(prow + c) =
                        make_float2(acc[(mi * 8 + ni) * 4 + hh * 2 + 0],
                                    acc[(mi * 8 + ni) * 4 + hh * 2 + 1]);
                }
            }
        }
}

// ============================ small kernels =================================
__global__ void init_kernel() {
    int i = blockIdx.x * blockDim.x + threadIdx.x;
    int stride = gridDim.x * blockDim.x;
    float4 z4 = make_float4(0.f, 0.f, 0.f, 0.f);
    for (int k = i; k < NV * 32; k += stride) reinterpret_cast<float4*>(g_agg)[k] = z4;
    for (int k = i; k < NV; k += stride) g_deg[k] = 0.0f;
    if (i < 128) { g_vsum[i] = 0.0f; g_vmax[i] = -3.402823466e38f; }
}

__global__ void wprep_kernel(const float* __restrict__ We1, const float* __restrict__ We2,
                             const float* __restrict__ Wn1, const float* __restrict__ Wn2) {
    int i = blockIdx.x * blockDim.x + threadIdx.x;
    int stride = gridDim.x * blockDim.x;
    for (int idx = i; idx < 320 * 128; idx += stride) {
        int k = idx >> 7, n = idx & 127;
        float v = We1[idx];
        __nv_bfloat16 h = __float2bfloat16(v);
        __nv_bfloat16 l = __float2bfloat16(v - __bfloat162float(h));
        if (k < 64)       { WE1h[n * 64 + k] = h;          WE1l[n * 64 + k] = l; }
        else if (k < 192) { WS1h[n * 128 + (k - 64)] = h;  WS1l[n * 128 + (k - 64)] = l; }
        else              { WD1h[n * 128 + (k - 192)] = h; WD1l[n * 128 + (k - 192)] = l; }
    }
    for (int idx = i; idx < 128 * 128; idx += stride) {
        int k = idx >> 7, n = idx & 127;
        float v = We2[idx];
        __nv_bfloat16 h = __float2bfloat16(v);
        WB2h[n * 128 + k] = h;
        WB2l[n * 128 + k] = __float2bfloat16(v - __bfloat162float(h));
    }
    for (int idx = i; idx < 256 * 128; idx += stride) {
        int k = idx >> 7, n = idx & 127;
        float v = Wn1[idx];
        __nv_bfloat16 h = __float2bfloat16(v);
        WN1h[n * 256 + k] = h;
        WN1l[n * 256 + k] = __float2bfloat16(v - __bfloat162float(h));
    }
    for (int idx = i; idx < 128 * 128; idx += stride) {
        int k = idx >> 7, n = idx & 127;
        float v = Wn2[idx];
        __nv_bfloat16 h = __float2bfloat16(v);
        WN2h[n * 128 + k] = h;
        WN2l[n * 128 + k] = __float2bfloat16(v - __bfloat162float(h));
    }
}

// c[n] = bn1[n] + sum z[k] Wn1[256+k][n] + sum u[k] Wn1[384+k][n]
__global__ void cnode_kernel(const float* __restrict__ Wn1, const float* __restrict__ bn1,
                             const float* __restrict__ z, const float* __restrict__ u) {
    int t = threadIdx.x;
    float c = bn1[t];
    for (int k = 0; k < 128; k++) c = fmaf(z[k], Wn1[(256 + k) * 128 + t], c);
    for (int k = 0; k < 64; k++)  c = fmaf(u[k], Wn1[(384 + k) * 128 + t], c);
    g_cnode[t] = c;
}

// ============================ pgemm: P_s, P_d ===============================
__global__ __launch_bounds__(256, 2) void pgemm_kernel(const float* __restrict__ V) {
    __nv_bfloat16* sA = reinterpret_cast<__nv_bfloat16*>(dynbase);
    const int tid = threadIdx.x, lane = tid & 31, w = tid >> 5;
    const int wm = w >> 1, wn = w & 1;
    const int nbase = blockIdx.x * 128;
    const int row = tid >> 1, half = tid & 1;
    const int n = nbase + row;
    const size_t nc = (n < NV) ? (size_t)n : (size_t)(NV - 1);

    const uint32_t aS = smem_u32(dynbase), bS = aS + B_OFF;

    issue_w(WS1h, WS1l, 128, 0, bS, row, half);
    CP_COMMIT();
    // V row -> both A slots (thread handles 64 floats = one K-half, slot = half)
    {
        float4 rv[16];
        const float4* vp = reinterpret_cast<const float4*>(V + nc * 128 + half * 64);
#pragma unroll
        for (int g = 0; g < 16; g++) rv[g] = vp[g];
        __nv_bfloat16* hd = sA + row * 280 + half * 144;
        split_regs(rv, 1.0f, hd, hd + 64);
        split_regs(rv + 8, 1.0f, hd + 32, hd + 96);
    }
    CP_WAIT0(); __syncthreads();

    float acc[64];
#pragma unroll
    for (int i = 0; i < 64; i++) acc[i] = 0.0f;
    mma_chunk2(acc, aS, bS, wm, wn, lane, 0);
    __syncthreads();
    issue_w(WS1h, WS1l, 128, 1, bS, row, half);
    CP_COMMIT(); CP_WAIT0(); __syncthreads();
    mma_chunk2(acc, aS, bS, wm, wn, lane, 144);
    store_p(acc, g_Ps, nbase, wm, wn, lane);
    __syncthreads();
    issue_w(WD1h, WD1l, 128, 0, bS, row, half);
    CP_COMMIT(); CP_WAIT0(); __syncthreads();
#pragma unroll
    for (int i = 0; i < 64; i++) acc[i] = 0.0f;
    mma_chunk2(acc, aS, bS, wm, wn, lane, 0);
    __syncthreads();
    issue_w(WD1h, WD1l, 128, 1, bS, row, half);
    CP_COMMIT(); CP_WAIT0(); __syncthreads();
    mma_chunk2(acc, aS, bS, wm, wn, lane, 144);
    store_p(acc, g_Pd, nbase, wm, wn, lane);
}

// ============================ edge kernel ===================================
// H = relu(E@W1e + Ps[src] + Pd[dst] + b1); C = H@W2 + b2 -> scatter agg[dst]
__global__ __launch_bounds__(256, 2) void edge_kernel(
    const float* __restrict__ E, const int* __restrict__ ei,
    const float* __restrict__ b1, const float* __restrict__ b2)
{
    __nv_bfloat16* sA = reinterpret_cast<__nv_bfloat16*>(dynbase);
    __shared__ float sb1[128], sb2[128];
    __shared__ int sSrc[128], sDst[128];

    const int tid = threadIdx.x, lane = tid & 31, w = tid >> 5;
    const int wm = w >> 1, wn = w & 1;
    const int ebase = blockIdx.x * 128;
    const int row = tid >> 1, half = tid & 1;

    const uint32_t aS = smem_u32(dynbase), bS = aS + B_OFF;

    issue_w(WE1h, WE1l, 64, 0, bS, row, half);
    CP_COMMIT();

    if (tid < 128) {
        sb1[tid] = b1[tid];
        int s = ei[ebase + tid], d = ei[NE + ebase + tid];
        sSrc[tid] = s; sDst[tid] = d;
        atomicAdd(&g_deg[d], 1.0f);
    } else {
        sb2[tid - 128] = b2[tid - 128];
    }
    // E chunk -> A slot0 (direct LDG + split)
    {
        float4 rv[8];
        const float4* ep = reinterpret_cast<const float4*>(E + (size_t)(ebase + row) * 64 + half * 32);
#pragma unroll
        for (int g = 0; g < 8; g++) rv[g] = ep[g];
        split_regs(rv, 1.0f, sA + row * 280 + half * 32, sA + row * 280 + 64 + half * 32);
    }
    CP_WAIT0(); __syncthreads();

    float acc[64];
#pragma unroll
    for (int i = 0; i < 64; i++) acc[i] = 0.0f;
    mma_chunk2(acc, aS, bS, wm, wn, lane, 0);      // GEMM1: E x W1e
    add_p_gmem(acc, g_Ps, sSrc, wm, wn, lane);     // += Ps[src]
    add_p_gmem(acc, g_Pd, sDst, wm, wn, lane);     // += Pd[dst]
    __syncthreads();   // RACE FIX: band-partner warp's slot0 ldsm reads must
                       // finish before hsplit overwrites slot0
    hsplit(acc, sA, sb1, wm, wn, lane);            // relu(+b1) -> A slots (own band)
    __syncthreads();                               // hsplit visible + B reads done
    issue_w(WB2h, WB2l, 128, 0, bS, row, half);
    CP_COMMIT();
#pragma unroll
    for (int i = 0; i < 64; i++) acc[i] = 0.0f;
    CP_WAIT0(); __syncthreads();
    mma_chunk2(acc, aS, bS, wm, wn, lane, 0);      // GEMM2 c0
    __syncthreads();
    issue_w(WB2h, WB2l, 128, 1, bS, row, half);
    CP_COMMIT(); CP_WAIT0(); __syncthreads();
    mma_chunk2(acc, aS, bS, wm, wn, lane, 144);    // GEMM2 c1
    __syncthreads();   // RACE FIX: partner's slot1 ldsm reads finish before
                       // stage_out140 overwrites the A region as f32

    float* st = reinterpret_cast<float*>(dynbase); // A reuse, stride 140
    stage_out140(acc, st, sb2, wm, wn, lane);      // own band writes
    __syncthreads();
#pragma unroll
    for (int i = 0; i < 16; i++) {
        int idx = tid + i * 256;
        int r = idx >> 5, c4 = (idx & 31) * 4;
        float4 v = *reinterpret_cast<float4*>(st + r * 140 + c4);
        red4(&g_agg[(size_t)sDst[r] * 128 + c4], v.x, v.y, v.z, v.w);
    }
}

// ============================ node kernel ===================================
// V' = relu([agg/deg | V] @ W1' + c) @ W2 + b2
__global__ __launch_bounds__(256, 2) void node_kernel(
    const float* __restrict__ V,
    const float* __restrict__ b2, float* __restrict__ out)
{
    __nv_bfloat16* sA = reinterpret_cast<__nv_bfloat16*>(dynbase);
    __shared__ float sb1[128], sb2[128];

    const int tid = threadIdx.x, lane = tid & 31, w = tid >> 5;
    const int wm = w >> 1, wn = w & 1;
    const int nbase = blockIdx.x * 128;
    const int row = tid >> 1, half = tid & 1;

    const uint32_t aS = smem_u32(dynbase), bS = aS + B_OFF;

    const int n = nbase + row;
    const bool valid = n < NV;
    const size_t nc = valid ? (size_t)n : (size_t)(NV - 1);

    if (tid < 128) sb1[tid] = g_cnode[tid];
    else           sb2[tid - 128] = b2[tid - 128];
    const float inv = valid ? 1.0f / fmaxf(g_deg[nc], 1.0f) : 0.0f;

    issue_w(WN1h, WN1l, 256, 0, bS, row, half);
    CP_COMMIT();
    {   // raw chunk0: agg low half
        float4 rv[8];
        const float4* p = reinterpret_cast<const float4*>(g_agg + nc * 128 + half * 32);
#pragma unroll
        for (int g = 0; g < 8; g++) rv[g] = p[g];
        split_regs(rv, inv, sA + row * 280 + half * 32, sA + row * 280 + 64 + half * 32);
    }
    CP_WAIT0(); __syncthreads();

    float acc[64];
#pragma unroll
    for (int i = 0; i < 64; i++) acc[i] = 0.0f;

    // GEMM1: 4 chunks (agg0, agg1, V0, V1); slot alternates s&1
    for (int s = 0; s < 4; s++) {
        mma_chunk2(acc, aS, bS, wm, wn, lane, (s & 1) * 144);
        __syncthreads();                               // B consumers done
        if (s < 3) {
            issue_w(WN1h, WN1l, 256, s + 1, bS, row, half);
            CP_COMMIT();
            const float* src = (s == 0) ? g_agg + nc * 128 + 64 + half * 32
                             : (s == 1) ? V + nc * 128 + half * 32
                                        : V + nc * 128 + 64 + half * 32;
            float4 rv[8];
            const float4* p = reinterpret_cast<const float4*>(src);
#pragma unroll
            for (int g = 0; g < 8; g++) rv[g] = p[g];
            int so = ((s + 1) & 1) * 144;
            split_regs(rv, (s == 0) ? inv : 1.0f,
                       sA + row * 280 + so + half * 32,
                       sA + row * 280 + so + 64 + half * 32);
        } else {
            issue_w(WN2h, WN2l, 128, 0, bS, row, half);
            CP_COMMIT();
        }
        CP_WAIT0(); __syncthreads();
    }

    hsplit(acc, sA, sb1, wm, wn, lane);                // own band; safe (barrier above)
    __syncthreads();   // RACE FIX: hsplit writes visible to band-partner
                       // before GEMM2 c0 ldsm reads slot0
#pragma unroll
    for (int i = 0; i < 64; i++) acc[i] = 0.0f;
    mma_chunk2(acc, aS, bS, wm, wn, lane, 0);          // GEMM2 c0
    __syncthreads();
    issue_w(WN2h, WN2l, 128, 1, bS, row, half);
    CP_COMMIT(); CP_WAIT0(); __syncthreads();
    mma_chunk2(acc, aS, bS, wm, wn, lane, 144);        // GEMM2 c1
    __syncthreads();   // RACE FIX: slot1 ldsm reads finish before f32 staging

    float* st = reinterpret_cast<float*>(dynbase);
    stage_out140(acc, st, sb2, wm, wn, lane);
    __syncthreads();
#pragma unroll
    for (int i = 0; i < 16; i++) {
        int idx = tid + i * 256;
        int r = idx >> 5, c4 = (idx & 31) * 4;
        int nn = nbase + r;
        if (nn < NV) {
            float4 v = *reinterpret_cast<float4*>(st + r * 140 + c4);
            *reinterpret_cast<float4*>(out + (size_t)nn * 128 + c4) = v;
        }
    }
}

// ======================= V' column sum/max reduce ===========================
__global__ void reduce_kernel(const float* __restrict__ out) {
    const int t = threadIdx.x;
    const int b = blockIdx.x;
    float s = 0.0f, mx = -3.402823466e38f;
    for (int r = b * 250; r < (b + 1) * 250; r++) {
        float v = out[(size_t)r * 128 + t];
        s += v;
        mx = fmaxf(mx, v);
    }
    atomicAdd(&g_vsum[t], s);
    atomicMaxF(&g_vmax[t], mx);
}

// ============================ global kernel =================================
__global__ void global_kernel(
    const float* __restrict__ z, const float* __restrict__ u,
    const float* __restrict__ Wg1, const float* __restrict__ bg1,
    const float* __restrict__ Wg2, const float* __restrict__ bg2,
    const float* __restrict__ Wu1, const float* __restrict__ bu1,
    const float* __restrict__ Wu2, const float* __restrict__ bu2,
    float* __restrict__ out)
{
    __shared__ float x[448], h[128], part[4][128], zp[128];
    const int tid = threadIdx.x;         // 512
    const int t = tid & 127, s = tid >> 7;

    if (tid < 128)      x[tid] = g_vsum[tid] * (1.0f / (float)NV);
    else if (tid < 256) x[tid] = z[tid - 128];
    __syncthreads();

    {
        float acc = 0.0f;
        for (int k = s * 64; k < s * 64 + 64; k++) acc = fmaf(x[k], Wg1[k * 128 + t], acc);
        part[s][t] = acc;
    }
    __syncthreads();
    if (s == 0) h[t] = fmaxf(part[0][t] + part[1][t] + part[2][t] + part[3][t] + bg1[t], 0.0f);
    __syncthreads();
    {
        float acc = 0.0f;
        for (int k = s * 32; k < s * 32 + 32; k++) acc = fmaf(h[k], Wg2[k * 128 + t], acc);
        part[s][t] = acc;
    }
    __syncthreads();
    if (s == 0) {
        float v = part[0][t] + part[1][t] + part[2][t] + part[3][t] + bg2[t];
        zp[t] = v;
        out[(size_t)NV * 128 + 64 + t] = v;
        x[128 + t] = g_vmax[t];
    }
    __syncthreads();
    if (tid < 128)      x[256 + tid] = zp[tid];
    else if (tid < 192) x[384 + (tid - 128)] = u[tid - 128];
    __syncthreads();
    {
        float acc = 0.0f;
        for (int k = s * 112; k < s * 112 + 112; k++) acc = fmaf(x[k], Wu1[k * 128 + t], acc);
        part[s][t] = acc;
    }
    __syncthreads();
    if (s == 0) h[t] = fmaxf(part[0][t] + part[1][t] + part[2][t] + part[3][t] + bu1[t], 0.0f);
    __syncthreads();
    if (t < 64) {
        float acc = 0.0f;
        for (int k = s * 32; k < s * 32 + 32; k++) acc = fmaf(h[k], Wu2[k * 64 + t], acc);
        part[s][t] = acc;
    }
    __syncthreads();
    if (s == 0 && t < 64)
        out[(size_t)NV * 128 + t] = part[0][t] + part[1][t] + part[2][t] + part[3][t] + bu2[t];
}

// ============================ launch ========================================
extern "C" void kernel_launch(void* const* d_in, const int* in_sizes, int n_in,
                              void* d_out, int out_size) {
    const float* V   = (const float*)d_in[0];
    const float* E   = (const float*)d_in[1];
    const int*   ei  = (const int*)d_in[2];
    const float* u   = (const float*)d_in[3];
    const float* z   = (const float*)d_in[4];
    const float* We1 = (const float*)d_in[5];
    const float* be1 = (const float*)d_in[6];
    const float* We2 = (const float*)d_in[7];
    const float* be2 = (const float*)d_in[8];
    const float* Wn1 = (const float*)d_in[9];
    const float* bn1 = (const float*)d_in[10];
    const float* Wn2 = (const float*)d_in[11];
    const float* bn2 = (const float*)d_in[12];
    const float* Wg1 = (const float*)d_in[13];
    const float* bg1 = (const float*)d_in[14];
    const float* Wg2 = (const float*)d_in[15];
    const float* bg2 = (const float*)d_in[16];
    const float* Wu1 = (const float*)d_in[17];
    const float* bu1 = (const float*)d_in[18];
    const float* Wu2 = (const float*)d_in[19];
    const float* bu2 = (const float*)d_in[20];
    float* out = (float*)d_out;

    cudaFuncSetAttribute(pgemm_kernel, cudaFuncAttributeMaxDynamicSharedMemorySize, SMEM_TOTAL);
    cudaFuncSetAttribute(edge_kernel, cudaFuncAttributeMaxDynamicSharedMemorySize, SMEM_TOTAL);
    cudaFuncSetAttribute(node_kernel, cudaFuncAttributeMaxDynamicSharedMemorySize, SMEM_TOTAL);

    init_kernel<<<512, 256>>>();
    wprep_kernel<<<256, 256>>>(We1, We2, Wn1, Wn2);
    cnode_kernel<<<1, 128>>>(Wn1, bn1, z, u);
    pgemm_kernel<<<(NV + 127) / 128, 256, SMEM_TOTAL>>>(V);
    edge_kernel<<<NE / 128, 256, SMEM_TOTAL>>>(E, ei, be1, be2);
    node_kernel<<<(NV + 127) / 128, 256, SMEM_TOTAL>>>(V, bn2, out);
    reduce_kernel<<<200, 128>>>(out);
    global_kernel<<<1, 512>>>(z, u, Wg1, bg1, Wg2, bg2, Wu1, bu1, Wu2, bu2, out);
}

// round 16
// speedup vs baseline: 3.8787x; 1.0183x over previous
#include <cuda_runtime.h>
#include <cuda_bf16.h>
#include <cstdint>

#define NV 50000
#define NE 800000
#define NTILES (NE / 128)   // 6250
#define EGRID 148

// ============================ device globals ================================
__device__ float g_agg[(size_t)NV * 128];
__device__ float g_deg[NV];
__device__ float g_vsum[128];
__device__ float g_vmax[128];
__device__ float g_Ps[(size_t)NV * 128];   // V @ W1s^T
__device__ float g_Pd[(size_t)NV * 128];   // V @ W1d^T
__device__ float g_cnode[128];             // z@W1z + u@W1u + b1 (node)
// pre-split transposed weights [n][k] bf16 hi/lo
__device__ __nv_bfloat16 WE1h[128 * 64],  WE1l[128 * 64];    // We1 rows 0..63
__device__ __nv_bfloat16 WS1h[128 * 128], WS1l[128 * 128];   // We1 rows 64..191
__device__ __nv_bfloat16 WD1h[128 * 128], WD1l[128 * 128];   // We1 rows 192..319
__device__ __nv_bfloat16 WB2h[128 * 128], WB2l[128 * 128];
__device__ __nv_bfloat16 WN1h[128 * 256], WN1l[128 * 256];   // Wn1 rows 0..255
__device__ __nv_bfloat16 WN2h[128 * 128], WN2l[128 * 128];

// pgemm/node smem (2 CTAs/SM):  A[0,71680) + B[71680,+34816)
#define B_OFF 71680
#define SMEM_TOTAL (B_OFF + 34816)        // 106496
// edge persistent smem (1 CTA/SM): A[0,71680) + W0,W1,W2 chunks resident
#define EW0_OFF 71680
#define ESMEM_TOTAL (EW0_OFF + 3 * 34816) // 176128

extern __shared__ char dynbase[];

// ============================ helpers =======================================
__device__ __forceinline__ uint32_t smem_u32(const void* p) {
    uint32_t a;
    asm("{ .reg .u64 t; cvta.to.shared.u64 t, %1; cvt.u32.u64 %0, t; }" : "=r"(a) : "l"(p));
    return a;
}
__device__ __forceinline__ void ldsm4(uint32_t* r, uint32_t addr) {
    asm volatile("ldmatrix.sync.aligned.m8n8.x4.shared.b16 {%0,%1,%2,%3}, [%4];"
                 : "=r"(r[0]), "=r"(r[1]), "=r"(r[2]), "=r"(r[3]) : "r"(addr));
}
__device__ __forceinline__ void mma16816(float* d, const uint32_t* a, const uint32_t* b) {
    asm volatile("mma.sync.aligned.m16n8k16.row.col.f32.bf16.bf16.f32 "
                 "{%0,%1,%2,%3}, {%4,%5,%6,%7}, {%8,%9}, {%0,%1,%2,%3};"
                 : "+f"(d[0]), "+f"(d[1]), "+f"(d[2]), "+f"(d[3])
                 : "r"(a[0]), "r"(a[1]), "r"(a[2]), "r"(a[3]), "r"(b[0]), "r"(b[1]));
}
__device__ __forceinline__ void red4(float* p, float a, float b, float c, float d) {
    asm volatile("red.global.add.v4.f32 [%0], {%1, %2, %3, %4};"
                 :: "l"(p), "f"(a), "f"(b), "f"(c), "f"(d) : "memory");
}
__device__ __forceinline__ void atomicMaxF(float* addr, float val) {
    int old = __float_as_int(*addr);
    while (__int_as_float(old) < val) {
        int assumed = old;
        old = atomicCAS((int*)addr, assumed, __float_as_int(val));
        if (old == assumed) break;
    }
}
__device__ __forceinline__ void cp16(uint32_t dst, const void* src, int sz) {
    asm volatile("cp.async.cg.shared.global [%0], [%1], 16, %2;"
                 :: "r"(dst), "l"(src), "r"(sz) : "memory");
}
#define CP_COMMIT() asm volatile("cp.async.commit_group;" ::: "memory")
#define CP_WAIT0()  asm volatile("cp.async.wait_group 0;" ::: "memory")

// split 32 fp32 regs (scaled) -> bf16 hi/lo (64B each) to smem
__device__ __forceinline__ void split_regs(const float4* f, float scale,
                                           __nv_bfloat16* hptr, __nv_bfloat16* lptr) {
    uint32_t H[16], L[16];
#pragma unroll
    for (int g = 0; g < 8; g++) {
        float4 v = f[g];
        v.x *= scale; v.y *= scale; v.z *= scale; v.w *= scale;
        __nv_bfloat162 h0 = __floats2bfloat162_rn(v.x, v.y);
        __nv_bfloat162 l0 = __floats2bfloat162_rn(v.x - __low2float(h0), v.y - __high2float(h0));
        __nv_bfloat162 h1 = __floats2bfloat162_rn(v.z, v.w);
        __nv_bfloat162 l1 = __floats2bfloat162_rn(v.z - __low2float(h1), v.w - __high2float(h1));
        H[g * 2 + 0] = *reinterpret_cast<uint32_t*>(&h0);
        H[g * 2 + 1] = *reinterpret_cast<uint32_t*>(&h1);
        L[g * 2 + 0] = *reinterpret_cast<uint32_t*>(&l0);
        L[g * 2 + 1] = *reinterpret_cast<uint32_t*>(&l1);
    }
    uint4* dh = reinterpret_cast<uint4*>(hptr);
    uint4* dl = reinterpret_cast<uint4*>(lptr);
#pragma unroll
    for (int q = 0; q < 4; q++) {
        dh[q] = make_uint4(H[q * 4], H[q * 4 + 1], H[q * 4 + 2], H[q * 4 + 3]);
        dl[q] = make_uint4(L[q * 4], L[q * 4 + 1], L[q * 4 + 2], L[q * 4 + 3]);
    }
}

// one weight half-row chunk (hi+lo, 32+32 bf16) -> B buf via cp.async
__device__ __forceinline__ void issue_w(const __nv_bfloat16* Wh, const __nv_bfloat16* Wl,
                                        int stride, int chunk, uint32_t bBuf,
                                        int row, int half) {
    const __nv_bfloat16* sh = Wh + (size_t)row * stride + chunk * 64 + half * 32;
    const __nv_bfloat16* sl = Wl + (size_t)row * stride + chunk * 64 + half * 32;
    uint32_t dh = bBuf + (uint32_t)(row * 272 + half * 64);
    uint32_t dl = dh + 128;
#pragma unroll
    for (int g = 0; g < 4; g++) { cp16(dh + g * 16, sh + g * 8, 16); cp16(dl + g * 16, sl + g * 8, 16); }
}

// one 64-k chunk, bf16x3: acc += Ah*Bh + Al*Bh + Ah*Bl
__device__ __forceinline__ void mma_chunk2(float* acc, uint32_t aS, uint32_t bS,
                                           int wm, int wn, int lane, int abase) {
#pragma unroll
    for (int ks = 0; ks < 4; ks++) {
        const int kb = ks * 16;
        uint32_t ah[2][4], al[2][4], bh[4][4], bl[4][4];
#pragma unroll
        for (int mi = 0; mi < 2; mi++) {
            int r = wm * 32 + mi * 16 + (lane & 15);
            ldsm4(ah[mi], aS + ((uint32_t)(r * 280 + abase + kb + ((lane >> 4) << 3)) << 1));
        }
#pragma unroll
        for (int np = 0; np < 4; np++) {
            int rowb = wn * 64 + np * 16 + (lane & 7) + ((lane >> 4) << 3);
            int k = kb + (((lane >> 3) & 1) << 3);
            ldsm4(bh[np], bS + ((uint32_t)(rowb * 136 + k) << 1));
        }
#pragma unroll
        for (int mi = 0; mi < 2; mi++)
#pragma unroll
            for (int ni = 0; ni < 8; ni++)
                mma16816(&acc[(mi * 8 + ni) * 4], ah[mi], &bh[ni >> 1][(ni & 1) * 2]);
#pragma unroll
        for (int mi = 0; mi < 2; mi++) {
            int r = wm * 32 + mi * 16 + (lane & 15);
            ldsm4(al[mi], aS + ((uint32_t)(r * 280 + abase + 64 + kb + ((lane >> 4) << 3)) << 1));
        }
#pragma unroll
        for (int mi = 0; mi < 2; mi++)
#pragma unroll
            for (int ni = 0; ni < 8; ni++)
                mma16816(&acc[(mi * 8 + ni) * 4], al[mi], &bh[ni >> 1][(ni & 1) * 2]);
#pragma unroll
        for (int np = 0; np < 4; np++) {
            int rowb = wn * 64 + np * 16 + (lane & 7) + ((lane >> 4) << 3);
            int k = kb + (((lane >> 3) & 1) << 3);
            ldsm4(bl[np], bS + ((uint32_t)(rowb * 136 + 64 + k) << 1));
        }
#pragma unroll
        for (int mi = 0; mi < 2; mi++)
#pragma unroll
            for (int ni = 0; ni < 8; ni++)
                mma16816(&acc[(mi * 8 + ni) * 4], ah[mi], &bl[ni >> 1][(ni & 1) * 2]);
    }
}

// bias+relu+split fragments into A slots 0/1 (own 32-row band only)
__device__ __forceinline__ void hsplit(const float* acc, __nv_bfloat16* sA,
                                       const float* sb1, int wm, int wn, int lane) {
#pragma unroll
    for (int mi = 0; mi < 2; mi++)
#pragma unroll
        for (int ni = 0; ni < 8; ni++) {
            const float* a4 = &acc[(mi * 8 + ni) * 4];
            int c = wn * 64 + ni * 8 + 2 * (lane & 3);
            int soff = (c >> 6) * 144, kk = c & 63;
            float bb0 = sb1[c], bb1 = sb1[c + 1];
            int r0 = wm * 32 + mi * 16 + (lane >> 2);
#pragma unroll
            for (int hh = 0; hh < 2; hh++) {
                int r = r0 + hh * 8;
                float v0 = fmaxf(a4[hh * 2 + 0] + bb0, 0.0f);
                float v1 = fmaxf(a4[hh * 2 + 1] + bb1, 0.0f);
                __nv_bfloat162 hv = __floats2bfloat162_rn(v0, v1);
                __nv_bfloat162 lv = __floats2bfloat162_rn(v0 - __low2float(hv), v1 - __high2float(hv));
                *reinterpret_cast<uint32_t*>(sA + r * 280 + soff + kk) = *reinterpret_cast<uint32_t*>(&hv);
                *reinterpret_cast<uint32_t*>(sA + r * 280 + soff + 64 + kk) = *reinterpret_cast<uint32_t*>(&lv);
            }
        }
}

// acc += P[idx[r]][c] via direct gmem loads (L2-resident P)
__device__ __forceinline__ void add_p_gmem(float* acc, const float* __restrict__ P,
                                           const int* sIdx, int wm, int wn, int lane) {
#pragma unroll
    for (int mi = 0; mi < 2; mi++)
#pragma unroll
        for (int hh = 0; hh < 2; hh++) {
            int r = wm * 32 + mi * 16 + hh * 8 + (lane >> 2);
            const float* prow = P + (size_t)sIdx[r] * 128;
#pragma unroll
            for (int ni = 0; ni < 8; ni++) {
                int c = wn * 64 + ni * 8 + 2 * (lane & 3);
                float2 p = *reinterpret_cast<const float2*>(prow + c);
                acc[(mi * 8 + ni) * 4 + hh * 2 + 0] += p.x;
                acc[(mi * 8 + ni) * 4 + hh * 2 + 1] += p.y;
            }
        }
}

// stage fragments (+bias) to f32 smem stride 140 (A region reuse)
__device__ __forceinline__ void stage_out140(const float* acc, float* st, const float* sb2,
                                             int wm, int wn, int lane) {
#pragma unroll
    for (int mi = 0; mi < 2; mi++)
#pragma unroll
        for (int ni = 0; ni < 8; ni++) {
            const float* a4 = &acc[(mi * 8 + ni) * 4];
            int c = wn * 64 + ni * 8 + 2 * (lane & 3);
            float bb0 = sb2[c], bb1 = sb2[c + 1];
            int r0 = wm * 32 + mi * 16 + (lane >> 2);
            st[r0 * 140 + c] = a4[0] + bb0;
            st[r0 * 140 + c + 1] = a4[1] + bb1;
            st[(r0 + 8) * 140 + c] = a4[2] + bb0;
            st[(r0 + 8) * 140 + c + 1] = a4[3] + bb1;
        }
}

// store fragments directly to a [*,128] f32 gmem array (row nbase+r, no bias)
__device__ __forceinline__ void store_p(const float* acc, float* P, int nbase,
                                        int wm, int wn, int lane) {
#pragma unroll
    for (int mi = 0; mi < 2; mi++)
#pragma unroll
        for (int hh = 0; hh < 2; hh++) {
            int r = wm * 32 + mi * 16 + hh * 8 + (lane >> 2);
            int n = nbase + r;
            if (n < NV) {
                float* prow = P + (size_t)n * 128;
#pragma unroll
                for (int ni = 0; ni < 8; ni++) {
                    int c = wn * 64 + ni * 8 + 2 * (lane & 3);
                    *reinterpret_cast<float2*>(prow + c) =
                        make_float2(acc[(mi * 8 + ni) * 4 + hh * 2 + 0],
                                    acc[(mi * 8 + ni) * 4 + hh * 2 + 1]);
                }
            }
        }
}

// ============================ small kernels =================================
__global__ void init_kernel() {
    int i = blockIdx.x * blockDim.x + threadIdx.x;
    int stride = gridDim.x * blockDim.x;
    float4 z4 = make_float4(0.f, 0.f, 0.f, 0.f);
    for (int k = i; k < NV * 32; k += stride) reinterpret_cast<float4*>(g_agg)[k] = z4;
    for (int k = i; k < NV; k += stride) g_deg[k] = 0.0f;
    if (i < 128) { g_vsum[i] = 0.0f; g_vmax[i] = -3.402823466e38f; }
}

__global__ void wprep_kernel(const float* __restrict__ We1, const float* __restrict__ We2,
                             const float* __restrict__ Wn1, const float* __restrict__ Wn2) {
    int i = blockIdx.x * blockDim.x + threadIdx.x;
    int stride = gridDim.x * blockDim.x;
    for (int idx = i; idx < 320 * 128; idx += stride) {
        int k = idx >> 7, n = idx & 127;
        float v = We1[idx];
        __nv_bfloat16 h = __float2bfloat16(v);
        __nv_bfloat16 l = __float2bfloat16(v - __bfloat162float(h));
        if (k < 64)       { WE1h[n * 64 + k] = h;          WE1l[n * 64 + k] = l; }
        else if (k < 192) { WS1h[n * 128 + (k - 64)] = h;  WS1l[n * 128 + (k - 64)] = l; }
        else              { WD1h[n * 128 + (k - 192)] = h; WD1l[n * 128 + (k - 192)] = l; }
    }
    for (int idx = i; idx < 128 * 128; idx += stride) {
        int k = idx >> 7, n = idx & 127;
        float v = We2[idx];
        __nv_bfloat16 h = __float2bfloat16(v);
        WB2h[n * 128 + k] = h;
        WB2l[n * 128 + k] = __float2bfloat16(v - __bfloat162float(h));
    }
    for (int idx = i; idx < 256 * 128; idx += stride) {
        int k = idx >> 7, n = idx & 127;
        float v = Wn1[idx];
        __nv_bfloat16 h = __float2bfloat16(v);
        WN1h[n * 256 + k] = h;
        WN1l[n * 256 + k] = __float2bfloat16(v - __bfloat162float(h));
    }
    for (int idx = i; idx < 128 * 128; idx += stride) {
        int k = idx >> 7, n = idx & 127;
        float v = Wn2[idx];
        __nv_bfloat16 h = __float2bfloat16(v);
        WN2h[n * 128 + k] = h;
        WN2l[n * 128 + k] = __float2bfloat16(v - __bfloat162float(h));
    }
}

// c[n] = bn1[n] + sum z[k] Wn1[256+k][n] + sum u[k] Wn1[384+k][n]
__global__ void cnode_kernel(const float* __restrict__ Wn1, const float* __restrict__ bn1,
                             const float* __restrict__ z, const float* __restrict__ u) {
    int t = threadIdx.x;
    float c = bn1[t];
    for (int k = 0; k < 128; k++) c = fmaf(z[k], Wn1[(256 + k) * 128 + t], c);
    for (int k = 0; k < 64; k++)  c = fmaf(u[k], Wn1[(384 + k) * 128 + t], c);
    g_cnode[t] = c;
}

// ============================ pgemm: P_s, P_d ===============================
__global__ __launch_bounds__(256, 2) void pgemm_kernel(const float* __restrict__ V) {
    __nv_bfloat16* sA = reinterpret_cast<__nv_bfloat16*>(dynbase);
    const int tid = threadIdx.x, lane = tid & 31, w = tid >> 5;
    const int wm = w >> 1, wn = w & 1;
    const int nbase = blockIdx.x * 128;
    const int row = tid >> 1, half = tid & 1;
    const int n = nbase + row;
    const size_t nc = (n < NV) ? (size_t)n : (size_t)(NV - 1);

    const uint32_t aS = smem_u32(dynbase), bS = aS + B_OFF;

    issue_w(WS1h, WS1l, 128, 0, bS, row, half);
    CP_COMMIT();
    {
        float4 rv[16];
        const float4* vp = reinterpret_cast<const float4*>(V + nc * 128 + half * 64);
#pragma unroll
        for (int g = 0; g < 16; g++) rv[g] = vp[g];
        __nv_bfloat16* hd = sA + row * 280 + half * 144;
        split_regs(rv, 1.0f, hd, hd + 64);
        split_regs(rv + 8, 1.0f, hd + 32, hd + 96);
    }
    CP_WAIT0(); __syncthreads();

    float acc[64];
#pragma unroll
    for (int i = 0; i < 64; i++) acc[i] = 0.0f;
    mma_chunk2(acc, aS, bS, wm, wn, lane, 0);
    __syncthreads();
    issue_w(WS1h, WS1l, 128, 1, bS, row, half);
    CP_COMMIT(); CP_WAIT0(); __syncthreads();
    mma_chunk2(acc, aS, bS, wm, wn, lane, 144);
    store_p(acc, g_Ps, nbase, wm, wn, lane);
    __syncthreads();
    issue_w(WD1h, WD1l, 128, 0, bS, row, half);
    CP_COMMIT(); CP_WAIT0(); __syncthreads();
#pragma unroll
    for (int i = 0; i < 64; i++) acc[i] = 0.0f;
    mma_chunk2(acc, aS, bS, wm, wn, lane, 0);
    __syncthreads();
    issue_w(WD1h, WD1l, 128, 1, bS, row, half);
    CP_COMMIT(); CP_WAIT0(); __syncthreads();
    mma_chunk2(acc, aS, bS, wm, wn, lane, 144);
    store_p(acc, g_Pd, nbase, wm, wn, lane);
}

// ============================ edge kernel (persistent) ======================
// Per tile: H = relu(E@W1e + Ps[src] + Pd[dst] + b1); C = H@W2 + b2 -> agg[dst]
// Weights (WE1, WB2 c0/c1) resident in smem; E + indices prefetched in regs.
__global__ __launch_bounds__(256) void edge_kernel(
    const float* __restrict__ E, const int* __restrict__ ei,
    const float* __restrict__ b1, const float* __restrict__ b2)
{
    __nv_bfloat16* sA = reinterpret_cast<__nv_bfloat16*>(dynbase);
    __shared__ float sb1[128], sb2[128];
    __shared__ int sSrc[128], sDst[128];

    const int tid = threadIdx.x, lane = tid & 31, w = tid >> 5;
    const int wm = w >> 1, wn = w & 1;
    const int row = tid >> 1, half = tid & 1;

    const uint32_t aS = smem_u32(dynbase);
    const uint32_t wS0 = aS + EW0_OFF;            // WE1 chunk
    const uint32_t wS1 = wS0 + 34816;             // WB2 chunk0
    const uint32_t wS2 = wS1 + 34816;             // WB2 chunk1

    // resident weights (loaded once)
    issue_w(WE1h, WE1l, 64, 0, wS0, row, half);
    issue_w(WB2h, WB2l, 128, 0, wS1, row, half);
    issue_w(WB2h, WB2l, 128, 1, wS2, row, half);
    CP_COMMIT();

    if (tid < 128) sb1[tid] = b1[tid];
    else           sb2[tid - 128] = b2[tid - 128];

    int t = blockIdx.x;
    int src = 0, dst = 0;
    float4 eR[8];
    {   // prefetch first tile (t < NTILES always: grid 148 << 6250)
        src = ei[t * 128 + row];
        dst = ei[NE + t * 128 + row];
        const float4* ep = reinterpret_cast<const float4*>(E + (size_t)(t * 128 + row) * 64 + half * 32);
#pragma unroll
        for (int g = 0; g < 8; g++) eR[g] = ep[g];
    }
    CP_WAIT0(); __syncthreads();   // weights resident

    float acc[64];
    for (; t < NTILES; t += EGRID) {
        if (half == 0) {
            sSrc[row] = src; sDst[row] = dst;
            atomicAdd(&g_deg[dst], 1.0f);
        }
        split_regs(eR, 1.0f, sA + row * 280 + half * 32, sA + row * 280 + 64 + half * 32);
        __syncthreads();           // E split + indices visible

        // prefetch next tile (overlaps both GEMMs)
        const int tn = t + EGRID;
        if (tn < NTILES) {
            src = ei[tn * 128 + row];
            dst = ei[NE + tn * 128 + row];
            const float4* ep = reinterpret_cast<const float4*>(E + (size_t)(tn * 128 + row) * 64 + half * 32);
#pragma unroll
            for (int g = 0; g < 8; g++) eR[g] = ep[g];
        }

#pragma unroll
        for (int i = 0; i < 64; i++) acc[i] = 0.0f;
        mma_chunk2(acc, aS, wS0, wm, wn, lane, 0);     // GEMM1: E x W1e
        add_p_gmem(acc, g_Ps, sSrc, wm, wn, lane);     // += Ps[src]
        add_p_gmem(acc, g_Pd, sDst, wm, wn, lane);     // += Pd[dst]
        __syncthreads();           // partner's slot0 ldsm reads done
        hsplit(acc, sA, sb1, wm, wn, lane);            // relu(+b1) -> A slots
        __syncthreads();           // hsplit visible
#pragma unroll
        for (int i = 0; i < 64; i++) acc[i] = 0.0f;
        mma_chunk2(acc, aS, wS1, wm, wn, lane, 0);     // GEMM2 c0 (resident)
        mma_chunk2(acc, aS, wS2, wm, wn, lane, 144);   // GEMM2 c1 (resident)
        __syncthreads();           // slot ldsm reads done before f32 overwrite

        float* st = reinterpret_cast<float*>(dynbase);
        stage_out140(acc, st, sb2, wm, wn, lane);
        __syncthreads();
#pragma unroll
        for (int i = 0; i < 16; i++) {
            int idx = tid + i * 256;
            int r = idx >> 5, c4 = (idx & 31) * 4;
            float4 v = *reinterpret_cast<float4*>(st + r * 140 + c4);
            red4(&g_agg[(size_t)sDst[r] * 128 + c4], v.x, v.y, v.z, v.w);
        }
        __syncthreads();           // scatter reads of st/sDst done before next iter
    }
}

// ============================ node kernel ===================================
// V' = relu([agg/deg | V] @ W1' + c) @ W2 + b2
__global__ __launch_bounds__(256, 2) void node_kernel(
    const float* __restrict__ V,
    const float* __restrict__ b2, float* __restrict__ out)
{
    __nv_bfloat16* sA = reinterpret_cast<__nv_bfloat16*>(dynbase);
    __shared__ float sb1[128], sb2[128];

    const int tid = threadIdx.x, lane = tid & 31, w = tid >> 5;
    const int wm = w >> 1, wn = w & 1;
    const int nbase = blockIdx.x * 128;
    const int row = tid >> 1, half = tid & 1;

    const uint32_t aS = smem_u32(dynbase), bS = aS + B_OFF;

    const int n = nbase + row;
    const bool valid = n < NV;
    const size_t nc = valid ? (size_t)n : (size_t)(NV - 1);

    if (tid < 128) sb1[tid] = g_cnode[tid];
    else           sb2[tid - 128] = b2[tid - 128];
    const float inv = valid ? 1.0f / fmaxf(g_deg[nc], 1.0f) : 0.0f;

    issue_w(WN1h, WN1l, 256, 0, bS, row, half);
    CP_COMMIT();
    {   // raw chunk0: agg low half
        float4 rv[8];
        const float4* p = reinterpret_cast<const float4*>(g_agg + nc * 128 + half * 32);
#pragma unroll
        for (int g = 0; g < 8; g++) rv[g] = p[g];
        split_regs(rv, inv, sA + row * 280 + half * 32, sA + row * 280 + 64 + half * 32);
    }
    CP_WAIT0(); __syncthreads();

    float acc[64];
#pragma unroll
    for (int i = 0; i < 64; i++) acc[i] = 0.0f;

    // GEMM1: 4 chunks (agg0, agg1, V0, V1); slot alternates s&1
    for (int s = 0; s < 4; s++) {
        mma_chunk2(acc, aS, bS, wm, wn, lane, (s & 1) * 144);
        __syncthreads();                               // B consumers done
        if (s < 3) {
            issue_w(WN1h, WN1l, 256, s + 1, bS, row, half);
            CP_COMMIT();
            const float* src = (s == 0) ? g_agg + nc * 128 + 64 + half * 32
                             : (s == 1) ? V + nc * 128 + half * 32
                                        : V + nc * 128 + 64 + half * 32;
            float4 rv[8];
            const float4* p = reinterpret_cast<const float4*>(src);
#pragma unroll
            for (int g = 0; g < 8; g++) rv[g] = p[g];
            int so = ((s + 1) & 1) * 144;
            split_regs(rv, (s == 0) ? inv : 1.0f,
                       sA + row * 280 + so + half * 32,
                       sA + row * 280 + so + 64 + half * 32);
        } else {
            issue_w(WN2h, WN2l, 128, 0, bS, row, half);
            CP_COMMIT();
        }
        CP_WAIT0(); __syncthreads();
    }

    hsplit(acc, sA, sb1, wm, wn, lane);
    __syncthreads();   // hsplit visible before GEMM2 c0 ldsm reads
#pragma unroll
    for (int i = 0; i < 64; i++) acc[i] = 0.0f;
    mma_chunk2(acc, aS, bS, wm, wn, lane, 0);          // GEMM2 c0
    __syncthreads();
    issue_w(WN2h, WN2l, 128, 1, bS, row, half);
    CP_COMMIT(); CP_WAIT0(); __syncthreads();
    mma_chunk2(acc, aS, bS, wm, wn, lane, 144);        // GEMM2 c1
    __syncthreads();   // slot ldsm reads done before f32 staging

    float* st = reinterpret_cast<float*>(dynbase);
    stage_out140(acc, st, sb2, wm, wn, lane);
    __syncthreads();
#pragma unroll
    for (int i = 0; i < 16; i++) {
        int idx = tid + i * 256;
        int r = idx >> 5, c4 = (idx & 31) * 4;
        int nn = nbase + r;
        if (nn < NV) {
            float4 v = *reinterpret_cast<float4*>(st + r * 140 + c4);
            *reinterpret_cast<float4*>(out + (size_t)nn * 128 + c4) = v;
        }
    }
}

// ======================= V' column sum/max reduce ===========================
__global__ void reduce_kernel(const float* __restrict__ out) {
    const int t = threadIdx.x;
    const int b = blockIdx.x;
    float s = 0.0f, mx = -3.402823466e38f;
    for (int r = b * 250; r < (b + 1) * 250; r++) {
        float v = out[(size_t)r * 128 + t];
        s += v;
        mx = fmaxf(mx, v);
    }
    atomicAdd(&g_vsum[t], s);
    atomicMaxF(&g_vmax[t], mx);
}

// ============================ global kernel =================================
__global__ void global_kernel(
    const float* __restrict__ z, const float* __restrict__ u,
    const float* __restrict__ Wg1, const float* __restrict__ bg1,
    const float* __restrict__ Wg2, const float* __restrict__ bg2,
    const float* __restrict__ Wu1, const float* __restrict__ bu1,
    const float* __restrict__ Wu2, const float* __restrict__ bu2,
    float* __restrict__ out)
{
    __shared__ float x[448], h[128], part[4][128], zp[128];
    const int tid = threadIdx.x;         // 512
    const int t = tid & 127, s = tid >> 7;

    if (tid < 128)      x[tid] = g_vsum[tid] * (1.0f / (float)NV);
    else if (tid < 256) x[tid] = z[tid - 128];
    __syncthreads();

    {
        float acc = 0.0f;
        for (int k = s * 64; k < s * 64 + 64; k++) acc = fmaf(x[k], Wg1[k * 128 + t], acc);
        part[s][t] = acc;
    }
    __syncthreads();
    if (s == 0) h[t] = fmaxf(part[0][t] + part[1][t] + part[2][t] + part[3][t] + bg1[t], 0.0f);
    __syncthreads();
    {
        float acc = 0.0f;
        for (int k = s * 32; k < s * 32 + 32; k++) acc = fmaf(h[k], Wg2[k * 128 + t], acc);
        part[s][t] = acc;
    }
    __syncthreads();
    if (s == 0) {
        float v = part[0][t] + part[1][t] + part[2][t] + part[3][t] + bg2[t];
        zp[t] = v;
        out[(size_t)NV * 128 + 64 + t] = v;
        x[128 + t] = g_vmax[t];
    }
    __syncthreads();
    if (tid < 128)      x[256 + tid] = zp[tid];
    else if (tid < 192) x[384 + (tid - 128)] = u[tid - 128];
    __syncthreads();
    {
        float acc = 0.0f;
        for (int k = s * 112; k < s * 112 + 112; k++) acc = fmaf(x[k], Wu1[k * 128 + t], acc);
        part[s][t] = acc;
    }
    __syncthreads();
    if (s == 0) h[t] = fmaxf(part[0][t] + part[1][t] + part[2][t] + part[3][t] + bu1[t], 0.0f);
    __syncthreads();
    if (t < 64) {
        float acc = 0.0f;
        for (int k = s * 32; k < s * 32 + 32; k++) acc = fmaf(h[k], Wu2[k * 64 + t], acc);
        part[s][t] = acc;
    }
    __syncthreads();
    if (s == 0 && t < 64)
        out[(size_t)NV * 128 + t] = part[0][t] + part[1][t] + part[2][t] + part[3][t] + bu2[t];
}

// ============================ launch ========================================
extern "C" void kernel_launch(void* const* d_in, const int* in_sizes, int n_in,
                              void* d_out, int out_size) {
    const float* V   = (const float*)d_in[0];
    const float* E   = (const float*)d_in[1];
    const int*   ei  = (const int*)d_in[2];
    const float* u   = (const float*)d_in[3];
    const float* z   = (const float*)d_in[4];
    const float* We1 = (const float*)d_in[5];
    const float* be1 = (const float*)d_in[6];
    const float* We2 = (const float*)d_in[7];
    const float* be2 = (const float*)d_in[8];
    const float* Wn1 = (const float*)d_in[9];
    const float* bn1 = (const float*)d_in[10];
    const float* Wn2 = (const float*)d_in[11];
    const float* bn2 = (const float*)d_in[12];
    const float* Wg1 = (const float*)d_in[13];
    const float* bg1 = (const float*)d_in[14];
    const float* Wg2 = (const float*)d_in[15];
    const float* bg2 = (const float*)d_in[16];
    const float* Wu1 = (const float*)d_in[17];
    const float* bu1 = (const float*)d_in[18];
    const float* Wu2 = (const float*)d_in[19];
    const float* bu2 = (const float*)d_in[20];
    float* out = (float*)d_out;

    cudaFuncSetAttribute(pgemm_kernel, cudaFuncAttributeMaxDynamicSharedMemorySize, SMEM_TOTAL);
    cudaFuncSetAttribute(edge_kernel, cudaFuncAttributeMaxDynamicSharedMemorySize, ESMEM_TOTAL);
    cudaFuncSetAttribute(node_kernel, cudaFuncAttributeMaxDynamicSharedMemorySize, SMEM_TOTAL);

    init_kernel<<<512, 256>>>();
    wprep_kernel<<<256, 256>>>(We1, We2, Wn1, Wn2);
    cnode_kernel<<<1, 128>>>(Wn1, bn1, z, u);
    pgemm_kernel<<<(NV + 127) / 128, 256, SMEM_TOTAL>>>(V);
    edge_kernel<<<EGRID, 256, ESMEM_TOTAL>>>(E, ei, be1, be2);
    node_kernel<<<(NV + 127) / 128, 256, SMEM_TOTAL>>>(V, bn2, out);
    reduce_kernel<<<200, 128>>>(out);
    global_kernel<<<1, 512>>>(z, u, Wg1, bg1, Wg2, bg2, Wu1, bu1, Wu2, bu2, out);
}

// round 17
// speedup vs baseline: 4.2801x; 1.1035x over previous
#include <cuda_runtime.h>
#include <cuda_bf16.h>
#include <cstdint>

#define NV 50000
#define NE 800000
#define NTILES (NE / 128)   // 6250
#define EGRID 148

// ============================ device globals ================================
__device__ float g_agg[(size_t)NV * 128];
__device__ float g_deg[NV];
__device__ float g_vsum[128];
__device__ float g_vmax[128];
__device__ float g_Ps[(size_t)NV * 128];   // V @ W1s^T
__device__ float g_Pd[(size_t)NV * 128];   // V @ W1d^T
__device__ float g_cnode[128];             // z@W1z + u@W1u + b1 (node)
// pre-split transposed weights [n][k] bf16 hi/lo
__device__ __nv_bfloat16 WE1h[128 * 64],  WE1l[128 * 64];    // We1 rows 0..63
__device__ __nv_bfloat16 WS1h[128 * 128], WS1l[128 * 128];   // We1 rows 64..191
__device__ __nv_bfloat16 WD1h[128 * 128], WD1l[128 * 128];   // We1 rows 192..319
__device__ __nv_bfloat16 WB2h[128 * 128], WB2l[128 * 128];
__device__ __nv_bfloat16 WN1h[128 * 256], WN1l[128 * 256];   // Wn1 rows 0..255
__device__ __nv_bfloat16 WN2h[128 * 128], WN2l[128 * 128];

// pgemm/node smem (2 CTAs/SM):  A[0,71680) + B[71680,+34816)
#define B_OFF 71680
#define SMEM_TOTAL (B_OFF + 34816)        // 106496
// edge persistent smem (1 CTA/SM): A[0,71680) + W0,W1,W2 chunks resident
#define EW0_OFF 71680
#define ESMEM_TOTAL (EW0_OFF + 3 * 34816) // 176128

extern __shared__ char dynbase[];

// ============================ helpers =======================================
__device__ __forceinline__ uint32_t smem_u32(const void* p) {
    uint32_t a;
    asm("{ .reg .u64 t; cvta.to.shared.u64 t, %1; cvt.u32.u64 %0, t; }" : "=r"(a) : "l"(p));
    return a;
}
__device__ __forceinline__ void bar_band(int id) {
    asm volatile("bar.sync %0, 64;" :: "r"(id) : "memory");
}
__device__ __forceinline__ void ldsm4(uint32_t* r, uint32_t addr) {
    asm volatile("ldmatrix.sync.aligned.m8n8.x4.shared.b16 {%0,%1,%2,%3}, [%4];"
                 : "=r"(r[0]), "=r"(r[1]), "=r"(r[2]), "=r"(r[3]) : "r"(addr));
}
__device__ __forceinline__ void mma16816(float* d, const uint32_t* a, const uint32_t* b) {
    asm volatile("mma.sync.aligned.m16n8k16.row.col.f32.bf16.bf16.f32 "
                 "{%0,%1,%2,%3}, {%4,%5,%6,%7}, {%8,%9}, {%0,%1,%2,%3};"
                 : "+f"(d[0]), "+f"(d[1]), "+f"(d[2]), "+f"(d[3])
                 : "r"(a[0]), "r"(a[1]), "r"(a[2]), "r"(a[3]), "r"(b[0]), "r"(b[1]));
}
__device__ __forceinline__ void red4(float* p, float a, float b, float c, float d) {
    asm volatile("red.global.add.v4.f32 [%0], {%1, %2, %3, %4};"
                 :: "l"(p), "f"(a), "f"(b), "f"(c), "f"(d) : "memory");
}
__device__ __forceinline__ void atomicMaxF(float* addr, float val) {
    int old = __float_as_int(*addr);
    while (__int_as_float(old) < val) {
        int assumed = old;
        old = atomicCAS((int*)addr, assumed, __float_as_int(val));
        if (old == assumed) break;
    }
}
__device__ __forceinline__ void cp16(uint32_t dst, const void* src, int sz) {
    asm volatile("cp.async.cg.shared.global [%0], [%1], 16, %2;"
                 :: "r"(dst), "l"(src), "r"(sz) : "memory");
}
#define CP_COMMIT() asm volatile("cp.async.commit_group;" ::: "memory")
#define CP_WAIT0()  asm volatile("cp.async.wait_group 0;" ::: "memory")

// split 32 fp32 regs (scaled) -> bf16 hi/lo (64B each) to smem
__device__ __forceinline__ void split_regs(const float4* f, float scale,
                                           __nv_bfloat16* hptr, __nv_bfloat16* lptr) {
    uint32_t H[16], L[16];
#pragma unroll
    for (int g = 0; g < 8; g++) {
        float4 v = f[g];
        v.x *= scale; v.y *= scale; v.z *= scale; v.w *= scale;
        __nv_bfloat162 h0 = __floats2bfloat162_rn(v.x, v.y);
        __nv_bfloat162 l0 = __floats2bfloat162_rn(v.x - __low2float(h0), v.y - __high2float(h0));
        __nv_bfloat162 h1 = __floats2bfloat162_rn(v.z, v.w);
        __nv_bfloat162 l1 = __floats2bfloat162_rn(v.z - __low2float(h1), v.w - __high2float(h1));
        H[g * 2 + 0] = *reinterpret_cast<uint32_t*>(&h0);
        H[g * 2 + 1] = *reinterpret_cast<uint32_t*>(&h1);
        L[g * 2 + 0] = *reinterpret_cast<uint32_t*>(&l0);
        L[g * 2 + 1] = *reinterpret_cast<uint32_t*>(&l1);
    }
    uint4* dh = reinterpret_cast<uint4*>(hptr);
    uint4* dl = reinterpret_cast<uint4*>(lptr);
#pragma unroll
    for (int q = 0; q < 4; q++) {
        dh[q] = make_uint4(H[q * 4], H[q * 4 + 1], H[q * 4 + 2], H[q * 4 + 3]);
        dl[q] = make_uint4(L[q * 4], L[q * 4 + 1], L[q * 4 + 2], L[q * 4 + 3]);
    }
}

// one weight half-row chunk (hi+lo, 32+32 bf16) -> B buf via cp.async
__device__ __forceinline__ void issue_w(const __nv_bfloat16* Wh, const __nv_bfloat16* Wl,
                                        int stride, int chunk, uint32_t bBuf,
                                        int row, int half) {
    const __nv_bfloat16* sh = Wh + (size_t)row * stride + chunk * 64 + half * 32;
    const __nv_bfloat16* sl = Wl + (size_t)row * stride + chunk * 64 + half * 32;
    uint32_t dh = bBuf + (uint32_t)(row * 272 + half * 64);
    uint32_t dl = dh + 128;
#pragma unroll
    for (int g = 0; g < 4; g++) { cp16(dh + g * 16, sh + g * 8, 16); cp16(dl + g * 16, sl + g * 8, 16); }
}

// one 64-k chunk, bf16x3: acc += Ah*Bh + Al*Bh + Ah*Bl
__device__ __forceinline__ void mma_chunk2(float* acc, uint32_t aS, uint32_t bS,
                                           int wm, int wn, int lane, int abase) {
#pragma unroll
    for (int ks = 0; ks < 4; ks++) {
        const int kb = ks * 16;
        uint32_t ah[2][4], al[2][4], bh[4][4], bl[4][4];
#pragma unroll
        for (int mi = 0; mi < 2; mi++) {
            int r = wm * 32 + mi * 16 + (lane & 15);
            ldsm4(ah[mi], aS + ((uint32_t)(r * 280 + abase + kb + ((lane >> 4) << 3)) << 1));
        }
#pragma unroll
        for (int np = 0; np < 4; np++) {
            int rowb = wn * 64 + np * 16 + (lane & 7) + ((lane >> 4) << 3);
            int k = kb + (((lane >> 3) & 1) << 3);
            ldsm4(bh[np], bS + ((uint32_t)(rowb * 136 + k) << 1));
        }
#pragma unroll
        for (int mi = 0; mi < 2; mi++)
#pragma unroll
            for (int ni = 0; ni < 8; ni++)
                mma16816(&acc[(mi * 8 + ni) * 4], ah[mi], &bh[ni >> 1][(ni & 1) * 2]);
#pragma unroll
        for (int mi = 0; mi < 2; mi++) {
            int r = wm * 32 + mi * 16 + (lane & 15);
            ldsm4(al[mi], aS + ((uint32_t)(r * 280 + abase + 64 + kb + ((lane >> 4) << 3)) << 1));
        }
#pragma unroll
        for (int mi = 0; mi < 2; mi++)
#pragma unroll
            for (int ni = 0; ni < 8; ni++)
                mma16816(&acc[(mi * 8 + ni) * 4], al[mi], &bh[ni >> 1][(ni & 1) * 2]);
#pragma unroll
        for (int np = 0; np < 4; np++) {
            int rowb = wn * 64 + np * 16 + (lane & 7) + ((lane >> 4) << 3);
            int k = kb + (((lane >> 3) & 1) << 3);
            ldsm4(bl[np], bS + ((uint32_t)(rowb * 136 + 64 + k) << 1));
        }
#pragma unroll
        for (int mi = 0; mi < 2; mi++)
#pragma unroll
            for (int ni = 0; ni < 8; ni++)
                mma16816(&acc[(mi * 8 + ni) * 4], ah[mi], &bl[ni >> 1][(ni & 1) * 2]);
    }
}

// bias+relu+split fragments into A slots 0/1 (own 32-row band only)
__device__ __forceinline__ void hsplit(const float* acc, __nv_bfloat16* sA,
                                       const float* sb1, int wm, int wn, int lane) {
#pragma unroll
    for (int mi = 0; mi < 2; mi++)
#pragma unroll
        for (int ni = 0; ni < 8; ni++) {
            const float* a4 = &acc[(mi * 8 + ni) * 4];
            int c = wn * 64 + ni * 8 + 2 * (lane & 3);
            int soff = (c >> 6) * 144, kk = c & 63;
            float bb0 = sb1[c], bb1 = sb1[c + 1];
            int r0 = wm * 32 + mi * 16 + (lane >> 2);
#pragma unroll
            for (int hh = 0; hh < 2; hh++) {
                int r = r0 + hh * 8;
                float v0 = fmaxf(a4[hh * 2 + 0] + bb0, 0.0f);
                float v1 = fmaxf(a4[hh * 2 + 1] + bb1, 0.0f);
                __nv_bfloat162 hv = __floats2bfloat162_rn(v0, v1);
                __nv_bfloat162 lv = __floats2bfloat162_rn(v0 - __low2float(hv), v1 - __high2float(hv));
                *reinterpret_cast<uint32_t*>(sA + r * 280 + soff + kk) = *reinterpret_cast<uint32_t*>(&hv);
                *reinterpret_cast<uint32_t*>(sA + r * 280 + soff + 64 + kk) = *reinterpret_cast<uint32_t*>(&lv);
            }
        }
}

// acc += P[idx[r]][c] via direct gmem loads (L2-resident P)
__device__ __forceinline__ void add_p_gmem(float* acc, const float* __restrict__ P,
                                           const int* sIdx, int wm, int wn, int lane) {
#pragma unroll
    for (int mi = 0; mi < 2; mi++)
#pragma unroll
        for (int hh = 0; hh < 2; hh++) {
            int r = wm * 32 + mi * 16 + hh * 8 + (lane >> 2);
            const float* prow = P + (size_t)sIdx[r] * 128;
#pragma unroll
            for (int ni = 0; ni < 8; ni++) {
                int c = wn * 64 + ni * 8 + 2 * (lane & 3);
                float2 p = *reinterpret_cast<const float2*>(prow + c);
                acc[(mi * 8 + ni) * 4 + hh * 2 + 0] += p.x;
                acc[(mi * 8 + ni) * 4 + hh * 2 + 1] += p.y;
            }
        }
}

// stage fragments (+bias) to f32 smem stride 140 (A region reuse)
__device__ __forceinline__ void stage_out140(const float* acc, float* st, const float* sb2,
                                             int wm, int wn, int lane) {
#pragma unroll
    for (int mi = 0; mi < 2; mi++)
#pragma unroll
        for (int ni = 0; ni < 8; ni++) {
            const float* a4 = &acc[(mi * 8 + ni) * 4];
            int c = wn * 64 + ni * 8 + 2 * (lane & 3);
            float bb0 = sb2[c], bb1 = sb2[c + 1];
            int r0 = wm * 32 + mi * 16 + (lane >> 2);
            st[r0 * 140 + c] = a4[0] + bb0;
            st[r0 * 140 + c + 1] = a4[1] + bb1;
            st[(r0 + 8) * 140 + c] = a4[2] + bb0;
            st[(r0 + 8) * 140 + c + 1] = a4[3] + bb1;
        }
}

// store fragments directly to a [*,128] f32 gmem array (row nbase+r, no bias)
__device__ __forceinline__ void store_p(const float* acc, float* P, int nbase,
                                        int wm, int wn, int lane) {
#pragma unroll
    for (int mi = 0; mi < 2; mi++)
#pragma unroll
        for (int hh = 0; hh < 2; hh++) {
            int r = wm * 32 + mi * 16 + hh * 8 + (lane >> 2);
            int n = nbase + r;
            if (n < NV) {
                float* prow = P + (size_t)n * 128;
#pragma unroll
                for (int ni = 0; ni < 8; ni++) {
                    int c = wn * 64 + ni * 8 + 2 * (lane & 3);
                    *reinterpret_cast<float2*>(prow + c) =
                        make_float2(acc[(mi * 8 + ni) * 4 + hh * 2 + 0],
                                    acc[(mi * 8 + ni) * 4 + hh * 2 + 1]);
                }
            }
        }
}

// ============================ small kernels =================================
__global__ void init_kernel() {
    int i = blockIdx.x * blockDim.x + threadIdx.x;
    int stride = gridDim.x * blockDim.x;
    float4 z4 = make_float4(0.f, 0.f, 0.f, 0.f);
    for (int k = i; k < NV * 32; k += stride) reinterpret_cast<float4*>(g_agg)[k] = z4;
    for (int k = i; k < NV; k += stride) g_deg[k] = 0.0f;
    if (i < 128) { g_vsum[i] = 0.0f; g_vmax[i] = -3.402823466e38f; }
}

__global__ void wprep_kernel(const float* __restrict__ We1, const float* __restrict__ We2,
                             const float* __restrict__ Wn1, const float* __restrict__ Wn2) {
    int i = blockIdx.x * blockDim.x + threadIdx.x;
    int stride = gridDim.x * blockDim.x;
    for (int idx = i; idx < 320 * 128; idx += stride) {
        int k = idx >> 7, n = idx & 127;
        float v = We1[idx];
        __nv_bfloat16 h = __float2bfloat16(v);
        __nv_bfloat16 l = __float2bfloat16(v - __bfloat162float(h));
        if (k < 64)       { WE1h[n * 64 + k] = h;          WE1l[n * 64 + k] = l; }
        else if (k < 192) { WS1h[n * 128 + (k - 64)] = h;  WS1l[n * 128 + (k - 64)] = l; }
        else              { WD1h[n * 128 + (k - 192)] = h; WD1l[n * 128 + (k - 192)] = l; }
    }
    for (int idx = i; idx < 128 * 128; idx += stride) {
        int k = idx >> 7, n = idx & 127;
        float v = We2[idx];
        __nv_bfloat16 h = __float2bfloat16(v);
        WB2h[n * 128 + k] = h;
        WB2l[n * 128 + k] = __float2bfloat16(v - __bfloat162float(h));
    }
    for (int idx = i; idx < 256 * 128; idx += stride) {
        int k = idx >> 7, n = idx & 127;
        float v = Wn1[idx];
        __nv_bfloat16 h = __float2bfloat16(v);
        WN1h[n * 256 + k] = h;
        WN1l[n * 256 + k] = __float2bfloat16(v - __bfloat162float(h));
    }
    for (int idx = i; idx < 128 * 128; idx += stride) {
        int k = idx >> 7, n = idx & 127;
        float v = Wn2[idx];
        __nv_bfloat16 h = __float2bfloat16(v);
        WN2h[n * 128 + k] = h;
        WN2l[n * 128 + k] = __float2bfloat16(v - __bfloat162float(h));
    }
}

// c[n] = bn1[n] + sum z[k] Wn1[256+k][n] + sum u[k] Wn1[384+k][n]
__global__ void cnode_kernel(const float* __restrict__ Wn1, const float* __restrict__ bn1,
                             const float* __restrict__ z, const float* __restrict__ u) {
    int t = threadIdx.x;
    float c = bn1[t];
    for (int k = 0; k < 128; k++) c = fmaf(z[k], Wn1[(256 + k) * 128 + t], c);
    for (int k = 0; k < 64; k++)  c = fmaf(u[k], Wn1[(384 + k) * 128 + t], c);
    g_cnode[t] = c;
}

// ============================ pgemm: P_s, P_d ===============================
__global__ __launch_bounds__(256, 2) void pgemm_kernel(const float* __restrict__ V) {
    __nv_bfloat16* sA = reinterpret_cast<__nv_bfloat16*>(dynbase);
    const int tid = threadIdx.x, lane = tid & 31, w = tid >> 5;
    const int wm = w >> 1, wn = w & 1;
    const int nbase = blockIdx.x * 128;
    const int row = tid >> 1, half = tid & 1;
    const int n = nbase + row;
    const size_t nc = (n < NV) ? (size_t)n : (size_t)(NV - 1);

    const uint32_t aS = smem_u32(dynbase), bS = aS + B_OFF;

    issue_w(WS1h, WS1l, 128, 0, bS, row, half);
    CP_COMMIT();
    {
        float4 rv[16];
        const float4* vp = reinterpret_cast<const float4*>(V + nc * 128 + half * 64);
#pragma unroll
        for (int g = 0; g < 16; g++) rv[g] = vp[g];
        __nv_bfloat16* hd = sA + row * 280 + half * 144;
        split_regs(rv, 1.0f, hd, hd + 64);
        split_regs(rv + 8, 1.0f, hd + 32, hd + 96);
    }
    CP_WAIT0(); __syncthreads();

    float acc[64];
#pragma unroll
    for (int i = 0; i < 64; i++) acc[i] = 0.0f;
    mma_chunk2(acc, aS, bS, wm, wn, lane, 0);
    __syncthreads();
    issue_w(WS1h, WS1l, 128, 1, bS, row, half);
    CP_COMMIT(); CP_WAIT0(); __syncthreads();
    mma_chunk2(acc, aS, bS, wm, wn, lane, 144);
    store_p(acc, g_Ps, nbase, wm, wn, lane);
    __syncthreads();
    issue_w(WD1h, WD1l, 128, 0, bS, row, half);
    CP_COMMIT(); CP_WAIT0(); __syncthreads();
#pragma unroll
    for (int i = 0; i < 64; i++) acc[i] = 0.0f;
    mma_chunk2(acc, aS, bS, wm, wn, lane, 0);
    __syncthreads();
    issue_w(WD1h, WD1l, 128, 1, bS, row, half);
    CP_COMMIT(); CP_WAIT0(); __syncthreads();
    mma_chunk2(acc, aS, bS, wm, wn, lane, 144);
    store_p(acc, g_Pd, nbase, wm, wn, lane);
}

// ============================ edge kernel (persistent, band-decoupled) ======
// Per tile: H = relu(E@W1e + Ps[src] + Pd[dst] + b1); C = H@W2 + b2 -> agg[dst]
// Weights resident (read-only in loop). All smem hazards are confined to the
// 32-row band owned by warp-pair wm, so bands sync only among themselves
// (bar.sync wm+1, 64) and slip freely — 4 independent pipelines per SM.
__global__ __launch_bounds__(256) void edge_kernel(
    const float* __restrict__ E, const int* __restrict__ ei,
    const float* __restrict__ b1, const float* __restrict__ b2)
{
    __nv_bfloat16* sA = reinterpret_cast<__nv_bfloat16*>(dynbase);
    __shared__ float sb1[128], sb2[128];
    __shared__ int sSrc[128], sDst[128];

    const int tid = threadIdx.x, lane = tid & 31, w = tid >> 5;
    const int wm = w >> 1, wn = w & 1;
    const int row = tid >> 1, half = tid & 1;   // row is band-local: 32wm..32wm+31
    const int bar = wm + 1;
    const int btid = tid & 63;                  // thread index within band

    const uint32_t aS = smem_u32(dynbase);
    const uint32_t wS0 = aS + EW0_OFF;            // WE1 chunk
    const uint32_t wS1 = wS0 + 34816;             // WB2 chunk0
    const uint32_t wS2 = wS1 + 34816;             // WB2 chunk1

    // resident weights (loaded once)
    issue_w(WE1h, WE1l, 64, 0, wS0, row, half);
    issue_w(WB2h, WB2l, 128, 0, wS1, row, half);
    issue_w(WB2h, WB2l, 128, 1, wS2, row, half);
    CP_COMMIT();

    if (tid < 128) sb1[tid] = b1[tid];
    else           sb2[tid - 128] = b2[tid - 128];

    int t = blockIdx.x;
    int src = 0, dst = 0;
    float4 eR[8];
    {   // prefetch first tile
        src = ei[t * 128 + row];
        dst = ei[NE + t * 128 + row];
        const float4* ep = reinterpret_cast<const float4*>(E + (size_t)(t * 128 + row) * 64 + half * 32);
#pragma unroll
        for (int g = 0; g < 8; g++) eR[g] = ep[g];
    }
    CP_WAIT0(); __syncthreads();   // weights + biases resident (only full sync)

    float acc[64];
    float* st = reinterpret_cast<float*>(dynbase);
    for (; t < NTILES; t += EGRID) {
        if (half == 0) {
            sSrc[row] = src; sDst[row] = dst;
            atomicAdd(&g_deg[dst], 1.0f);
        }
        split_regs(eR, 1.0f, sA + row * 280 + half * 32, sA + row * 280 + 64 + half * 32);
        bar_band(bar);             // band's E split + indices visible

        // prefetch next tile (overlaps both GEMMs)
        const int tn = t + EGRID;
        if (tn < NTILES) {
            src = ei[tn * 128 + row];
            dst = ei[NE + tn * 128 + row];
            const float4* ep = reinterpret_cast<const float4*>(E + (size_t)(tn * 128 + row) * 64 + half * 32);
#pragma unroll
            for (int g = 0; g < 8; g++) eR[g] = ep[g];
        }

#pragma unroll
        for (int i = 0; i < 64; i++) acc[i] = 0.0f;
        mma_chunk2(acc, aS, wS0, wm, wn, lane, 0);     // GEMM1: E x W1e
        add_p_gmem(acc, g_Ps, sSrc, wm, wn, lane);     // += Ps[src]
        add_p_gmem(acc, g_Pd, sDst, wm, wn, lane);     // += Pd[dst]
        bar_band(bar);             // partner warp's slot0 ldsm reads done
        hsplit(acc, sA, sb1, wm, wn, lane);            // relu(+b1) -> A slots
        bar_band(bar);             // hsplit visible within band
#pragma unroll
        for (int i = 0; i < 64; i++) acc[i] = 0.0f;
        mma_chunk2(acc, aS, wS1, wm, wn, lane, 0);     // GEMM2 c0 (resident)
        mma_chunk2(acc, aS, wS2, wm, wn, lane, 144);   // GEMM2 c1 (resident)
        bar_band(bar);             // partner's slot ldsm reads done

        stage_out140(acc, st, sb2, wm, wn, lane);      // own band rows
        bar_band(bar);             // both warps' stage writes visible
        // band-local scatter: 64 threads cover own 32 rows x 128 cols
#pragma unroll
        for (int i = 0; i < 16; i++) {
            int idx = btid + i * 64;
            int r = wm * 32 + (idx >> 5), c4 = (idx & 31) * 4;
            float4 v = *reinterpret_cast<float4*>(st + r * 140 + c4);
            red4(&g_agg[(size_t)sDst[r] * 128 + c4], v.x, v.y, v.z, v.w);
        }
        bar_band(bar);             // scatter reads done before next split
    }
}

// ============================ node kernel ===================================
// V' = relu([agg/deg | V] @ W1' + c) @ W2 + b2
__global__ __launch_bounds__(256, 2) void node_kernel(
    const float* __restrict__ V,
    const float* __restrict__ b2, float* __restrict__ out)
{
    __nv_bfloat16* sA = reinterpret_cast<__nv_bfloat16*>(dynbase);
    __shared__ float sb1[128], sb2[128];

    const int tid = threadIdx.x, lane = tid & 31, w = tid >> 5;
    const int wm = w >> 1, wn = w & 1;
    const int nbase = blockIdx.x * 128;
    const int row = tid >> 1, half = tid & 1;

    const uint32_t aS = smem_u32(dynbase), bS = aS + B_OFF;

    const int n = nbase + row;
    const bool valid = n < NV;
    const size_t nc = valid ? (size_t)n : (size_t)(NV - 1);

    if (tid < 128) sb1[tid] = g_cnode[tid];
    else           sb2[tid - 128] = b2[tid - 128];
    const float inv = valid ? 1.0f / fmaxf(g_deg[nc], 1.0f) : 0.0f;

    issue_w(WN1h, WN1l, 256, 0, bS, row, half);
    CP_COMMIT();
    {   // raw chunk0: agg low half
        float4 rv[8];
        const float4* p = reinterpret_cast<const float4*>(g_agg + nc * 128 + half * 32);
#pragma unroll
        for (int g = 0; g < 8; g++) rv[g] = p[g];
        split_regs(rv, inv, sA + row * 280 + half * 32, sA + row * 280 + 64 + half * 32);
    }
    CP_WAIT0(); __syncthreads();

    float acc[64];
#pragma unroll
    for (int i = 0; i < 64; i++) acc[i] = 0.0f;

    // GEMM1: 4 chunks (agg0, agg1, V0, V1); slot alternates s&1
    for (int s = 0; s < 4; s++) {
        mma_chunk2(acc, aS, bS, wm, wn, lane, (s & 1) * 144);
        __syncthreads();                               // B consumers done
        if (s < 3) {
            issue_w(WN1h, WN1l, 256, s + 1, bS, row, half);
            CP_COMMIT();
            const float* src = (s == 0) ? g_agg + nc * 128 + 64 + half * 32
                             : (s == 1) ? V + nc * 128 + half * 32
                                        : V + nc * 128 + 64 + half * 32;
            float4 rv[8];
            const float4* p = reinterpret_cast<const float4*>(src);
#pragma unroll
            for (int g = 0; g < 8; g++) rv[g] = p[g];
            int so = ((s + 1) & 1) * 144;
            split_regs(rv, (s == 0) ? inv : 1.0f,
                       sA + row * 280 + so + half * 32,
                       sA + row * 280 + so + 64 + half * 32);
        } else {
            issue_w(WN2h, WN2l, 128, 0, bS, row, half);
            CP_COMMIT();
        }
        CP_WAIT0(); __syncthreads();
    }

    hsplit(acc, sA, sb1, wm, wn, lane);
    __syncthreads();   // hsplit visible before GEMM2 c0 ldsm reads
#pragma unroll
    for (int i = 0; i < 64; i++) acc[i] = 0.0f;
    mma_chunk2(acc, aS, bS, wm, wn, lane, 0);          // GEMM2 c0
    __syncthreads();
    issue_w(WN2h, WN2l, 128, 1, bS, row, half);
    CP_COMMIT(); CP_WAIT0(); __syncthreads();
    mma_chunk2(acc, aS, bS, wm, wn, lane, 144);        // GEMM2 c1
    __syncthreads();   // slot ldsm reads done before f32 staging

    float* st = reinterpret_cast<float*>(dynbase);
    stage_out140(acc, st, sb2, wm, wn, lane);
    __syncthreads();
#pragma unroll
    for (int i = 0; i < 16; i++) {
        int idx = tid + i * 256;
        int r = idx >> 5, c4 = (idx & 31) * 4;
        int nn = nbase + r;
        if (nn < NV) {
            float4 v = *reinterpret_cast<float4*>(st + r * 140 + c4);
            *reinterpret_cast<float4*>(out + (size_t)nn * 128 + c4) = v;
        }
    }
}

// ======================= V' column sum/max reduce ===========================
__global__ void reduce_kernel(const float* __restrict__ out) {
    const int t = threadIdx.x;
    const int b = blockIdx.x;
    float s = 0.0f, mx = -3.402823466e38f;
    for (int r = b * 250; r < (b + 1) * 250; r++) {
        float v = out[(size_t)r * 128 + t];
        s += v;
        mx = fmaxf(mx, v);
    }
    atomicAdd(&g_vsum[t], s);
    atomicMaxF(&g_vmax[t], mx);
}

// ============================ global kernel =================================
__global__ void global_kernel(
    const float* __restrict__ z, const float* __restrict__ u,
    const float* __restrict__ Wg1, const float* __restrict__ bg1,
    const float* __restrict__ Wg2, const float* __restrict__ bg2,
    const float* __restrict__ Wu1, const float* __restrict__ bu1,
    const float* __restrict__ Wu2, const float* __restrict__ bu2,
    float* __restrict__ out)
{
    __shared__ float x[448], h[128], part[4][128], zp[128];
    const int tid = threadIdx.x;         // 512
    const int t = tid & 127, s = tid >> 7;

    if (tid < 128)      x[tid] = g_vsum[tid] * (1.0f / (float)NV);
    else if (tid < 256) x[tid] = z[tid - 128];
    __syncthreads();

    {
        float acc = 0.0f;
        for (int k = s * 64; k < s * 64 + 64; k++) acc = fmaf(x[k], Wg1[k * 128 + t], acc);
        part[s][t] = acc;
    }
    __syncthreads();
    if (s == 0) h[t] = fmaxf(part[0][t] + part[1][t] + part[2][t] + part[3][t] + bg1[t], 0.0f);
    __syncthreads();
    {
        float acc = 0.0f;
        for (int k = s * 32; k < s * 32 + 32; k++) acc = fmaf(h[k], Wg2[k * 128 + t], acc);
        part[s][t] = acc;
    }
    __syncthreads();
    if (s == 0) {
        float v = part[0][t] + part[1][t] + part[2][t] + part[3][t] + bg2[t];
        zp[t] = v;
        out[(size_t)NV * 128 + 64 + t] = v;
        x[128 + t] = g_vmax[t];
    }
    __syncthreads();
    if (tid < 128)      x[256 + tid] = zp[tid];
    else if (tid < 192) x[384 + (tid - 128)] = u[tid - 128];
    __syncthreads();
    {
        float acc = 0.0f;
        for (int k = s * 112; k < s * 112 + 112; k++) acc = fmaf(x[k], Wu1[k * 128 + t], acc);
        part[s][t] = acc;
    }
    __syncthreads();
    if (s == 0) h[t] = fmaxf(part[0][t] + part[1][t] + part[2][t] + part[3][t] + bu1[t], 0.0f);
    __syncthreads();
    if (t < 64) {
        float acc = 0.0f;
        for (int k = s * 32; k < s * 32 + 32; k++) acc = fmaf(h[k], Wu2[k * 64 + t], acc);
        part[s][t] = acc;
    }
    __syncthreads();
    if (s == 0 && t < 64)
        out[(size_t)NV * 128 + t] = part[0][t] + part[1][t] + part[2][t] + part[3][t] + bu2[t];
}

// ============================ launch ========================================
extern "C" void kernel_launch(void* const* d_in, const int* in_sizes, int n_in,
                              void* d_out, int out_size) {
    const float* V   = (const float*)d_in[0];
    const float* E   = (const float*)d_in[1];
    const int*   ei  = (const int*)d_in[2];
    const float* u   = (const float*)d_in[3];
    const float* z   = (const float*)d_in[4];
    const float* We1 = (const float*)d_in[5];
    const float* be1 = (const float*)d_in[6];
    const float* We2 = (const float*)d_in[7];
    const float* be2 = (const float*)d_in[8];
    const float* Wn1 = (const float*)d_in[9];
    const float* bn1 = (const float*)d_in[10];
    const float* Wn2 = (const float*)d_in[11];
    const float* bn2 = (const float*)d_in[12];
    const float* Wg1 = (const float*)d_in[13];
    const float* bg1 = (const float*)d_in[14];
    const float* Wg2 = (const float*)d_in[15];
    const float* bg2 = (const float*)d_in[16];
    const float* Wu1 = (const float*)d_in[17];
    const float* bu1 = (const float*)d_in[18];
    const float* Wu2 = (const float*)d_in[19];
    const float* bu2 = (const float*)d_in[20];
    float* out = (float*)d_out;

    cudaFuncSetAttribute(pgemm_kernel, cudaFuncAttributeMaxDynamicSharedMemorySize, SMEM_TOTAL);
    cudaFuncSetAttribute(edge_kernel, cudaFuncAttributeMaxDynamicSharedMemorySize, ESMEM_TOTAL);
    cudaFuncSetAttribute(node_kernel, cudaFuncAttributeMaxDynamicSharedMemorySize, SMEM_TOTAL);

    init_kernel<<<512, 256>>>();
    wprep_kernel<<<256, 256>>>(We1, We2, Wn1, Wn2);
    cnode_kernel<<<1, 128>>>(Wn1, bn1, z, u);
    pgemm_kernel<<<(NV + 127) / 128, 256, SMEM_TOTAL>>>(V);
    edge_kernel<<<EGRID, 256, ESMEM_TOTAL>>>(E, ei, be1, be2);
    node_kernel<<<(NV + 127) / 128, 256, SMEM_TOTAL>>>(V, bn2, out);
    reduce_kernel<<<200, 128>>>(out);
    global_kernel<<<1, 512>>>(z, u, Wg1, bg1, Wg2, bg2, Wu1, bu1, Wu2, bu2, out);
}